// round 3
// baseline (speedup 1.0000x reference)
#include <cuda_runtime.h>
#include <math.h>
#include <stdio.h>

#define BSZ 1000
#define TSZ 100
#define ISZ 264
#define HSZ 100
#define G4  400   // 4*H

// ---------------- device scratch (static: no allocation allowed) ----------
__device__ float g_X[(size_t)BSZ * TSZ * G4];     // encoder gate inputs, 160MB
__device__ float g_henc[BSZ * HSZ];
__device__ float g_cenc[BSZ * HSZ];
__device__ float g_G0[BSZ * G4];                  // decoder step-0 gates
__device__ float g_Weff[G4 * HSZ];                // folded decoder recurrence weight
__device__ float g_beff[G4];                      // folded decoder bias
__device__ float g_hdec[(size_t)BSZ * TSZ * HSZ]; // decoder hidden states, 40MB
__device__ float g_loss[2];                       // [0]=reconstruct sum, [1]=predict sum

// ---------------- f32x2 packed helpers ------------------------------------
__device__ __forceinline__ unsigned long long pk2(float lo, float hi) {
    unsigned long long r;
    asm("mov.b64 %0, {%1,%2};" : "=l"(r) : "f"(lo), "f"(hi));
    return r;
}
__device__ __forceinline__ void fma2(unsigned long long& d,
                                     unsigned long long a, unsigned long long b) {
    asm("fma.rn.f32x2 %0, %1, %2, %0;" : "+l"(d) : "l"(a), "l"(b));
}
__device__ __forceinline__ float2 up2(unsigned long long v) {
    float2 r;
    asm("mov.b64 {%0,%1}, %2;" : "=f"(r.x), "=f"(r.y) : "l"(v));
    return r;
}
union F4U { float4 f4; unsigned long long u[2]; };

__device__ __forceinline__ float sigf(float x) { return 1.f / (1.f + expf(-x)); }

// one LSTM cell scalar update; c updated in place, returns h
__device__ __forceinline__ float cell_up(float gi, float gf, float gg, float go, float& c) {
    float i_ = sigf(gi);
    float f_ = sigf(gf);
    float g_ = tanhf(gg);
    float o_ = sigf(go);
    c = fmaf(f_, c, i_ * g_);
    return o_ * tanhf(c);
}

// ---------------- small kernels -------------------------------------------
__global__ void zero_loss_kernel(float* loss) { loss[0] = 0.f; loss[1] = 0.f; }

__global__ void finalize_kernel(const float* loss, float* out, float inv) {
    out[0] = loss[0] * inv;   // reconstruct_loss
    out[1] = loss[1] * inv;   // predict_loss
}

// Weff[j][k] = Whh[j][k] + sum_i Wih[j][i]*fcW[i][k]
// beff[j]    = bih[j] + bhh[j] + sum_i Wih[j][i]*fcb[i]
__global__ __launch_bounds__(128) void fold_kernel(
    const float* __restrict__ Wih, const float* __restrict__ Whh,
    const float* __restrict__ fcW, const float* __restrict__ fcb,
    const float* __restrict__ bih, const float* __restrict__ bhh,
    float* __restrict__ Weff, float* __restrict__ beff)
{
    int j = blockIdx.x;          // 0..399
    int tid = threadIdx.x;       // 128
    __shared__ float swih[ISZ];
    __shared__ float red[128];
    for (int i = tid; i < ISZ; i += 128) swih[i] = Wih[j * ISZ + i];
    __syncthreads();
    if (tid < HSZ) {
        float acc = Whh[j * HSZ + tid];
        #pragma unroll 4
        for (int i = 0; i < ISZ; ++i)
            acc = fmaf(swih[i], fcW[i * HSZ + tid], acc);
        Weff[j * HSZ + tid] = acc;
    }
    float p = 0.f;
    for (int i = tid; i < ISZ; i += 128) p = fmaf(swih[i], fcb[i], p);
    red[tid] = p;
    __syncthreads();
    for (int s = 64; s > 0; s >>= 1) {
        if (tid < s) red[tid] += red[tid + s];
        __syncthreads();
    }
    if (tid == 0) beff[j] = bih[j] + bhh[j] + red[0];
}

// ---------------- generic NT GEMM: C = A*B^T (+bias), optional MSE epilogue
// A: [M,K] row-major, B: [N,K] row-major.  f32x2 packed inner loop.
__global__ __launch_bounds__(256) void gemm_nt(
    const float* __restrict__ A, const float* __restrict__ B,
    const float* __restrict__ bias1, const float* __restrict__ bias2,
    float* __restrict__ C, int M, int N, int K,
    const float* __restrict__ ref, float* __restrict__ lossOut, int revT)
{
    const int BK = 16, LDSR = 68;
    __shared__ float As[BK * LDSR];
    __shared__ float Bs[BK * LDSR];
    __shared__ float red[256];
    int tid = threadIdx.x;
    int tx = tid & 15, ty = tid >> 4;
    int m0 = blockIdx.y * 64, n0 = blockIdx.x * 64;
    unsigned long long acc2[4][2];
    #pragma unroll
    for (int i = 0; i < 4; ++i) { acc2[i][0] = 0ull; acc2[i][1] = 0ull; }

    for (int k0 = 0; k0 < K; k0 += BK) {
        #pragma unroll
        for (int l = 0; l < 4; ++l) {
            int i = tid + l * 256;
            int r = i >> 4, c = i & 15;
            int m = m0 + r, k = k0 + c;
            As[c * LDSR + r] = (m < M && k < K) ? A[(size_t)m * K + k] : 0.f;
        }
        #pragma unroll
        for (int l = 0; l < 4; ++l) {
            int i = tid + l * 256;
            int r = i >> 4, c = i & 15;
            int n = n0 + r, k = k0 + c;
            Bs[c * LDSR + r] = (n < N && k < K) ? B[(size_t)n * K + k] : 0.f;
        }
        __syncthreads();
        #pragma unroll
        for (int kk = 0; kk < BK; ++kk) {
            float4 a4 = *(const float4*)(As + kk * LDSR + ty * 4);
            F4U bu; bu.f4 = *(const float4*)(Bs + kk * LDSR + tx * 4);
            float av[4] = {a4.x, a4.y, a4.z, a4.w};
            #pragma unroll
            for (int i = 0; i < 4; ++i) {
                unsigned long long ap = pk2(av[i], av[i]);
                fma2(acc2[i][0], ap, bu.u[0]);
                fma2(acc2[i][1], ap, bu.u[1]);
            }
        }
        __syncthreads();
    }

    float bv[4];
    #pragma unroll
    for (int j = 0; j < 4; ++j) {
        int n = n0 + tx * 4 + j;
        float v = 0.f;
        if (n < N) {
            if (bias1) v += bias1[n];
            if (bias2) v += bias2[n];
        }
        bv[j] = v;
    }

    if (!lossOut) {
        #pragma unroll
        for (int i = 0; i < 4; ++i) {
            int m = m0 + ty * 4 + i;
            if (m < M) {
                float2 c01 = up2(acc2[i][0]);
                float2 c23 = up2(acc2[i][1]);
                float cj[4] = {c01.x, c01.y, c23.x, c23.y};
                #pragma unroll
                for (int j = 0; j < 4; ++j) {
                    int n = n0 + tx * 4 + j;
                    if (n < N) C[(size_t)m * N + n] = cj[j] + bv[j];
                }
            }
        }
    } else {
        float ls = 0.f;
        #pragma unroll
        for (int i = 0; i < 4; ++i) {
            int m = m0 + ty * 4 + i;
            if (m < M) {
                const float* rrow;
                if (revT > 0) {
                    int b = m / revT, t = m - b * revT;
                    rrow = ref + ((size_t)b * revT + (revT - 1 - t)) * N;
                } else {
                    rrow = ref + (size_t)m * N;
                }
                float2 c01 = up2(acc2[i][0]);
                float2 c23 = up2(acc2[i][1]);
                float cj[4] = {c01.x, c01.y, c23.x, c23.y};
                #pragma unroll
                for (int j = 0; j < 4; ++j) {
                    int n = n0 + tx * 4 + j;
                    if (n < N) {
                        float d = cj[j] + bv[j] - rrow[n];
                        ls = fmaf(d, d, ls);
                    }
                }
            }
        }
        red[tid] = ls;
        __syncthreads();
        for (int s = 128; s > 0; s >>= 1) {
            if (tid < s) red[tid] += red[tid + s];
            __syncthreads();
        }
        if (tid == 0) atomicAdd(lossOut, red[0]);
    }
}

// ---------------- LSTM recurrence kernels ----------------------------------
// 8 batch elements per CTA (4 f32x2 pairs), 128 threads (100 active).
// Thread tid<100 owns k-slice tid: computes gates {tid, tid+100, tid+200, tid+300}
// for all 8 batches, then does the cell update for k=tid with c in registers.
// Weight transposed in smem with 401-float row pitch (conflict-free).
// h double-buffered in smem -> one __syncthreads per step.

#define WPITCH 401
#define RNN_SMEM_F (WPITCH * 100 + 800 + 800)   // sWT | sHa(float2[400]) | sHb

__global__ __launch_bounds__(128, 1) void rnn_enc(
    const float* __restrict__ X, const float* __restrict__ Whh,
    float* __restrict__ hf, float* __restrict__ cf)
{
    extern __shared__ float s[];
    float* sWT = s;                       // [100][401] : sWT[k*401 + j]
    float* sHa = s + WPITCH * 100;        // float2[400] : pair-major per k
    float* sHb = sHa + 800;
    const int tid = threadIdx.x;
    const int b0 = blockIdx.x * 8;

    for (int idx = tid; idx < G4 * HSZ; idx += 128) {
        int j = idx / HSZ, k = idx - j * HSZ;   // Whh[j][k]
        sWT[k * WPITCH + j] = Whh[idx];
    }
    for (int i = tid; i < 800; i += 128) sHa[i] = 0.f;
    __syncthreads();

    float cc[8], hh[8];
    #pragma unroll
    for (int b = 0; b < 8; ++b) { cc[b] = 0.f; hh[b] = 0.f; }

    for (int t = 0; t < TSZ; ++t) {
        const float* hin = (t & 1) ? sHb : sHa;
        float* hout = (t & 1) ? sHa : sHb;
        if (tid < 100) {
            // prefetch this step's precomputed gate inputs (DRAM, overlaps GEMM)
            float xr[4][8];
            #pragma unroll
            for (int q = 0; q < 4; ++q)
                #pragma unroll
                for (int b = 0; b < 8; ++b)
                    xr[q][b] = X[((size_t)(b0 + b) * TSZ + t) * G4 + tid + q * 100];

            unsigned long long acc[4][4];  // [pair][gate-q]
            #pragma unroll
            for (int p = 0; p < 4; ++p)
                #pragma unroll
                for (int q = 0; q < 4; ++q) acc[p][q] = 0ull;

            const float* wp = sWT + tid;
            const float* hp = hin;
            #pragma unroll 4
            for (int k = 0; k < 100; ++k) {
                F4U h01, h23;
                h01.f4 = *(const float4*)(hp);
                h23.f4 = *(const float4*)(hp + 4);
                #pragma unroll
                for (int q = 0; q < 4; ++q) {
                    float w = wp[q * 100];
                    unsigned long long w2 = pk2(w, w);
                    fma2(acc[0][q], h01.u[0], w2);
                    fma2(acc[1][q], h01.u[1], w2);
                    fma2(acc[2][q], h23.u[0], w2);
                    fma2(acc[3][q], h23.u[1], w2);
                }
                wp += WPITCH;
                hp += 8;
            }

            // cell update for k = tid, all 8 batches
            #pragma unroll
            for (int p = 0; p < 4; ++p) {
                float2 vi = up2(acc[p][0]);
                float2 vf = up2(acc[p][1]);
                float2 vg = up2(acc[p][2]);
                float2 vo = up2(acc[p][3]);
                int be = 2 * p, bo = 2 * p + 1;
                float he = cell_up(vi.x + xr[0][be], vf.x + xr[1][be],
                                   vg.x + xr[2][be], vo.x + xr[3][be], cc[be]);
                float ho = cell_up(vi.y + xr[0][bo], vf.y + xr[1][bo],
                                   vg.y + xr[2][bo], vo.y + xr[3][bo], cc[bo]);
                hh[be] = he; hh[bo] = ho;
                ((float2*)hout)[tid * 4 + p] = make_float2(he, ho);
            }
        }
        __syncthreads();
    }

    if (tid < 100) {
        #pragma unroll
        for (int b = 0; b < 8; ++b) {
            hf[(b0 + b) * HSZ + tid] = hh[b];
            cf[(b0 + b) * HSZ + tid] = cc[b];
        }
    }
}

__global__ __launch_bounds__(128, 1) void rnn_dec(
    const float* __restrict__ G0, const float* __restrict__ Weff,
    const float* __restrict__ beff,
    const float* __restrict__ h0, const float* __restrict__ c0,
    float* __restrict__ hall)
{
    extern __shared__ float s[];
    float* sWT = s;
    float* sHa = s + WPITCH * 100;
    float* sHb = sHa + 800;
    const int tid = threadIdx.x;
    const int b0 = blockIdx.x * 8;

    for (int idx = tid; idx < G4 * HSZ; idx += 128) {
        int j = idx / HSZ, k = idx - j * HSZ;
        sWT[k * WPITCH + j] = Weff[idx];
    }

    float cc[8];
    float bq[4];
    if (tid < 100) {
        #pragma unroll
        for (int q = 0; q < 4; ++q) bq[q] = beff[tid + q * 100];
        #pragma unroll
        for (int p = 0; p < 4; ++p) {
            float he = h0[(b0 + 2 * p) * HSZ + tid];
            float ho = h0[(b0 + 2 * p + 1) * HSZ + tid];
            ((float2*)sHa)[tid * 4 + p] = make_float2(he, ho);
        }
        #pragma unroll
        for (int b = 0; b < 8; ++b) cc[b] = c0[(b0 + b) * HSZ + tid];
    }
    __syncthreads();

    for (int t = 0; t < TSZ; ++t) {
        const float* hin = (t & 1) ? sHb : sHa;
        float* hout = (t & 1) ? sHa : sHb;
        if (tid < 100) {
            float gr[4][8];   // gate pre-activations per [q][batch]
            if (t == 0) {
                // step 0 gates fully precomputed: G0 = h_enc@Whh^T + bih + bhh
                #pragma unroll
                for (int q = 0; q < 4; ++q)
                    #pragma unroll
                    for (int b = 0; b < 8; ++b)
                        gr[q][b] = G0[(size_t)(b0 + b) * G4 + tid + q * 100];
            } else {
                unsigned long long acc[4][4];
                #pragma unroll
                for (int p = 0; p < 4; ++p)
                    #pragma unroll
                    for (int q = 0; q < 4; ++q) acc[p][q] = 0ull;

                const float* wp = sWT + tid;
                const float* hp = hin;
                #pragma unroll 4
                for (int k = 0; k < 100; ++k) {
                    F4U h01, h23;
                    h01.f4 = *(const float4*)(hp);
                    h23.f4 = *(const float4*)(hp + 4);
                    #pragma unroll
                    for (int q = 0; q < 4; ++q) {
                        float w = wp[q * 100];
                        unsigned long long w2 = pk2(w, w);
                        fma2(acc[0][q], h01.u[0], w2);
                        fma2(acc[1][q], h01.u[1], w2);
                        fma2(acc[2][q], h23.u[0], w2);
                        fma2(acc[3][q], h23.u[1], w2);
                    }
                    wp += WPITCH;
                    hp += 8;
                }
                #pragma unroll
                for (int p = 0; p < 4; ++p) {
                    #pragma unroll
                    for (int q = 0; q < 4; ++q) {
                        float2 v = up2(acc[p][q]);
                        gr[q][2 * p]     = v.x + bq[q];
                        gr[q][2 * p + 1] = v.y + bq[q];
                    }
                }
            }

            #pragma unroll
            for (int p = 0; p < 4; ++p) {
                int be = 2 * p, bo = 2 * p + 1;
                float he = cell_up(gr[0][be], gr[1][be], gr[2][be], gr[3][be], cc[be]);
                float ho = cell_up(gr[0][bo], gr[1][bo], gr[2][bo], gr[3][bo], cc[bo]);
                ((float2*)hout)[tid * 4 + p] = make_float2(he, ho);
                hall[((size_t)(b0 + be) * TSZ + t) * HSZ + tid] = he;
                hall[((size_t)(b0 + bo) * TSZ + t) * HSZ + tid] = ho;
            }
        }
        __syncthreads();
    }
}

// ---------------- launch ----------------------------------------------------
extern "C" void kernel_launch(void* const* d_in, const int* in_sizes, int n_in,
                              void* d_out, int out_size)
{
    const float* src     = (const float*)d_in[0];
    const float* trg     = (const float*)d_in[1];
    const float* enc_Wih = (const float*)d_in[2];
    const float* enc_Whh = (const float*)d_in[3];
    const float* enc_bih = (const float*)d_in[4];
    const float* enc_bhh = (const float*)d_in[5];
    const float* pd_Wih  = (const float*)d_in[6];
    const float* pd_Whh  = (const float*)d_in[7];
    const float* pd_bih  = (const float*)d_in[8];
    const float* pd_bhh  = (const float*)d_in[9];
    const float* pd_fcW  = (const float*)d_in[10];
    const float* pd_fcb  = (const float*)d_in[11];
    const float* rd_Wih  = (const float*)d_in[12];
    const float* rd_Whh  = (const float*)d_in[13];
    const float* rd_bih  = (const float*)d_in[14];
    const float* rd_bhh  = (const float*)d_in[15];
    const float* rd_fcW  = (const float*)d_in[16];
    const float* rd_fcb  = (const float*)d_in[17];
    float* out = (float*)d_out;

    float *pX, *pHenc, *pCenc, *pG0, *pWeff, *pBeff, *pHdec, *pLoss;
    cudaGetSymbolAddress((void**)&pX,    g_X);
    cudaGetSymbolAddress((void**)&pHenc, g_henc);
    cudaGetSymbolAddress((void**)&pCenc, g_cenc);
    cudaGetSymbolAddress((void**)&pG0,   g_G0);
    cudaGetSymbolAddress((void**)&pWeff, g_Weff);
    cudaGetSymbolAddress((void**)&pBeff, g_beff);
    cudaGetSymbolAddress((void**)&pHdec, g_hdec);
    cudaGetSymbolAddress((void**)&pLoss, g_loss);

    const int SMEM_RNN = RNN_SMEM_F * 4;
    cudaFuncSetAttribute(rnn_enc, cudaFuncAttributeMaxDynamicSharedMemorySize, SMEM_RNN);
    cudaFuncSetAttribute(rnn_dec, cudaFuncAttributeMaxDynamicSharedMemorySize, SMEM_RNN);

    const int RNN_BLOCKS = BSZ / 8;  // 125

    zero_loss_kernel<<<1, 1>>>(pLoss);

    // Phase A: X = src @ enc_Wih^T + (enc_bih + enc_bhh)   [100000 x 400]
    {
        dim3 grid((G4 + 63) / 64, (BSZ * TSZ + 63) / 64);
        gemm_nt<<<grid, 256>>>(src, enc_Wih, enc_bih, enc_bhh, pX,
                               BSZ * TSZ, G4, ISZ, nullptr, nullptr, 0);
    }

    // Encoder recurrence
    rnn_enc<<<RNN_BLOCKS, 128, SMEM_RNN>>>(pX, enc_Whh, pHenc, pCenc);

    // ---- predict decoder ----
    fold_kernel<<<G4, 128>>>(pd_Wih, pd_Whh, pd_fcW, pd_fcb, pd_bih, pd_bhh, pWeff, pBeff);
    {
        dim3 grid((G4 + 63) / 64, (BSZ + 63) / 64);
        gemm_nt<<<grid, 256>>>(pHenc, pd_Whh, pd_bih, pd_bhh, pG0,
                               BSZ, G4, HSZ, nullptr, nullptr, 0);
    }
    rnn_dec<<<RNN_BLOCKS, 128, SMEM_RNN>>>(pG0, pWeff, pBeff, pHenc, pCenc, pHdec);
    {
        dim3 grid((ISZ + 63) / 64, (BSZ * TSZ + 63) / 64);
        gemm_nt<<<grid, 256>>>(pHdec, pd_fcW, pd_fcb, nullptr, nullptr,
                               BSZ * TSZ, ISZ, HSZ, trg, pLoss + 1, 0);
    }

    // ---- reconstruct decoder ----
    fold_kernel<<<G4, 128>>>(rd_Wih, rd_Whh, rd_fcW, rd_fcb, rd_bih, rd_bhh, pWeff, pBeff);
    {
        dim3 grid((G4 + 63) / 64, (BSZ + 63) / 64);
        gemm_nt<<<grid, 256>>>(pHenc, rd_Whh, rd_bih, rd_bhh, pG0,
                               BSZ, G4, HSZ, nullptr, nullptr, 0);
    }
    rnn_dec<<<RNN_BLOCKS, 128, SMEM_RNN>>>(pG0, pWeff, pBeff, pHenc, pCenc, pHdec);
    {
        dim3 grid((ISZ + 63) / 64, (BSZ * TSZ + 63) / 64);
        gemm_nt<<<grid, 256>>>(pHdec, rd_fcW, rd_fcb, nullptr, nullptr,
                               BSZ * TSZ, ISZ, HSZ, src, pLoss + 0, TSZ);
    }

    finalize_kernel<<<1, 1>>>(pLoss, out, 1.0f / (float)(BSZ * TSZ * ISZ));
}

// round 4
// speedup vs baseline: 1.5256x; 1.5256x over previous
#include <cuda_runtime.h>
#include <math.h>

#define BSZ 1000
#define TSZ 100
#define ISZ 264
#define HSZ 100
#define G4  400   // 4*H

// ---------------- device scratch (static: no allocation allowed) ----------
__device__ float g_X[(size_t)BSZ * TSZ * G4];     // encoder gate inputs, 160MB
__device__ float g_henc[BSZ * HSZ];
__device__ float g_cenc[BSZ * HSZ];
__device__ float g_G0[BSZ * G4];                  // decoder step-0 gates
__device__ float g_Weff[2][G4 * HSZ];             // folded decoder recurrence weights
__device__ float g_beff[2][G4];                   // folded decoder biases
__device__ float g_hdec[(size_t)BSZ * TSZ * HSZ]; // decoder hidden states, 40MB
__device__ float g_loss[2];                       // [0]=reconstruct sum, [1]=predict sum

__device__ __forceinline__ float sigf(float x) { return 1.f / (1.f + expf(-x)); }

// ---------------- small kernels -------------------------------------------
__global__ void zero_loss_kernel(float* loss) { loss[0] = 0.f; loss[1] = 0.f; }

__global__ void finalize_kernel(const float* loss, float* out, float inv) {
    out[0] = loss[0] * inv;   // reconstruct_loss
    out[1] = loss[1] * inv;   // predict_loss
}

// Weff[j][k] = Whh[j][k] + sum_i Wih[j][i]*fcW[i][k]
// beff[j]    = bih[j] + bhh[j] + sum_i Wih[j][i]*fcb[i]
__global__ __launch_bounds__(128) void fold_kernel(
    const float* __restrict__ Wih, const float* __restrict__ Whh,
    const float* __restrict__ fcW, const float* __restrict__ fcb,
    const float* __restrict__ bih, const float* __restrict__ bhh,
    float* __restrict__ Weff, float* __restrict__ beff)
{
    int j = blockIdx.x;          // 0..399
    int tid = threadIdx.x;       // 128
    __shared__ float swih[ISZ];
    __shared__ float red[128];
    for (int i = tid; i < ISZ; i += 128) swih[i] = Wih[j * ISZ + i];
    __syncthreads();
    if (tid < HSZ) {
        float acc = Whh[j * HSZ + tid];
        #pragma unroll 4
        for (int i = 0; i < ISZ; ++i)
            acc = fmaf(swih[i], fcW[i * HSZ + tid], acc);
        Weff[j * HSZ + tid] = acc;
    }
    float p = 0.f;
    for (int i = tid; i < ISZ; i += 128) p = fmaf(swih[i], fcb[i], p);
    red[tid] = p;
    __syncthreads();
    for (int s = 64; s > 0; s >>= 1) {
        if (tid < s) red[tid] += red[tid + s];
        __syncthreads();
    }
    if (tid == 0) beff[j] = bih[j] + bhh[j] + red[0];
}

// ---------------- generic NT GEMM: C = A*B^T (+bias), optional MSE epilogue
// A: [M,K] row-major, B: [N,K] row-major. 128x64 tile, 8x4/thread, BK=8.
#define APITCH 136
#define BPITCH 68
__global__ __launch_bounds__(256) void gemm_nt(
    const float* __restrict__ A, const float* __restrict__ B,
    const float* __restrict__ bias1, const float* __restrict__ bias2,
    float* __restrict__ C, int M, int N, int K,
    const float* __restrict__ ref, float* __restrict__ lossOut, int revT)
{
    __shared__ float As[8 * APITCH];   // [k][m], 128 rows
    __shared__ float Bs[8 * BPITCH];   // [k][n], 64 rows
    __shared__ float red[256];
    const int tid = threadIdx.x;
    const int tx = tid & 15, ty = tid >> 4;
    const int m0 = blockIdx.y * 128, n0 = blockIdx.x * 64;

    float acc[8][4];
    #pragma unroll
    for (int i = 0; i < 8; ++i)
        #pragma unroll
        for (int j = 0; j < 4; ++j) acc[i][j] = 0.f;

    const int ar = tid >> 1;          // 0..127
    const int ac = (tid & 1) * 4;     // 0 or 4
    const int br = (tid & 127) >> 1;  // 0..63
    const int bc = (tid & 1) * 4;

    for (int k0 = 0; k0 < K; k0 += 8) {
        {
            int m = m0 + ar;
            const float* ap = A + (size_t)m * K + k0 + ac;
            #pragma unroll
            for (int j = 0; j < 4; ++j) {
                int k = k0 + ac + j;
                As[(ac + j) * APITCH + ar] = (m < M && k < K) ? ap[j] : 0.f;
            }
        }
        if (tid < 128) {
            int n = n0 + br;
            const float* bp = B + (size_t)n * K + k0 + bc;
            #pragma unroll
            for (int j = 0; j < 4; ++j) {
                int k = k0 + bc + j;
                Bs[(bc + j) * BPITCH + br] = (n < N && k < K) ? bp[j] : 0.f;
            }
        }
        __syncthreads();
        #pragma unroll
        for (int kk = 0; kk < 8; ++kk) {
            float4 a0 = *(const float4*)(As + kk * APITCH + ty * 8);
            float4 a1 = *(const float4*)(As + kk * APITCH + ty * 8 + 4);
            float4 b  = *(const float4*)(Bs + kk * BPITCH + tx * 4);
            float av[8] = {a0.x, a0.y, a0.z, a0.w, a1.x, a1.y, a1.z, a1.w};
            float bv[4] = {b.x, b.y, b.z, b.w};
            #pragma unroll
            for (int i = 0; i < 8; ++i)
                #pragma unroll
                for (int j = 0; j < 4; ++j)
                    acc[i][j] = fmaf(av[i], bv[j], acc[i][j]);
        }
        __syncthreads();
    }

    float bb[4];
    #pragma unroll
    for (int j = 0; j < 4; ++j) {
        int n = n0 + tx * 4 + j;
        float v = 0.f;
        if (n < N) {
            if (bias1) v += bias1[n];
            if (bias2) v += bias2[n];
        }
        bb[j] = v;
    }

    if (!lossOut) {
        #pragma unroll
        for (int i = 0; i < 8; ++i) {
            int m = m0 + ty * 8 + i;
            if (m < M) {
                #pragma unroll
                for (int j = 0; j < 4; ++j) {
                    int n = n0 + tx * 4 + j;
                    if (n < N) C[(size_t)m * N + n] = acc[i][j] + bb[j];
                }
            }
        }
    } else {
        float ls = 0.f;
        #pragma unroll
        for (int i = 0; i < 8; ++i) {
            int m = m0 + ty * 8 + i;
            if (m < M) {
                const float* rrow;
                if (revT > 0) {
                    int b = m / revT, t = m - b * revT;
                    rrow = ref + ((size_t)b * revT + (revT - 1 - t)) * N;
                } else {
                    rrow = ref + (size_t)m * N;
                }
                #pragma unroll
                for (int j = 0; j < 4; ++j) {
                    int n = n0 + tx * 4 + j;
                    if (n < N) {
                        float d = acc[i][j] + bb[j] - rrow[n];
                        ls = fmaf(d, d, ls);
                    }
                }
            }
        }
        red[tid] = ls;
        __syncthreads();
        for (int s = 128; s > 0; s >>= 1) {
            if (tid < s) red[tid] += red[tid + s];
            __syncthreads();
        }
        if (tid == 0) atomicAdd(lossOut, red[0]);
    }
}

// ---------------- LSTM recurrence kernels ----------------------------------
// 416 threads (13 warps), 8 batch elements per CTA (125 CTAs).
// Thread tid<400 owns gate row j=tid: acc[j] over k for 8 batches.
// Weight transposed in smem, pitch 401 (conflict-free stride-1 loads).
// Gate activations exchanged via sG (pitch 9, conflict-free); cell update by
// threads tid<100 with c in registers; h double-buffered -> 2 syncs/step.

#define WPITCH 401
#define NT_RNN 416
// sWT 40100 | sHa 800 | sHb 800 | sG 3600
#define RNN_SMEM_F (40100 + 800 + 800 + 3600)

__global__ __launch_bounds__(NT_RNN, 1) void rnn_enc(
    const float* __restrict__ X, const float* __restrict__ Whh,
    float* __restrict__ hf, float* __restrict__ cf)
{
    extern __shared__ float s[];
    float* sWT = s;                 // [k][j] pitch 401
    float* sHa = s + 40100;         // [k][b] k*8+b
    float* sHb = sHa + 800;
    float* sG  = sHb + 800;         // [j][b] pitch 9
    const int tid = threadIdx.x;
    const int b0 = blockIdx.x * 8;

    for (int idx = tid; idx < G4 * HSZ; idx += NT_RNN) {
        int j = idx / HSZ, k = idx - j * HSZ;   // Whh[j][k]
        sWT[k * WPITCH + j] = Whh[idx];
    }
    for (int i = tid; i < 800; i += NT_RNN) sHa[i] = 0.f;
    __syncthreads();

    float cc[8], hh[8];
    #pragma unroll
    for (int b = 0; b < 8; ++b) { cc[b] = 0.f; hh[b] = 0.f; }
    const bool isG = (tid >= 200 && tid < 300);

    for (int t = 0; t < TSZ; ++t) {
        const float* hin = (t & 1) ? sHb : sHa;
        float* hout = (t & 1) ? sHa : sHb;
        if (tid < 400) {
            float xr[8];
            #pragma unroll
            for (int b = 0; b < 8; ++b)
                xr[b] = X[((size_t)(b0 + b) * TSZ + t) * G4 + tid];
            float acc[8];
            #pragma unroll
            for (int b = 0; b < 8; ++b) acc[b] = 0.f;
            const float* wp = sWT + tid;
            const float* hp = hin;
            #pragma unroll 4
            for (int k = 0; k < HSZ; ++k) {
                float w = wp[0];
                float4 h0 = *(const float4*)(hp);
                float4 h1 = *(const float4*)(hp + 4);
                acc[0] = fmaf(w, h0.x, acc[0]);
                acc[1] = fmaf(w, h0.y, acc[1]);
                acc[2] = fmaf(w, h0.z, acc[2]);
                acc[3] = fmaf(w, h0.w, acc[3]);
                acc[4] = fmaf(w, h1.x, acc[4]);
                acc[5] = fmaf(w, h1.y, acc[5]);
                acc[6] = fmaf(w, h1.z, acc[6]);
                acc[7] = fmaf(w, h1.w, acc[7]);
                wp += WPITCH;
                hp += 8;
            }
            float* gp = sG + tid * 9;
            #pragma unroll
            for (int b = 0; b < 8; ++b) {
                float v = acc[b] + xr[b];
                gp[b] = isG ? tanhf(v) : sigf(v);
            }
        }
        __syncthreads();
        if (tid < 100) {
            const float* gi = sG + tid * 9;
            const float* gf = sG + (100 + tid) * 9;
            const float* gg = sG + (200 + tid) * 9;
            const float* go = sG + (300 + tid) * 9;
            #pragma unroll
            for (int b = 0; b < 8; ++b) {
                float c = fmaf(gf[b], cc[b], gi[b] * gg[b]);
                cc[b] = c;
                hh[b] = go[b] * tanhf(c);
            }
            *(float4*)(hout + tid * 8)     = make_float4(hh[0], hh[1], hh[2], hh[3]);
            *(float4*)(hout + tid * 8 + 4) = make_float4(hh[4], hh[5], hh[6], hh[7]);
        }
        __syncthreads();
    }

    if (tid < 100) {
        #pragma unroll
        for (int b = 0; b < 8; ++b) {
            hf[(b0 + b) * HSZ + tid] = hh[b];
            cf[(b0 + b) * HSZ + tid] = cc[b];
        }
    }
}

__global__ __launch_bounds__(NT_RNN, 1) void rnn_dec(
    const float* __restrict__ G0, const float* __restrict__ Weff,
    const float* __restrict__ beff,
    const float* __restrict__ h0, const float* __restrict__ c0,
    float* __restrict__ hall)
{
    extern __shared__ float s[];
    float* sWT = s;
    float* sHa = s + 40100;
    float* sHb = sHa + 800;
    float* sG  = sHb + 800;
    const int tid = threadIdx.x;
    const int b0 = blockIdx.x * 8;

    for (int idx = tid; idx < G4 * HSZ; idx += NT_RNN) {
        int j = idx / HSZ, k = idx - j * HSZ;
        sWT[k * WPITCH + j] = Weff[idx];
    }
    float bq = (tid < 400) ? beff[tid] : 0.f;
    float cc[8];
    if (tid < 100) {
        float hb[8];
        #pragma unroll
        for (int b = 0; b < 8; ++b) {
            hb[b] = h0[(b0 + b) * HSZ + tid];
            cc[b] = c0[(b0 + b) * HSZ + tid];
        }
        *(float4*)(sHa + tid * 8)     = make_float4(hb[0], hb[1], hb[2], hb[3]);
        *(float4*)(sHa + tid * 8 + 4) = make_float4(hb[4], hb[5], hb[6], hb[7]);
    }
    __syncthreads();

    const bool isG = (tid >= 200 && tid < 300);

    for (int t = 0; t < TSZ; ++t) {
        const float* hin = (t & 1) ? sHb : sHa;
        float* hout = (t & 1) ? sHa : sHb;
        if (tid < 400) {
            float v8[8];
            if (t == 0) {
                // step-0 gates fully precomputed: G0 = h_enc@Whh^T + bih + bhh
                #pragma unroll
                for (int b = 0; b < 8; ++b)
                    v8[b] = G0[(size_t)(b0 + b) * G4 + tid];
            } else {
                float acc[8];
                #pragma unroll
                for (int b = 0; b < 8; ++b) acc[b] = 0.f;
                const float* wp = sWT + tid;
                const float* hp = hin;
                #pragma unroll 4
                for (int k = 0; k < HSZ; ++k) {
                    float w = wp[0];
                    float4 h0v = *(const float4*)(hp);
                    float4 h1v = *(const float4*)(hp + 4);
                    acc[0] = fmaf(w, h0v.x, acc[0]);
                    acc[1] = fmaf(w, h0v.y, acc[1]);
                    acc[2] = fmaf(w, h0v.z, acc[2]);
                    acc[3] = fmaf(w, h0v.w, acc[3]);
                    acc[4] = fmaf(w, h1v.x, acc[4]);
                    acc[5] = fmaf(w, h1v.y, acc[5]);
                    acc[6] = fmaf(w, h1v.z, acc[6]);
                    acc[7] = fmaf(w, h1v.w, acc[7]);
                    wp += WPITCH;
                    hp += 8;
                }
                #pragma unroll
                for (int b = 0; b < 8; ++b) v8[b] = acc[b] + bq;
            }
            float* gp = sG + tid * 9;
            #pragma unroll
            for (int b = 0; b < 8; ++b)
                gp[b] = isG ? tanhf(v8[b]) : sigf(v8[b]);
        }
        __syncthreads();
        if (tid < 100) {
            const float* gi = sG + tid * 9;
            const float* gf = sG + (100 + tid) * 9;
            const float* gg = sG + (200 + tid) * 9;
            const float* go = sG + (300 + tid) * 9;
            float hb[8];
            #pragma unroll
            for (int b = 0; b < 8; ++b) {
                float c = fmaf(gf[b], cc[b], gi[b] * gg[b]);
                cc[b] = c;
                float h = go[b] * tanhf(c);
                hb[b] = h;
                hall[((size_t)(b0 + b) * TSZ + t) * HSZ + tid] = h;
            }
            *(float4*)(hout + tid * 8)     = make_float4(hb[0], hb[1], hb[2], hb[3]);
            *(float4*)(hout + tid * 8 + 4) = make_float4(hb[4], hb[5], hb[6], hb[7]);
        }
        __syncthreads();
    }
}

// ---------------- launch ----------------------------------------------------
extern "C" void kernel_launch(void* const* d_in, const int* in_sizes, int n_in,
                              void* d_out, int out_size)
{
    const float* src     = (const float*)d_in[0];
    const float* trg     = (const float*)d_in[1];
    const float* enc_Wih = (const float*)d_in[2];
    const float* enc_Whh = (const float*)d_in[3];
    const float* enc_bih = (const float*)d_in[4];
    const float* enc_bhh = (const float*)d_in[5];
    const float* pd_Wih  = (const float*)d_in[6];
    const float* pd_Whh  = (const float*)d_in[7];
    const float* pd_bih  = (const float*)d_in[8];
    const float* pd_bhh  = (const float*)d_in[9];
    const float* pd_fcW  = (const float*)d_in[10];
    const float* pd_fcb  = (const float*)d_in[11];
    const float* rd_Wih  = (const float*)d_in[12];
    const float* rd_Whh  = (const float*)d_in[13];
    const float* rd_bih  = (const float*)d_in[14];
    const float* rd_bhh  = (const float*)d_in[15];
    const float* rd_fcW  = (const float*)d_in[16];
    const float* rd_fcb  = (const float*)d_in[17];
    float* out = (float*)d_out;

    float *pX, *pHenc, *pCenc, *pG0, *pWeff, *pBeff, *pHdec, *pLoss;
    cudaGetSymbolAddress((void**)&pX,    g_X);
    cudaGetSymbolAddress((void**)&pHenc, g_henc);
    cudaGetSymbolAddress((void**)&pCenc, g_cenc);
    cudaGetSymbolAddress((void**)&pG0,   g_G0);
    cudaGetSymbolAddress((void**)&pWeff, g_Weff);
    cudaGetSymbolAddress((void**)&pBeff, g_beff);
    cudaGetSymbolAddress((void**)&pHdec, g_hdec);
    cudaGetSymbolAddress((void**)&pLoss, g_loss);
    float* pWeff0 = pWeff;            // predict decoder
    float* pWeff1 = pWeff + G4 * HSZ; // reconstruct decoder
    float* pBeff0 = pBeff;
    float* pBeff1 = pBeff + G4;

    const int SMEM_RNN = RNN_SMEM_F * 4;
    cudaFuncSetAttribute(rnn_enc, cudaFuncAttributeMaxDynamicSharedMemorySize, SMEM_RNN);
    cudaFuncSetAttribute(rnn_dec, cudaFuncAttributeMaxDynamicSharedMemorySize, SMEM_RNN);

    const int RNN_BLOCKS = BSZ / 8;  // 125

    // Folds first (independent of everything; also puts big kernels in the
    // ncu capture slot).
    fold_kernel<<<G4, 128>>>(pd_Wih, pd_Whh, pd_fcW, pd_fcb, pd_bih, pd_bhh, pWeff0, pBeff0);
    fold_kernel<<<G4, 128>>>(rd_Wih, rd_Whh, rd_fcW, rd_fcb, rd_bih, rd_bhh, pWeff1, pBeff1);
    zero_loss_kernel<<<1, 1>>>(pLoss);

    // Phase A: X = src @ enc_Wih^T + (enc_bih + enc_bhh)   [100000 x 400]
    {
        dim3 grid((G4 + 63) / 64, (BSZ * TSZ + 127) / 128);
        gemm_nt<<<grid, 256>>>(src, enc_Wih, enc_bih, enc_bhh, pX,
                               BSZ * TSZ, G4, ISZ, nullptr, nullptr, 0);
    }

    // Encoder recurrence
    rnn_enc<<<RNN_BLOCKS, NT_RNN, SMEM_RNN>>>(pX, enc_Whh, pHenc, pCenc);

    // ---- predict decoder ----
    {
        dim3 grid((G4 + 63) / 64, (BSZ + 127) / 128);
        gemm_nt<<<grid, 256>>>(pHenc, pd_Whh, pd_bih, pd_bhh, pG0,
                               BSZ, G4, HSZ, nullptr, nullptr, 0);
    }
    rnn_dec<<<RNN_BLOCKS, NT_RNN, SMEM_RNN>>>(pG0, pWeff0, pBeff0, pHenc, pCenc, pHdec);
    {
        dim3 grid((ISZ + 63) / 64, (BSZ * TSZ + 127) / 128);
        gemm_nt<<<grid, 256>>>(pHdec, pd_fcW, pd_fcb, nullptr, nullptr,
                               BSZ * TSZ, ISZ, HSZ, trg, pLoss + 1, 0);
    }

    // ---- reconstruct decoder ----
    {
        dim3 grid((G4 + 63) / 64, (BSZ + 127) / 128);
        gemm_nt<<<grid, 256>>>(pHenc, rd_Whh, rd_bih, rd_bhh, pG0,
                               BSZ, G4, HSZ, nullptr, nullptr, 0);
    }
    rnn_dec<<<RNN_BLOCKS, NT_RNN, SMEM_RNN>>>(pG0, pWeff1, pBeff1, pHenc, pCenc, pHdec);
    {
        dim3 grid((ISZ + 63) / 64, (BSZ * TSZ + 127) / 128);
        gemm_nt<<<grid, 256>>>(pHdec, rd_fcW, rd_fcb, nullptr, nullptr,
                               BSZ * TSZ, ISZ, HSZ, src, pLoss + 0, TSZ);
    }

    finalize_kernel<<<1, 1>>>(pLoss, out, 1.0f / (float)(BSZ * TSZ * ISZ));
}

// round 5
// speedup vs baseline: 1.6034x; 1.0510x over previous
#include <cuda_runtime.h>
#include <math.h>

#define BSZ 1000
#define TSZ 100
#define ISZ 264
#define HSZ 100
#define G4  400   // 4*H

// ---------------- device scratch (static: no allocation allowed) ----------
__device__ float g_X[(size_t)BSZ * TSZ * G4];     // encoder gate inputs, 160MB
__device__ float g_henc[BSZ * HSZ];
__device__ float g_cenc[BSZ * HSZ];
__device__ float g_G0[BSZ * G4];                  // decoder step-0 gates
__device__ float g_Weff[2][G4 * HSZ];             // folded decoder recurrence weights
__device__ float g_beff[2][G4];                   // folded decoder biases
__device__ float g_hdec[(size_t)BSZ * TSZ * HSZ]; // decoder hidden states, 40MB
__device__ float g_loss[2];                       // [0]=reconstruct sum, [1]=predict sum

__device__ __forceinline__ float sigf(float x) { return 1.f / (1.f + expf(-x)); }

// ---------------- small kernels -------------------------------------------
__global__ void zero_loss_kernel(float* loss) { loss[0] = 0.f; loss[1] = 0.f; }

__global__ void finalize_kernel(const float* loss, float* out, float inv) {
    out[0] = loss[0] * inv;   // reconstruct_loss
    out[1] = loss[1] * inv;   // predict_loss
}

// Weff[j][k] = Whh[j][k] + sum_i Wih[j][i]*fcW[i][k]
// beff[j]    = bih[j] + bhh[j] + sum_i Wih[j][i]*fcb[i]
__global__ __launch_bounds__(128) void fold_kernel(
    const float* __restrict__ Wih, const float* __restrict__ Whh,
    const float* __restrict__ fcW, const float* __restrict__ fcb,
    const float* __restrict__ bih, const float* __restrict__ bhh,
    float* __restrict__ Weff, float* __restrict__ beff)
{
    int j = blockIdx.x;          // 0..399
    int tid = threadIdx.x;       // 128
    __shared__ float swih[ISZ];
    __shared__ float red[128];
    for (int i = tid; i < ISZ; i += 128) swih[i] = Wih[j * ISZ + i];
    __syncthreads();
    if (tid < HSZ) {
        float acc = Whh[j * HSZ + tid];
        #pragma unroll 4
        for (int i = 0; i < ISZ; ++i)
            acc = fmaf(swih[i], fcW[i * HSZ + tid], acc);
        Weff[j * HSZ + tid] = acc;
    }
    float p = 0.f;
    for (int i = tid; i < ISZ; i += 128) p = fmaf(swih[i], fcb[i], p);
    red[tid] = p;
    __syncthreads();
    for (int s = 64; s > 0; s >>= 1) {
        if (tid < s) red[tid] += red[tid + s];
        __syncthreads();
    }
    if (tid == 0) beff[j] = bih[j] + bhh[j] + red[0];
}

// ---------------- generic NT GEMM: C = A*B^T (+bias), optional MSE epilogue
// A: [M,K] row-major, B: [N,K] row-major. 256x64 tile, 8x8/thread, BK=8.
#define AP 264
#define BP 68
__global__ __launch_bounds__(256) void gemm_nt(
    const float* __restrict__ A, const float* __restrict__ B,
    const float* __restrict__ bias1, const float* __restrict__ bias2,
    float* __restrict__ C, int M, int N, int K,
    const float* __restrict__ ref, float* __restrict__ lossOut, int revT)
{
    __shared__ float As[8 * AP];   // [k][m], 256 m rows
    __shared__ float Bs[8 * BP];   // [k][n], 64 n rows
    __shared__ float red[256];
    const int tid = threadIdx.x;
    const int tx = tid & 7;        // n group (0..7)
    const int ty = tid >> 3;       // m group (0..31)
    const int m0 = blockIdx.y * 256, n0 = blockIdx.x * 64;

    float acc[8][8];
    #pragma unroll
    for (int i = 0; i < 8; ++i)
        #pragma unroll
        for (int j = 0; j < 8; ++j) acc[i][j] = 0.f;

    const int am = m0 + tid;           // one A row per thread
    const int br = tid >> 2;           // 0..63 B row
    const int bc = (tid & 3) * 2;      // 0,2,4,6 B col pair

    for (int k0 = 0; k0 < K; k0 += 8) {
        // ---- A tile: 256 x 8 ----
        if (am < M && k0 + 8 <= K) {
            const float* ap = A + (size_t)am * K + k0;
            float4 v0 = *(const float4*)(ap);
            float4 v1 = *(const float4*)(ap + 4);
            As[0 * AP + tid] = v0.x; As[1 * AP + tid] = v0.y;
            As[2 * AP + tid] = v0.z; As[3 * AP + tid] = v0.w;
            As[4 * AP + tid] = v1.x; As[5 * AP + tid] = v1.y;
            As[6 * AP + tid] = v1.z; As[7 * AP + tid] = v1.w;
        } else {
            #pragma unroll
            for (int j = 0; j < 8; ++j) {
                int k = k0 + j;
                As[j * AP + tid] = (am < M && k < K) ? A[(size_t)am * K + k] : 0.f;
            }
        }
        // ---- B tile: 64 x 8 ----
        {
            int n = n0 + br;
            #pragma unroll
            for (int j = 0; j < 2; ++j) {
                int k = k0 + bc + j;
                Bs[(bc + j) * BP + br] = (n < N && k < K) ? B[(size_t)n * K + k] : 0.f;
            }
        }
        __syncthreads();
        #pragma unroll
        for (int kk = 0; kk < 8; ++kk) {
            float4 a0 = *(const float4*)(As + kk * AP + ty * 8);
            float4 a1 = *(const float4*)(As + kk * AP + ty * 8 + 4);
            float4 b0 = *(const float4*)(Bs + kk * BP + tx * 8);
            float4 b1 = *(const float4*)(Bs + kk * BP + tx * 8 + 4);
            float av[8] = {a0.x, a0.y, a0.z, a0.w, a1.x, a1.y, a1.z, a1.w};
            float bv[8] = {b0.x, b0.y, b0.z, b0.w, b1.x, b1.y, b1.z, b1.w};
            #pragma unroll
            for (int i = 0; i < 8; ++i)
                #pragma unroll
                for (int j = 0; j < 8; ++j)
                    acc[i][j] = fmaf(av[i], bv[j], acc[i][j]);
        }
        __syncthreads();
    }

    float bb[8];
    #pragma unroll
    for (int j = 0; j < 8; ++j) {
        int n = n0 + tx * 8 + j;
        float v = 0.f;
        if (n < N) {
            if (bias1) v += bias1[n];
            if (bias2) v += bias2[n];
        }
        bb[j] = v;
    }

    if (!lossOut) {
        #pragma unroll
        for (int i = 0; i < 8; ++i) {
            int m = m0 + ty * 8 + i;
            if (m < M) {
                #pragma unroll
                for (int j = 0; j < 8; ++j) {
                    int n = n0 + tx * 8 + j;
                    if (n < N) C[(size_t)m * N + n] = acc[i][j] + bb[j];
                }
            }
        }
    } else {
        float ls = 0.f;
        #pragma unroll
        for (int i = 0; i < 8; ++i) {
            int m = m0 + ty * 8 + i;
            if (m < M) {
                const float* rrow;
                if (revT > 0) {
                    int b = m / revT, t = m - b * revT;
                    rrow = ref + ((size_t)b * revT + (revT - 1 - t)) * N;
                } else {
                    rrow = ref + (size_t)m * N;
                }
                #pragma unroll
                for (int j = 0; j < 8; ++j) {
                    int n = n0 + tx * 8 + j;
                    if (n < N) {
                        float d = acc[i][j] + bb[j] - rrow[n];
                        ls = fmaf(d, d, ls);
                    }
                }
            }
        }
        red[tid] = ls;
        __syncthreads();
        for (int s = 128; s > 0; s >>= 1) {
            if (tid < s) red[tid] += red[tid + s];
            __syncthreads();
        }
        if (tid == 0) atomicAdd(lossOut, red[0]);
    }
}

// ---------------- LSTM recurrence kernels ----------------------------------
// 416 threads (13 warps), 7 batch elements per CTA, 143 CTAs (wave fill 143/148).
// Gate phase: thread j<400 owns gate row j; weight in natural [j][k] layout
// (pitch 100, float4 loads, quad-bank 25j%8 -> conflict-free); h broadcast
// loads from [k][b] pitch-8 buffer; writes raw preactivation to sG (pitch 9).
// Cell phase: distributed over all threads, 2 (k,b) items each, c in registers.

#define NB 7
#define NT_RNN 416
// sW 40000 | sHa 800 | sHb 800 | sG 3600
#define RNN_SMEM_F (40000 + 800 + 800 + 3600)

__global__ __launch_bounds__(NT_RNN, 1) void rnn_enc(
    const float* __restrict__ X, const float* __restrict__ Whh,
    float* __restrict__ hf, float* __restrict__ cf)
{
    extern __shared__ float s[];
    float* sW  = s;                 // [j][k] pitch 100 (natural layout)
    float* sHa = s + 40000;         // [k][b] pitch 8
    float* sHb = sHa + 800;
    float* sG  = sHb + 800;         // [j][b] pitch 9, raw preactivations
    const int tid = threadIdx.x;
    const int b0 = blockIdx.x * NB;

    for (int i = tid; i < 10000; i += NT_RNN)
        ((float4*)sW)[i] = ((const float4*)Whh)[i];
    for (int i = tid; i < 800; i += NT_RNN) sHa[i] = 0.f;
    __syncthreads();

    // cell-phase ownership: items idx = b*100 + k, idx in {tid, tid+NT_RNN}
    const int i0 = tid, i1 = tid + NT_RNN;
    const int k0c = i0 % 100, b0c = i0 / 100;
    const int k1c = i1 % 100, b1c = i1 / 100;
    const bool v0 = (i0 < NB * 100), v1 = (i1 < NB * 100);
    float c0r = 0.f, c1r = 0.f, h0r = 0.f, h1r = 0.f;

    int bidx[NB];
    #pragma unroll
    for (int b = 0; b < NB; ++b) {
        int bb = b0 + b; if (bb > BSZ - 1) bb = BSZ - 1;
        bidx[b] = bb;
    }

    for (int t = 0; t < TSZ; ++t) {
        const float* hin = (t & 1) ? sHb : sHa;
        float* hout = (t & 1) ? sHa : sHb;
        if (tid < 400) {
            const int j = tid;
            float xr[NB];
            #pragma unroll
            for (int b = 0; b < NB; ++b)
                xr[b] = X[((size_t)bidx[b] * TSZ + t) * G4 + j];
            float acc[NB];
            #pragma unroll
            for (int b = 0; b < NB; ++b) acc[b] = 0.f;
            const float4* wj = (const float4*)(sW + j * 100);
            const float* hp = hin;
            #pragma unroll 5
            for (int k4 = 0; k4 < 25; ++k4) {
                float4 w = wj[k4];
                #pragma unroll
                for (int d = 0; d < 4; ++d) {
                    float wv = (d == 0) ? w.x : (d == 1) ? w.y : (d == 2) ? w.z : w.w;
                    float4 ha = *(const float4*)(hp + (k4 * 4 + d) * 8);
                    float4 hb = *(const float4*)(hp + (k4 * 4 + d) * 8 + 4);
                    acc[0] = fmaf(wv, ha.x, acc[0]);
                    acc[1] = fmaf(wv, ha.y, acc[1]);
                    acc[2] = fmaf(wv, ha.z, acc[2]);
                    acc[3] = fmaf(wv, ha.w, acc[3]);
                    acc[4] = fmaf(wv, hb.x, acc[4]);
                    acc[5] = fmaf(wv, hb.y, acc[5]);
                    acc[6] = fmaf(wv, hb.z, acc[6]);
                }
            }
            float* gp = sG + j * 9;
            #pragma unroll
            for (int b = 0; b < NB; ++b) gp[b] = acc[b] + xr[b];
        }
        __syncthreads();
        if (v0) {
            float gi = sigf(sG[(k0c) * 9 + b0c]);
            float gf = sigf(sG[(100 + k0c) * 9 + b0c]);
            float gg = tanhf(sG[(200 + k0c) * 9 + b0c]);
            float go = sigf(sG[(300 + k0c) * 9 + b0c]);
            c0r = fmaf(gf, c0r, gi * gg);
            h0r = go * tanhf(c0r);
            hout[k0c * 8 + b0c] = h0r;
        }
        if (v1) {
            float gi = sigf(sG[(k1c) * 9 + b1c]);
            float gf = sigf(sG[(100 + k1c) * 9 + b1c]);
            float gg = tanhf(sG[(200 + k1c) * 9 + b1c]);
            float go = sigf(sG[(300 + k1c) * 9 + b1c]);
            c1r = fmaf(gf, c1r, gi * gg);
            h1r = go * tanhf(c1r);
            hout[k1c * 8 + b1c] = h1r;
        }
        __syncthreads();
    }

    if (v0 && b0 + b0c < BSZ) {
        hf[(b0 + b0c) * HSZ + k0c] = h0r;
        cf[(b0 + b0c) * HSZ + k0c] = c0r;
    }
    if (v1 && b0 + b1c < BSZ) {
        hf[(b0 + b1c) * HSZ + k1c] = h1r;
        cf[(b0 + b1c) * HSZ + k1c] = c1r;
    }
}

__global__ __launch_bounds__(NT_RNN, 1) void rnn_dec(
    const float* __restrict__ G0, const float* __restrict__ Weff,
    const float* __restrict__ beff,
    const float* __restrict__ h0, const float* __restrict__ c0,
    float* __restrict__ hall)
{
    extern __shared__ float s[];
    float* sW  = s;
    float* sHa = s + 40000;
    float* sHb = sHa + 800;
    float* sG  = sHb + 800;
    const int tid = threadIdx.x;
    const int b0 = blockIdx.x * NB;

    for (int i = tid; i < 10000; i += NT_RNN)
        ((float4*)sW)[i] = ((const float4*)Weff)[i];

    const float bq = (tid < 400) ? beff[tid] : 0.f;

    const int i0 = tid, i1 = tid + NT_RNN;
    const int k0c = i0 % 100, b0c = i0 / 100;
    const int k1c = i1 % 100, b1c = i1 / 100;
    const bool v0 = (i0 < NB * 100), v1 = (i1 < NB * 100);
    float c0r = 0.f, c1r = 0.f;

    int bidx[NB];
    #pragma unroll
    for (int b = 0; b < NB; ++b) {
        int bb = b0 + b; if (bb > BSZ - 1) bb = BSZ - 1;
        bidx[b] = bb;
    }

    // init h (smem) and c (registers)
    if (v0) {
        sHa[k0c * 8 + b0c] = h0[bidx[b0c] * HSZ + k0c];
        c0r = c0[bidx[b0c] * HSZ + k0c];
    }
    if (v1) {
        sHa[k1c * 8 + b1c] = h0[bidx[b1c] * HSZ + k1c];
        c1r = c0[bidx[b1c] * HSZ + k1c];
    }
    __syncthreads();

    for (int t = 0; t < TSZ; ++t) {
        const float* hin = (t & 1) ? sHb : sHa;
        float* hout = (t & 1) ? sHa : sHb;
        if (tid < 400) {
            const int j = tid;
            float* gp = sG + j * 9;
            if (t == 0) {
                // step-0 gates fully precomputed: G0 = h_enc@Whh^T + bih + bhh
                #pragma unroll
                for (int b = 0; b < NB; ++b)
                    gp[b] = G0[(size_t)bidx[b] * G4 + j];
            } else {
                float acc[NB];
                #pragma unroll
                for (int b = 0; b < NB; ++b) acc[b] = 0.f;
                const float4* wj = (const float4*)(sW + j * 100);
                const float* hp = hin;
                #pragma unroll 5
                for (int k4 = 0; k4 < 25; ++k4) {
                    float4 w = wj[k4];
                    #pragma unroll
                    for (int d = 0; d < 4; ++d) {
                        float wv = (d == 0) ? w.x : (d == 1) ? w.y : (d == 2) ? w.z : w.w;
                        float4 ha = *(const float4*)(hp + (k4 * 4 + d) * 8);
                        float4 hb = *(const float4*)(hp + (k4 * 4 + d) * 8 + 4);
                        acc[0] = fmaf(wv, ha.x, acc[0]);
                        acc[1] = fmaf(wv, ha.y, acc[1]);
                        acc[2] = fmaf(wv, ha.z, acc[2]);
                        acc[3] = fmaf(wv, ha.w, acc[3]);
                        acc[4] = fmaf(wv, hb.x, acc[4]);
                        acc[5] = fmaf(wv, hb.y, acc[5]);
                        acc[6] = fmaf(wv, hb.z, acc[6]);
                    }
                }
                #pragma unroll
                for (int b = 0; b < NB; ++b) gp[b] = acc[b] + bq;
            }
        }
        __syncthreads();
        if (v0) {
            float gi = sigf(sG[(k0c) * 9 + b0c]);
            float gf = sigf(sG[(100 + k0c) * 9 + b0c]);
            float gg = tanhf(sG[(200 + k0c) * 9 + b0c]);
            float go = sigf(sG[(300 + k0c) * 9 + b0c]);
            c0r = fmaf(gf, c0r, gi * gg);
            float h = go * tanhf(c0r);
            hout[k0c * 8 + b0c] = h;
            if (b0 + b0c < BSZ)
                hall[((size_t)(b0 + b0c) * TSZ + t) * HSZ + k0c] = h;
        }
        if (v1) {
            float gi = sigf(sG[(k1c) * 9 + b1c]);
            float gf = sigf(sG[(100 + k1c) * 9 + b1c]);
            float gg = tanhf(sG[(200 + k1c) * 9 + b1c]);
            float go = sigf(sG[(300 + k1c) * 9 + b1c]);
            c1r = fmaf(gf, c1r, gi * gg);
            float h = go * tanhf(c1r);
            hout[k1c * 8 + b1c] = h;
            if (b0 + b1c < BSZ)
                hall[((size_t)(b0 + b1c) * TSZ + t) * HSZ + k1c] = h;
        }
        __syncthreads();
    }
}

// ---------------- launch ----------------------------------------------------
extern "C" void kernel_launch(void* const* d_in, const int* in_sizes, int n_in,
                              void* d_out, int out_size)
{
    const float* src     = (const float*)d_in[0];
    const float* trg     = (const float*)d_in[1];
    const float* enc_Wih = (const float*)d_in[2];
    const float* enc_Whh = (const float*)d_in[3];
    const float* enc_bih = (const float*)d_in[4];
    const float* enc_bhh = (const float*)d_in[5];
    const float* pd_Wih  = (const float*)d_in[6];
    const float* pd_Whh  = (const float*)d_in[7];
    const float* pd_bih  = (const float*)d_in[8];
    const float* pd_bhh  = (const float*)d_in[9];
    const float* pd_fcW  = (const float*)d_in[10];
    const float* pd_fcb  = (const float*)d_in[11];
    const float* rd_Wih  = (const float*)d_in[12];
    const float* rd_Whh  = (const float*)d_in[13];
    const float* rd_bih  = (const float*)d_in[14];
    const float* rd_bhh  = (const float*)d_in[15];
    const float* rd_fcW  = (const float*)d_in[16];
    const float* rd_fcb  = (const float*)d_in[17];
    float* out = (float*)d_out;

    float *pX, *pHenc, *pCenc, *pG0, *pWeff, *pBeff, *pHdec, *pLoss;
    cudaGetSymbolAddress((void**)&pX,    g_X);
    cudaGetSymbolAddress((void**)&pHenc, g_henc);
    cudaGetSymbolAddress((void**)&pCenc, g_cenc);
    cudaGetSymbolAddress((void**)&pG0,   g_G0);
    cudaGetSymbolAddress((void**)&pWeff, g_Weff);
    cudaGetSymbolAddress((void**)&pBeff, g_beff);
    cudaGetSymbolAddress((void**)&pHdec, g_hdec);
    cudaGetSymbolAddress((void**)&pLoss, g_loss);
    float* pWeff0 = pWeff;            // predict decoder
    float* pWeff1 = pWeff + G4 * HSZ; // reconstruct decoder
    float* pBeff0 = pBeff;
    float* pBeff1 = pBeff + G4;

    const int SMEM_RNN = RNN_SMEM_F * 4;
    cudaFuncSetAttribute(rnn_enc, cudaFuncAttributeMaxDynamicSharedMemorySize, SMEM_RNN);
    cudaFuncSetAttribute(rnn_dec, cudaFuncAttributeMaxDynamicSharedMemorySize, SMEM_RNN);

    const int RNN_BLOCKS = (BSZ + NB - 1) / NB;  // 143

    // Folds first (independent; also keeps big kernels in the ncu capture slot)
    fold_kernel<<<G4, 128>>>(pd_Wih, pd_Whh, pd_fcW, pd_fcb, pd_bih, pd_bhh, pWeff0, pBeff0);
    fold_kernel<<<G4, 128>>>(rd_Wih, rd_Whh, rd_fcW, rd_fcb, rd_bih, rd_bhh, pWeff1, pBeff1);
    zero_loss_kernel<<<1, 1>>>(pLoss);

    // Phase A: X = src @ enc_Wih^T + (enc_bih + enc_bhh)   [100000 x 400]
    {
        dim3 grid((G4 + 63) / 64, (BSZ * TSZ + 255) / 256);
        gemm_nt<<<grid, 256>>>(src, enc_Wih, enc_bih, enc_bhh, pX,
                               BSZ * TSZ, G4, ISZ, nullptr, nullptr, 0);
    }

    // Encoder recurrence
    rnn_enc<<<RNN_BLOCKS, NT_RNN, SMEM_RNN>>>(pX, enc_Whh, pHenc, pCenc);

    // ---- predict decoder ----
    {
        dim3 grid((G4 + 63) / 64, (BSZ + 255) / 256);
        gemm_nt<<<grid, 256>>>(pHenc, pd_Whh, pd_bih, pd_bhh, pG0,
                               BSZ, G4, HSZ, nullptr, nullptr, 0);
    }
    rnn_dec<<<RNN_BLOCKS, NT_RNN, SMEM_RNN>>>(pG0, pWeff0, pBeff0, pHenc, pCenc, pHdec);
    {
        dim3 grid((ISZ + 63) / 64, (BSZ * TSZ + 255) / 256);
        gemm_nt<<<grid, 256>>>(pHdec, pd_fcW, pd_fcb, nullptr, nullptr,
                               BSZ * TSZ, ISZ, HSZ, trg, pLoss + 1, 0);
    }

    // ---- reconstruct decoder ----
    {
        dim3 grid((G4 + 63) / 64, (BSZ + 255) / 256);
        gemm_nt<<<grid, 256>>>(pHenc, rd_Whh, rd_bih, rd_bhh, pG0,
                               BSZ, G4, HSZ, nullptr, nullptr, 0);
    }
    rnn_dec<<<RNN_BLOCKS, NT_RNN, SMEM_RNN>>>(pG0, pWeff1, pBeff1, pHenc, pCenc, pHdec);
    {
        dim3 grid((ISZ + 63) / 64, (BSZ * TSZ + 255) / 256);
        gemm_nt<<<grid, 256>>>(pHdec, rd_fcW, rd_fcb, nullptr, nullptr,
                               BSZ * TSZ, ISZ, HSZ, src, pLoss + 0, TSZ);
    }

    finalize_kernel<<<1, 1>>>(pLoss, out, 1.0f / (float)(BSZ * TSZ * ISZ));
}

// round 6
// speedup vs baseline: 1.9677x; 1.2272x over previous
#include <cuda_runtime.h>
#include <cuda_bf16.h>
#include <math.h>

#define BSZ 1000
#define TSZ 100
#define ISZ 264
#define HSZ 100
#define G4  400   // 4*H
#define KPA 272   // padded K for phase A (264 -> 17*16)
#define KPL 112   // padded K for loss GEMMs (100 -> 7*16)

// ---------------- device scratch (static: no allocation allowed) ----------
__device__ float g_X[(size_t)BSZ * TSZ * G4];       // encoder gate inputs fp32
__device__ float g_henc[BSZ * HSZ];
__device__ float g_cenc[BSZ * HSZ];
__device__ float g_G0[2][BSZ * G4];                 // decoder step-0 gates
__device__ float g_Weff[2][G4 * HSZ];
__device__ float g_beff[2][G4];
__device__ float g_loss[2];

// bf16 split operands
__device__ __nv_bfloat16 g_srch[(size_t)BSZ * TSZ * KPA];
__device__ __nv_bfloat16 g_srcl[(size_t)BSZ * TSZ * KPA];
__device__ __nv_bfloat16 g_wihh[G4 * KPA];
__device__ __nv_bfloat16 g_wihl[G4 * KPA];
__device__ __nv_bfloat16 g_fcwh[2][ISZ * KPL];
__device__ __nv_bfloat16 g_fcwl[2][ISZ * KPL];
__device__ __nv_bfloat16 g_hdh[2][(size_t)BSZ * TSZ * KPL];  // decoder h, split
__device__ __nv_bfloat16 g_hdl[2][(size_t)BSZ * TSZ * KPL];

__device__ __forceinline__ float sigf(float x) { return 1.f / (1.f + expf(-x)); }

// ---------------- small kernels -------------------------------------------
__global__ void zero_loss_kernel(float* loss) { loss[0] = 0.f; loss[1] = 0.f; }

__global__ void finalize_kernel(const float* loss, float* out, float inv) {
    out[0] = loss[0] * inv;
    out[1] = loss[1] * inv;
}

// fp32 -> (bf16 hi, bf16 lo), with K padded to Kp (pad = 0)
__global__ __launch_bounds__(256) void cvt_split(
    const float* __restrict__ x, __nv_bfloat16* __restrict__ h,
    __nv_bfloat16* __restrict__ l, int rows, int K, int Kp)
{
    int idx = blockIdx.x * 256 + threadIdx.x;
    if (idx >= rows * Kp) return;
    int r = idx / Kp, k = idx - r * Kp;
    float v = (k < K) ? x[(size_t)r * K + k] : 0.f;
    __nv_bfloat16 hi = __float2bfloat16(v);
    h[idx] = hi;
    l[idx] = __float2bfloat16(v - __bfloat162float(hi));
}

// Weff[j][k] = Whh[j][k] + sum_i Wih[j][i]*fcW[i][k]
// beff[j]    = bih[j] + bhh[j] + sum_i Wih[j][i]*fcb[i]
__global__ __launch_bounds__(128) void fold_kernel(
    const float* __restrict__ Wih, const float* __restrict__ Whh,
    const float* __restrict__ fcW, const float* __restrict__ fcb,
    const float* __restrict__ bih, const float* __restrict__ bhh,
    float* __restrict__ Weff, float* __restrict__ beff)
{
    int j = blockIdx.x;
    int tid = threadIdx.x;
    __shared__ float swih[ISZ];
    __shared__ float red[128];
    for (int i = tid; i < ISZ; i += 128) swih[i] = Wih[j * ISZ + i];
    __syncthreads();
    if (tid < HSZ) {
        float acc = Whh[j * HSZ + tid];
        #pragma unroll 4
        for (int i = 0; i < ISZ; ++i)
            acc = fmaf(swih[i], fcW[i * HSZ + tid], acc);
        Weff[j * HSZ + tid] = acc;
    }
    float p = 0.f;
    for (int i = tid; i < ISZ; i += 128) p = fmaf(swih[i], fcb[i], p);
    red[tid] = p;
    __syncthreads();
    for (int s = 64; s > 0; s >>= 1) {
        if (tid < s) red[tid] += red[tid + s];
        __syncthreads();
    }
    if (tid == 0) beff[j] = bih[j] + bhh[j] + red[0];
}

// ---------------- SIMT NT GEMM (kept for small G0 GEMMs) -------------------
#define AP 264
#define BP 68
__global__ __launch_bounds__(256) void gemm_nt(
    const float* __restrict__ A, const float* __restrict__ B,
    const float* __restrict__ bias1, const float* __restrict__ bias2,
    float* __restrict__ C, int M, int N, int K)
{
    __shared__ float As[8 * AP];
    __shared__ float Bs[8 * BP];
    const int tid = threadIdx.x;
    const int tx = tid & 7;
    const int ty = tid >> 3;
    const int m0 = blockIdx.y * 256, n0 = blockIdx.x * 64;

    float acc[8][8];
    #pragma unroll
    for (int i = 0; i < 8; ++i)
        #pragma unroll
        for (int j = 0; j < 8; ++j) acc[i][j] = 0.f;

    const int am = m0 + tid;
    const int br = tid >> 2;
    const int bc = (tid & 3) * 2;

    for (int k0 = 0; k0 < K; k0 += 8) {
        #pragma unroll
        for (int j = 0; j < 8; ++j) {
            int k = k0 + j;
            As[j * AP + tid] = (am < M && k < K) ? A[(size_t)am * K + k] : 0.f;
        }
        {
            int n = n0 + br;
            #pragma unroll
            for (int j = 0; j < 2; ++j) {
                int k = k0 + bc + j;
                Bs[(bc + j) * BP + br] = (n < N && k < K) ? B[(size_t)n * K + k] : 0.f;
            }
        }
        __syncthreads();
        #pragma unroll
        for (int kk = 0; kk < 8; ++kk) {
            float4 a0 = *(const float4*)(As + kk * AP + ty * 8);
            float4 a1 = *(const float4*)(As + kk * AP + ty * 8 + 4);
            float4 b0 = *(const float4*)(Bs + kk * BP + tx * 8);
            float4 b1 = *(const float4*)(Bs + kk * BP + tx * 8 + 4);
            float av[8] = {a0.x, a0.y, a0.z, a0.w, a1.x, a1.y, a1.z, a1.w};
            float bv[8] = {b0.x, b0.y, b0.z, b0.w, b1.x, b1.y, b1.z, b1.w};
            #pragma unroll
            for (int i = 0; i < 8; ++i)
                #pragma unroll
                for (int j = 0; j < 8; ++j)
                    acc[i][j] = fmaf(av[i], bv[j], acc[i][j]);
        }
        __syncthreads();
    }

    #pragma unroll
    for (int i = 0; i < 8; ++i) {
        int m = m0 + ty * 8 + i;
        if (m < M) {
            #pragma unroll
            for (int j = 0; j < 8; ++j) {
                int n = n0 + tx * 8 + j;
                if (n < N) {
                    float v = acc[i][j];
                    if (bias1) v += bias1[n];
                    if (bias2) v += bias2[n];
                    C[(size_t)m * N + n] = v;
                }
            }
        }
    }
}

// ---------------- tensor-core split-bf16 NT GEMM ---------------------------
// C = (Ah+Al) * (Bh+Bl)^T + bias, fp32 accumulate, dropping Al*Bl.
// A: [M,lda] bf16 pair, B: [N,ldb] bf16 pair, K = Kp (multiple of 16, pre-padded).
// If lossOut: accumulate sum((C - ref)^2); revT>0 -> time-reversed ref rows.
#define SAP 24   // smem pitch in bf16 (48B -> conflict-free frag loads)

__device__ __forceinline__ void mma16816(float* d, const unsigned* a, const unsigned* b) {
    asm volatile(
        "mma.sync.aligned.m16n8k16.row.col.f32.bf16.bf16.f32 "
        "{%0,%1,%2,%3},{%4,%5,%6,%7},{%8,%9},{%0,%1,%2,%3};"
        : "+f"(d[0]), "+f"(d[1]), "+f"(d[2]), "+f"(d[3])
        : "r"(a[0]), "r"(a[1]), "r"(a[2]), "r"(a[3]), "r"(b[0]), "r"(b[1]));
}

__global__ __launch_bounds__(256) void gemm_bf16_nt(
    const __nv_bfloat16* __restrict__ Ah, const __nv_bfloat16* __restrict__ Al, int lda,
    const __nv_bfloat16* __restrict__ Bh, const __nv_bfloat16* __restrict__ Bl, int ldb,
    const float* __restrict__ bias1, const float* __restrict__ bias2,
    float* __restrict__ C, int M, int N, int Kp,
    const float* __restrict__ ref, float* __restrict__ lossOut, int revT)
{
    __shared__ __nv_bfloat16 Ash[128 * SAP];
    __shared__ __nv_bfloat16 Asl[128 * SAP];
    __shared__ __nv_bfloat16 Bsh[64 * SAP];
    __shared__ __nv_bfloat16 Bsl[64 * SAP];
    __shared__ float red[256];

    const int tid = threadIdx.x;
    const int lane = tid & 31;
    const int wid = tid >> 5;          // 0..7
    const int wy = wid & 3;            // m-warp 0..3 (32 rows each)
    const int wx = wid >> 2;           // n-warp 0..1 (32 cols each)
    const int m0 = blockIdx.y * 128, n0 = blockIdx.x * 64;
    const int g = lane >> 2, t = lane & 3;

    float d[2][4][4];
    #pragma unroll
    for (int mi = 0; mi < 2; ++mi)
        #pragma unroll
        for (int ni = 0; ni < 4; ++ni)
            #pragma unroll
            for (int e = 0; e < 4; ++e) d[mi][ni][e] = 0.f;

    const int ar = tid >> 1;           // A row slot 0..127
    const int ah8 = (tid & 1) * 8;     // k-half
    const int bs = tid & 127;          // B slot
    const int brow = bs >> 1;
    const int bh8 = (bs & 1) * 8;

    for (int k0 = 0; k0 < Kp; k0 += 16) {
        // ---- A tiles (hi & lo): 128 x 16 each
        {
            int gm = m0 + ar;
            uint4 zv = make_uint4(0, 0, 0, 0);
            uint4 vh = zv, vl = zv;
            if (gm < M) {
                vh = *(const uint4*)(Ah + (size_t)gm * lda + k0 + ah8);
                vl = *(const uint4*)(Al + (size_t)gm * lda + k0 + ah8);
            }
            *(uint4*)&Ash[ar * SAP + ah8] = vh;
            *(uint4*)&Asl[ar * SAP + ah8] = vl;
        }
        // ---- B tiles: first 128 threads -> Bh, rest -> Bl
        {
            int gn = n0 + brow;
            uint4 v = make_uint4(0, 0, 0, 0);
            const __nv_bfloat16* src = (tid < 128) ? Bh : Bl;
            if (gn < N)
                v = *(const uint4*)(src + (size_t)gn * ldb + k0 + bh8);
            __nv_bfloat16* dst = (tid < 128) ? Bsh : Bsl;
            *(uint4*)&dst[brow * SAP + bh8] = v;
        }
        __syncthreads();

        // B fragments for this warp's 32-col strip
        unsigned bh[4][2], bl[4][2];
        #pragma unroll
        for (int ni = 0; ni < 4; ++ni) {
            int base = (wx * 32 + ni * 8 + g) * SAP;
            bh[ni][0] = *(const unsigned*)&Bsh[base + 2 * t];
            bh[ni][1] = *(const unsigned*)&Bsh[base + 2 * t + 8];
            bl[ni][0] = *(const unsigned*)&Bsl[base + 2 * t];
            bl[ni][1] = *(const unsigned*)&Bsl[base + 2 * t + 8];
        }
        #pragma unroll
        for (int mi = 0; mi < 2; ++mi) {
            int r0 = (wy * 32 + mi * 16 + g) * SAP;
            int r1 = (wy * 32 + mi * 16 + 8 + g) * SAP;
            unsigned ahf[4], alf[4];
            ahf[0] = *(const unsigned*)&Ash[r0 + 2 * t];
            ahf[1] = *(const unsigned*)&Ash[r1 + 2 * t];
            ahf[2] = *(const unsigned*)&Ash[r0 + 2 * t + 8];
            ahf[3] = *(const unsigned*)&Ash[r1 + 2 * t + 8];
            alf[0] = *(const unsigned*)&Asl[r0 + 2 * t];
            alf[1] = *(const unsigned*)&Asl[r1 + 2 * t];
            alf[2] = *(const unsigned*)&Asl[r0 + 2 * t + 8];
            alf[3] = *(const unsigned*)&Asl[r1 + 2 * t + 8];
            #pragma unroll
            for (int ni = 0; ni < 4; ++ni) {
                mma16816(d[mi][ni], ahf, bh[ni]);
                mma16816(d[mi][ni], ahf, bl[ni]);
                mma16816(d[mi][ni], alf, bh[ni]);
            }
        }
        __syncthreads();
    }

    // ---- epilogue ----
    if (!lossOut) {
        #pragma unroll
        for (int mi = 0; mi < 2; ++mi) {
            #pragma unroll
            for (int rr = 0; rr < 2; ++rr) {
                int m = m0 + wy * 32 + mi * 16 + rr * 8 + g;
                if (m >= M) continue;
                #pragma unroll
                for (int ni = 0; ni < 4; ++ni) {
                    int n = n0 + wx * 32 + ni * 8 + 2 * t;
                    if (n + 1 < N) {
                        float v0 = d[mi][ni][rr * 2 + 0];
                        float v1 = d[mi][ni][rr * 2 + 1];
                        if (bias1) { v0 += bias1[n]; v1 += bias1[n + 1]; }
                        if (bias2) { v0 += bias2[n]; v1 += bias2[n + 1]; }
                        *(float2*)(C + (size_t)m * N + n) = make_float2(v0, v1);
                    } else if (n < N) {
                        float v0 = d[mi][ni][rr * 2 + 0];
                        if (bias1) v0 += bias1[n];
                        if (bias2) v0 += bias2[n];
                        C[(size_t)m * N + n] = v0;
                    }
                }
            }
        }
    } else {
        float ls = 0.f;
        #pragma unroll
        for (int mi = 0; mi < 2; ++mi) {
            #pragma unroll
            for (int rr = 0; rr < 2; ++rr) {
                int m = m0 + wy * 32 + mi * 16 + rr * 8 + g;
                if (m >= M) continue;
                const float* rrow;
                if (revT > 0) {
                    int b = m / revT, tt = m - b * revT;
                    rrow = ref + ((size_t)b * revT + (revT - 1 - tt)) * N;
                } else {
                    rrow = ref + (size_t)m * N;
                }
                #pragma unroll
                for (int ni = 0; ni < 4; ++ni) {
                    int n = n0 + wx * 32 + ni * 8 + 2 * t;
                    #pragma unroll
                    for (int e = 0; e < 2; ++e) {
                        if (n + e < N) {
                            float v = d[mi][ni][rr * 2 + e];
                            if (bias1) v += bias1[n + e];
                            float diff = v - rrow[n + e];
                            ls = fmaf(diff, diff, ls);
                        }
                    }
                }
            }
        }
        red[tid] = ls;
        __syncthreads();
        for (int s = 128; s > 0; s >>= 1) {
            if (tid < s) red[tid] += red[tid + s];
            __syncthreads();
        }
        if (tid == 0) atomicAdd(lossOut, red[0]);
    }
}

// ---------------- LSTM recurrence kernels ----------------------------------
#define NB 7
#define NT_RNN 416
#define RNN_SMEM_F (40000 + 800 + 800 + 3600)

__global__ __launch_bounds__(NT_RNN, 1) void rnn_enc(
    const float* __restrict__ X, const float* __restrict__ Whh,
    float* __restrict__ hf, float* __restrict__ cf)
{
    extern __shared__ float s[];
    float* sW  = s;
    float* sHa = s + 40000;
    float* sHb = sHa + 800;
    float* sG  = sHb + 800;
    const int tid = threadIdx.x;
    const int b0 = blockIdx.x * NB;

    for (int i = tid; i < 10000; i += NT_RNN)
        ((float4*)sW)[i] = ((const float4*)Whh)[i];
    for (int i = tid; i < 800; i += NT_RNN) sHa[i] = 0.f;
    __syncthreads();

    const int i0 = tid, i1 = tid + NT_RNN;
    const int k0c = i0 % 100, b0c = i0 / 100;
    const int k1c = i1 % 100, b1c = i1 / 100;
    const bool v0 = (i0 < NB * 100), v1 = (i1 < NB * 100);
    float c0r = 0.f, c1r = 0.f, h0r = 0.f, h1r = 0.f;

    int bidx[NB];
    #pragma unroll
    for (int b = 0; b < NB; ++b) {
        int bb = b0 + b; if (bb > BSZ - 1) bb = BSZ - 1;
        bidx[b] = bb;
    }

    for (int t = 0; t < TSZ; ++t) {
        const float* hin = (t & 1) ? sHb : sHa;
        float* hout = (t & 1) ? sHa : sHb;
        if (tid < 400) {
            const int j = tid;
            float xr[NB];
            #pragma unroll
            for (int b = 0; b < NB; ++b)
                xr[b] = X[((size_t)bidx[b] * TSZ + t) * G4 + j];
            float acc[NB];
            #pragma unroll
            for (int b = 0; b < NB; ++b) acc[b] = 0.f;
            const float4* wj = (const float4*)(sW + j * 100);
            const float* hp = hin;
            #pragma unroll 5
            for (int k4 = 0; k4 < 25; ++k4) {
                float4 w = wj[k4];
                #pragma unroll
                for (int dd = 0; dd < 4; ++dd) {
                    float wv = (dd == 0) ? w.x : (dd == 1) ? w.y : (dd == 2) ? w.z : w.w;
                    float4 ha = *(const float4*)(hp + (k4 * 4 + dd) * 8);
                    float4 hb = *(const float4*)(hp + (k4 * 4 + dd) * 8 + 4);
                    acc[0] = fmaf(wv, ha.x, acc[0]);
                    acc[1] = fmaf(wv, ha.y, acc[1]);
                    acc[2] = fmaf(wv, ha.z, acc[2]);
                    acc[3] = fmaf(wv, ha.w, acc[3]);
                    acc[4] = fmaf(wv, hb.x, acc[4]);
                    acc[5] = fmaf(wv, hb.y, acc[5]);
                    acc[6] = fmaf(wv, hb.z, acc[6]);
                }
            }
            float* gp = sG + j * 9;
            #pragma unroll
            for (int b = 0; b < NB; ++b) gp[b] = acc[b] + xr[b];
        }
        __syncthreads();
        if (v0) {
            float gi = sigf(sG[(k0c) * 9 + b0c]);
            float gf = sigf(sG[(100 + k0c) * 9 + b0c]);
            float gg = tanhf(sG[(200 + k0c) * 9 + b0c]);
            float go = sigf(sG[(300 + k0c) * 9 + b0c]);
            c0r = fmaf(gf, c0r, gi * gg);
            h0r = go * tanhf(c0r);
            hout[k0c * 8 + b0c] = h0r;
        }
        if (v1) {
            float gi = sigf(sG[(k1c) * 9 + b1c]);
            float gf = sigf(sG[(100 + k1c) * 9 + b1c]);
            float gg = tanhf(sG[(200 + k1c) * 9 + b1c]);
            float go = sigf(sG[(300 + k1c) * 9 + b1c]);
            c1r = fmaf(gf, c1r, gi * gg);
            h1r = go * tanhf(c1r);
            hout[k1c * 8 + b1c] = h1r;
        }
        __syncthreads();
    }

    if (v0 && b0 + b0c < BSZ) {
        hf[(b0 + b0c) * HSZ + k0c] = h0r;
        cf[(b0 + b0c) * HSZ + k0c] = c0r;
    }
    if (v1 && b0 + b1c < BSZ) {
        hf[(b0 + b1c) * HSZ + k1c] = h1r;
        cf[(b0 + b1c) * HSZ + k1c] = c1r;
    }
}

// merged decoders: grid (143, 2); blockIdx.y selects decoder.
// h written directly as bf16 hi/lo pairs with K padded pitch KPL.
__global__ __launch_bounds__(NT_RNN, 2) void rnn_dec2(
    const float* __restrict__ G0base, const float* __restrict__ Weffbase,
    const float* __restrict__ beffbase,
    const float* __restrict__ h0, const float* __restrict__ c0,
    __nv_bfloat16* __restrict__ hdh0, __nv_bfloat16* __restrict__ hdl0,
    __nv_bfloat16* __restrict__ hdh1, __nv_bfloat16* __restrict__ hdl1)
{
    extern __shared__ float s[];
    float* sW  = s;
    float* sHa = s + 40000;
    float* sHb = sHa + 800;
    float* sG  = sHb + 800;
    const int tid = threadIdx.x;
    const int b0 = blockIdx.x * NB;
    const int did = blockIdx.y;

    const float* G0   = G0base + (size_t)did * BSZ * G4;
    const float* Weff = Weffbase + (size_t)did * G4 * HSZ;
    const float* beff = beffbase + (size_t)did * G4;
    __nv_bfloat16* hdh = did ? hdh1 : hdh0;
    __nv_bfloat16* hdl = did ? hdl1 : hdl0;

    for (int i = tid; i < 10000; i += NT_RNN)
        ((float4*)sW)[i] = ((const float4*)Weff)[i];

    const float bq = (tid < 400) ? beff[tid] : 0.f;

    const int i0 = tid, i1 = tid + NT_RNN;
    const int k0c = i0 % 100, b0c = i0 / 100;
    const int k1c = i1 % 100, b1c = i1 / 100;
    const bool v0 = (i0 < NB * 100), v1 = (i1 < NB * 100);
    float c0r = 0.f, c1r = 0.f;

    int bidx[NB];
    #pragma unroll
    for (int b = 0; b < NB; ++b) {
        int bb = b0 + b; if (bb > BSZ - 1) bb = BSZ - 1;
        bidx[b] = bb;
    }

    if (v0) {
        sHa[k0c * 8 + b0c] = h0[bidx[b0c] * HSZ + k0c];
        c0r = c0[bidx[b0c] * HSZ + k0c];
    }
    if (v1) {
        sHa[k1c * 8 + b1c] = h0[bidx[b1c] * HSZ + k1c];
        c1r = c0[bidx[b1c] * HSZ + k1c];
    }
    __syncthreads();

    for (int t = 0; t < TSZ; ++t) {
        const float* hin = (t & 1) ? sHb : sHa;
        float* hout = (t & 1) ? sHa : sHb;
        if (tid < 400) {
            const int j = tid;
            float* gp = sG + j * 9;
            if (t == 0) {
                #pragma unroll
                for (int b = 0; b < NB; ++b)
                    gp[b] = G0[(size_t)bidx[b] * G4 + j];
            } else {
                float acc[NB];
                #pragma unroll
                for (int b = 0; b < NB; ++b) acc[b] = 0.f;
                const float4* wj = (const float4*)(sW + j * 100);
                const float* hp = hin;
                #pragma unroll 5
                for (int k4 = 0; k4 < 25; ++k4) {
                    float4 w = wj[k4];
                    #pragma unroll
                    for (int dd = 0; dd < 4; ++dd) {
                        float wv = (dd == 0) ? w.x : (dd == 1) ? w.y : (dd == 2) ? w.z : w.w;
                        float4 ha = *(const float4*)(hp + (k4 * 4 + dd) * 8);
                        float4 hb = *(const float4*)(hp + (k4 * 4 + dd) * 8 + 4);
                        acc[0] = fmaf(wv, ha.x, acc[0]);
                        acc[1] = fmaf(wv, ha.y, acc[1]);
                        acc[2] = fmaf(wv, ha.z, acc[2]);
                        acc[3] = fmaf(wv, ha.w, acc[3]);
                        acc[4] = fmaf(wv, hb.x, acc[4]);
                        acc[5] = fmaf(wv, hb.y, acc[5]);
                        acc[6] = fmaf(wv, hb.z, acc[6]);
                    }
                }
                #pragma unroll
                for (int b = 0; b < NB; ++b) gp[b] = acc[b] + bq;
            }
        }
        __syncthreads();
        if (v0) {
            float gi = sigf(sG[(k0c) * 9 + b0c]);
            float gf = sigf(sG[(100 + k0c) * 9 + b0c]);
            float gg = tanhf(sG[(200 + k0c) * 9 + b0c]);
            float go = sigf(sG[(300 + k0c) * 9 + b0c]);
            c0r = fmaf(gf, c0r, gi * gg);
            float h = go * tanhf(c0r);
            hout[k0c * 8 + b0c] = h;
            if (b0 + b0c < BSZ) {
                size_t off = ((size_t)(b0 + b0c) * TSZ + t) * KPL + k0c;
                __nv_bfloat16 hi = __float2bfloat16(h);
                hdh[off] = hi;
                hdl[off] = __float2bfloat16(h - __bfloat162float(hi));
            }
        }
        if (v1) {
            float gi = sigf(sG[(k1c) * 9 + b1c]);
            float gf = sigf(sG[(100 + k1c) * 9 + b1c]);
            float gg = tanhf(sG[(200 + k1c) * 9 + b1c]);
            float go = sigf(sG[(300 + k1c) * 9 + b1c]);
            c1r = fmaf(gf, c1r, gi * gg);
            float h = go * tanhf(c1r);
            hout[k1c * 8 + b1c] = h;
            if (b0 + b1c < BSZ) {
                size_t off = ((size_t)(b0 + b1c) * TSZ + t) * KPL + k1c;
                __nv_bfloat16 hi = __float2bfloat16(h);
                hdh[off] = hi;
                hdl[off] = __float2bfloat16(h - __bfloat162float(hi));
            }
        }
        __syncthreads();
    }
}

// ---------------- launch ----------------------------------------------------
extern "C" void kernel_launch(void* const* d_in, const int* in_sizes, int n_in,
                              void* d_out, int out_size)
{
    const float* src     = (const float*)d_in[0];
    const float* trg     = (const float*)d_in[1];
    const float* enc_Wih = (const float*)d_in[2];
    const float* enc_Whh = (const float*)d_in[3];
    const float* enc_bih = (const float*)d_in[4];
    const float* enc_bhh = (const float*)d_in[5];
    const float* pd_Wih  = (const float*)d_in[6];
    const float* pd_Whh  = (const float*)d_in[7];
    const float* pd_bih  = (const float*)d_in[8];
    const float* pd_bhh  = (const float*)d_in[9];
    const float* pd_fcW  = (const float*)d_in[10];
    const float* pd_fcb  = (const float*)d_in[11];
    const float* rd_Wih  = (const float*)d_in[12];
    const float* rd_Whh  = (const float*)d_in[13];
    const float* rd_bih  = (const float*)d_in[14];
    const float* rd_bhh  = (const float*)d_in[15];
    const float* rd_fcW  = (const float*)d_in[16];
    const float* rd_fcb  = (const float*)d_in[17];
    float* out = (float*)d_out;

    float *pX, *pHenc, *pCenc, *pG0, *pWeff, *pBeff, *pLoss;
    __nv_bfloat16 *pSrch, *pSrcl, *pWihh, *pWihl, *pFcwh, *pFcwl, *pHdh, *pHdl;
    cudaGetSymbolAddress((void**)&pX,    g_X);
    cudaGetSymbolAddress((void**)&pHenc, g_henc);
    cudaGetSymbolAddress((void**)&pCenc, g_cenc);
    cudaGetSymbolAddress((void**)&pG0,   g_G0);
    cudaGetSymbolAddress((void**)&pWeff, g_Weff);
    cudaGetSymbolAddress((void**)&pBeff, g_beff);
    cudaGetSymbolAddress((void**)&pLoss, g_loss);
    cudaGetSymbolAddress((void**)&pSrch, g_srch);
    cudaGetSymbolAddress((void**)&pSrcl, g_srcl);
    cudaGetSymbolAddress((void**)&pWihh, g_wihh);
    cudaGetSymbolAddress((void**)&pWihl, g_wihl);
    cudaGetSymbolAddress((void**)&pFcwh, g_fcwh);
    cudaGetSymbolAddress((void**)&pFcwl, g_fcwl);
    cudaGetSymbolAddress((void**)&pHdh,  g_hdh);
    cudaGetSymbolAddress((void**)&pHdl,  g_hdl);

    const int SMEM_RNN = RNN_SMEM_F * 4;
    cudaFuncSetAttribute(rnn_enc,  cudaFuncAttributeMaxDynamicSharedMemorySize, SMEM_RNN);
    cudaFuncSetAttribute(rnn_dec2, cudaFuncAttributeMaxDynamicSharedMemorySize, SMEM_RNN);

    const int RNN_BLOCKS = (BSZ + NB - 1) / NB;  // 143
    const int MROWS = BSZ * TSZ;                 // 100000

    // ---- independent prep ----
    fold_kernel<<<G4, 128>>>(pd_Wih, pd_Whh, pd_fcW, pd_fcb, pd_bih, pd_bhh,
                             pWeff, pBeff);
    fold_kernel<<<G4, 128>>>(rd_Wih, rd_Whh, rd_fcW, rd_fcb, rd_bih, rd_bhh,
                             pWeff + G4 * HSZ, pBeff + G4);
    zero_loss_kernel<<<1, 1>>>(pLoss);
    {
        int n = MROWS * KPA;
        cvt_split<<<(n + 255) / 256, 256>>>(src, pSrch, pSrcl, MROWS, ISZ, KPA);
    }
    {
        int n = G4 * KPA;
        cvt_split<<<(n + 255) / 256, 256>>>(enc_Wih, pWihh, pWihl, G4, ISZ, KPA);
    }
    {
        int n = ISZ * KPL;
        cvt_split<<<(n + 255) / 256, 256>>>(pd_fcW, pFcwh, pFcwl, ISZ, HSZ, KPL);
        cvt_split<<<(n + 255) / 256, 256>>>(rd_fcW, pFcwh + ISZ * KPL,
                                            pFcwl + ISZ * KPL, ISZ, HSZ, KPL);
    }

    // ---- phase A: X = src @ enc_Wih^T + biases (tensor cores) ----
    {
        dim3 grid((G4 + 63) / 64, (MROWS + 127) / 128);
        gemm_bf16_nt<<<grid, 256>>>(pSrch, pSrcl, KPA, pWihh, pWihl, KPA,
                                    enc_bih, enc_bhh, pX, MROWS, G4, KPA,
                                    nullptr, nullptr, 0);
    }

    // ---- encoder recurrence ----
    rnn_enc<<<RNN_BLOCKS, NT_RNN, SMEM_RNN>>>(pX, enc_Whh, pHenc, pCenc);

    // ---- decoder step-0 gates (small SIMT GEMMs) ----
    {
        dim3 grid((G4 + 63) / 64, (BSZ + 255) / 256);
        gemm_nt<<<grid, 256>>>(pHenc, pd_Whh, pd_bih, pd_bhh, pG0,
                               BSZ, G4, HSZ);
        gemm_nt<<<grid, 256>>>(pHenc, rd_Whh, rd_bih, rd_bhh, pG0 + BSZ * G4,
                               BSZ, G4, HSZ);
    }

    // ---- merged decoders (both run concurrently, 2 CTAs/SM) ----
    {
        dim3 grid(RNN_BLOCKS, 2);
        size_t hdsz = (size_t)MROWS * KPL;
        rnn_dec2<<<grid, NT_RNN, SMEM_RNN>>>(pG0, pWeff, pBeff, pHenc, pCenc,
                                             pHdh, pHdl, pHdh + hdsz, pHdl + hdsz);
    }

    // ---- losses (tensor cores, fused MSE epilogue) ----
    {
        size_t hdsz = (size_t)MROWS * KPL;
        dim3 grid((ISZ + 63) / 64, (MROWS + 127) / 128);
        gemm_bf16_nt<<<grid, 256>>>(pHdh, pHdl, KPL, pFcwh, pFcwl, KPL,
                                    pd_fcb, nullptr, nullptr, MROWS, ISZ, KPL,
                                    trg, pLoss + 1, 0);
        gemm_bf16_nt<<<grid, 256>>>(pHdh + hdsz, pHdl + hdsz, KPL,
                                    pFcwh + ISZ * KPL, pFcwl + ISZ * KPL, KPL,
                                    rd_fcb, nullptr, nullptr, MROWS, ISZ, KPL,
                                    src, pLoss + 0, TSZ);
    }

    finalize_kernel<<<1, 1>>>(pLoss, out, 1.0f / (float)(BSZ * TSZ * ISZ));
}

// round 7
// speedup vs baseline: 2.0592x; 1.0465x over previous
#include <cuda_runtime.h>
#include <cuda_bf16.h>
#include <math.h>

#define BSZ 1000
#define TSZ 100
#define ISZ 264
#define HSZ 100
#define G4  400   // 4*H
#define KPA 272   // padded K for phase A (264 -> 17*16)
#define KPL 112   // padded K for loss GEMMs (100 -> 7*16)

// ---------------- device scratch (static: no allocation allowed) ----------
__device__ float g_X[(size_t)BSZ * TSZ * G4];       // encoder gate inputs fp32
__device__ float g_henc[BSZ * HSZ];
__device__ float g_cenc[BSZ * HSZ];
__device__ float g_G0[2][BSZ * G4];                 // decoder step-0 gates
__device__ float g_Weff[2][G4 * HSZ];
__device__ float g_beff[2][G4];
__device__ float g_loss[2];

// bf16 split operands
__device__ __nv_bfloat16 g_srch[(size_t)BSZ * TSZ * KPA];
__device__ __nv_bfloat16 g_srcl[(size_t)BSZ * TSZ * KPA];
__device__ __nv_bfloat16 g_wihh[G4 * KPA];
__device__ __nv_bfloat16 g_wihl[G4 * KPA];
__device__ __nv_bfloat16 g_fcwh[2][ISZ * KPL];
__device__ __nv_bfloat16 g_fcwl[2][ISZ * KPL];
__device__ __nv_bfloat16 g_hdh[2][(size_t)BSZ * TSZ * KPL];  // decoder h, split
__device__ __nv_bfloat16 g_hdl[2][(size_t)BSZ * TSZ * KPL];

__device__ __forceinline__ float sigf(float x) { return 1.f / (1.f + expf(-x)); }

// ---------------- small kernels -------------------------------------------
__global__ void finalize_kernel(const float* loss, float* out, float inv) {
    out[0] = loss[0] * inv;
    out[1] = loss[1] * inv;
}

// fp32 -> (bf16 hi, bf16 lo), K padded to Kp, templated (fast const division),
// float4 vectorized (4 elements / thread).
template <int K, int Kp>
__global__ __launch_bounds__(256) void cvt_split_t(
    const float* __restrict__ x, __nv_bfloat16* __restrict__ h,
    __nv_bfloat16* __restrict__ l, int rows)
{
    const int Kp4 = Kp / 4;
    int idx = blockIdx.x * 256 + threadIdx.x;      // float4 slot index
    if (idx >= rows * Kp4) return;
    int r = idx / Kp4;
    int k4 = (idx - r * Kp4) * 4;
    float4 v;
    if (k4 + 3 < K) {
        v = *(const float4*)(x + (size_t)r * K + k4);
    } else {
        float tmp[4] = {0.f, 0.f, 0.f, 0.f};
        #pragma unroll
        for (int e = 0; e < 4; ++e)
            if (k4 + e < K) tmp[e] = x[(size_t)r * K + k4 + e];
        v = make_float4(tmp[0], tmp[1], tmp[2], tmp[3]);
    }
    float vv[4] = {v.x, v.y, v.z, v.w};
    __nv_bfloat16 hh[4], ll[4];
    #pragma unroll
    for (int e = 0; e < 4; ++e) {
        hh[e] = __float2bfloat16(vv[e]);
        ll[e] = __float2bfloat16(vv[e] - __bfloat162float(hh[e]));
    }
    *(uint2*)(h + (size_t)idx * 4) = *(const uint2*)hh;
    *(uint2*)(l + (size_t)idx * 4) = *(const uint2*)ll;
}

// Both decoder folds in one launch: blockIdx.y selects decoder.
// Weff[j][k] = Whh[j][k] + sum_i Wih[j][i]*fcW[i][k]
// beff[j]    = bih[j] + bhh[j] + sum_i Wih[j][i]*fcb[i]
__global__ __launch_bounds__(128) void fold2_kernel(
    const float* __restrict__ pd_Wih, const float* __restrict__ pd_Whh,
    const float* __restrict__ pd_fcW, const float* __restrict__ pd_fcb,
    const float* __restrict__ pd_bih, const float* __restrict__ pd_bhh,
    const float* __restrict__ rd_Wih, const float* __restrict__ rd_Whh,
    const float* __restrict__ rd_fcW, const float* __restrict__ rd_fcb,
    const float* __restrict__ rd_bih, const float* __restrict__ rd_bhh,
    float* __restrict__ Weff, float* __restrict__ beff, float* __restrict__ loss)
{
    const int did = blockIdx.y;
    const float* Wih = did ? rd_Wih : pd_Wih;
    const float* Whh = did ? rd_Whh : pd_Whh;
    const float* fcW = did ? rd_fcW : pd_fcW;
    const float* fcb = did ? rd_fcb : pd_fcb;
    const float* bih = did ? rd_bih : pd_bih;
    const float* bhh = did ? rd_bhh : pd_bhh;
    float* We = Weff + (size_t)did * G4 * HSZ;
    float* be = beff + (size_t)did * G4;

    int j = blockIdx.x;
    int tid = threadIdx.x;
    if (blockIdx.x == 0 && did == 0 && tid < 2) loss[tid] = 0.f;

    __shared__ float swih[ISZ];
    __shared__ float red[128];
    for (int i = tid; i < ISZ; i += 128) swih[i] = Wih[j * ISZ + i];
    __syncthreads();
    if (tid < HSZ) {
        float acc = Whh[j * HSZ + tid];
        #pragma unroll 4
        for (int i = 0; i < ISZ; ++i)
            acc = fmaf(swih[i], fcW[i * HSZ + tid], acc);
        We[j * HSZ + tid] = acc;
    }
    float p = 0.f;
    for (int i = tid; i < ISZ; i += 128) p = fmaf(swih[i], fcb[i], p);
    red[tid] = p;
    __syncthreads();
    for (int s = 64; s > 0; s >>= 1) {
        if (tid < s) red[tid] += red[tid + s];
        __syncthreads();
    }
    if (tid == 0) be[j] = bih[j] + bhh[j] + red[0];
}

// ---------------- SIMT NT GEMM for the two small G0 GEMMs ------------------
// blockIdx.z selects decoder (B/bias/output set).
#define AP 264
#define BP 68
__global__ __launch_bounds__(256) void gemm_g0(
    const float* __restrict__ A,
    const float* __restrict__ B0, const float* __restrict__ B1,
    const float* __restrict__ b10, const float* __restrict__ b11,
    const float* __restrict__ b20, const float* __restrict__ b21,
    float* __restrict__ Cbase, int M, int N, int K)
{
    const int did = blockIdx.z;
    const float* B = did ? B1 : B0;
    const float* bias1 = did ? b11 : b10;
    const float* bias2 = did ? b21 : b20;
    float* C = Cbase + (size_t)did * M * N;

    __shared__ float As[8 * AP];
    __shared__ float Bs[8 * BP];
    const int tid = threadIdx.x;
    const int tx = tid & 7;
    const int ty = tid >> 3;
    const int m0 = blockIdx.y * 256, n0 = blockIdx.x * 64;

    float acc[8][8];
    #pragma unroll
    for (int i = 0; i < 8; ++i)
        #pragma unroll
        for (int j = 0; j < 8; ++j) acc[i][j] = 0.f;

    const int am = m0 + tid;
    const int br = tid >> 2;
    const int bc = (tid & 3) * 2;

    for (int k0 = 0; k0 < K; k0 += 8) {
        #pragma unroll
        for (int j = 0; j < 8; ++j) {
            int k = k0 + j;
            As[j * AP + tid] = (am < M && k < K) ? A[(size_t)am * K + k] : 0.f;
        }
        {
            int n = n0 + br;
            #pragma unroll
            for (int j = 0; j < 2; ++j) {
                int k = k0 + bc + j;
                Bs[(bc + j) * BP + br] = (n < N && k < K) ? B[(size_t)n * K + k] : 0.f;
            }
        }
        __syncthreads();
        #pragma unroll
        for (int kk = 0; kk < 8; ++kk) {
            float4 a0 = *(const float4*)(As + kk * AP + ty * 8);
            float4 a1 = *(const float4*)(As + kk * AP + ty * 8 + 4);
            float4 b0 = *(const float4*)(Bs + kk * BP + tx * 8);
            float4 b1 = *(const float4*)(Bs + kk * BP + tx * 8 + 4);
            float av[8] = {a0.x, a0.y, a0.z, a0.w, a1.x, a1.y, a1.z, a1.w};
            float bv[8] = {b0.x, b0.y, b0.z, b0.w, b1.x, b1.y, b1.z, b1.w};
            #pragma unroll
            for (int i = 0; i < 8; ++i)
                #pragma unroll
                for (int j = 0; j < 8; ++j)
                    acc[i][j] = fmaf(av[i], bv[j], acc[i][j]);
        }
        __syncthreads();
    }

    #pragma unroll
    for (int i = 0; i < 8; ++i) {
        int m = m0 + ty * 8 + i;
        if (m < M) {
            #pragma unroll
            for (int j = 0; j < 8; ++j) {
                int n = n0 + tx * 8 + j;
                if (n < N) {
                    float v = acc[i][j] + bias1[n] + bias2[n];
                    C[(size_t)m * N + n] = v;
                }
            }
        }
    }
}

// ---------------- tensor-core split-bf16 NT GEMM (pipelined) ---------------
// C = (Ah+Al)*(Bh+Bl)^T + bias, fp32 accumulate, dropping Al*Bl.
// Global->register prefetch of next k-tile overlaps MMA on current tile.
#define SAP 24

__device__ __forceinline__ void mma16816(float* d, const unsigned* a, const unsigned* b) {
    asm volatile(
        "mma.sync.aligned.m16n8k16.row.col.f32.bf16.bf16.f32 "
        "{%0,%1,%2,%3},{%4,%5,%6,%7},{%8,%9},{%0,%1,%2,%3};"
        : "+f"(d[0]), "+f"(d[1]), "+f"(d[2]), "+f"(d[3])
        : "r"(a[0]), "r"(a[1]), "r"(a[2]), "r"(a[3]), "r"(b[0]), "r"(b[1]));
}

__global__ __launch_bounds__(256) void gemm_bf16_nt(
    const __nv_bfloat16* __restrict__ Ah, const __nv_bfloat16* __restrict__ Al, int lda,
    const __nv_bfloat16* __restrict__ Bh, const __nv_bfloat16* __restrict__ Bl, int ldb,
    const float* __restrict__ bias1, const float* __restrict__ bias2,
    float* __restrict__ C, int M, int N, int Kp,
    const float* __restrict__ ref, float* __restrict__ lossOut, int revT)
{
    __shared__ __nv_bfloat16 Ash[128 * SAP];
    __shared__ __nv_bfloat16 Asl[128 * SAP];
    __shared__ __nv_bfloat16 Bsh[64 * SAP];
    __shared__ __nv_bfloat16 Bsl[64 * SAP];
    __shared__ float red[256];

    const int tid = threadIdx.x;
    const int lane = tid & 31;
    const int wid = tid >> 5;
    const int wy = wid & 3;
    const int wx = wid >> 2;
    const int m0 = blockIdx.y * 128, n0 = blockIdx.x * 64;
    const int g = lane >> 2, t = lane & 3;

    float d[2][4][4];
    #pragma unroll
    for (int mi = 0; mi < 2; ++mi)
        #pragma unroll
        for (int ni = 0; ni < 4; ++ni)
            #pragma unroll
            for (int e = 0; e < 4; ++e) d[mi][ni][e] = 0.f;

    const int ar = tid >> 1;
    const int ah8 = (tid & 1) * 8;
    const int bs = tid & 127;
    const int brow = bs >> 1;
    const int bh8 = (bs & 1) * 8;
    const int gm = m0 + ar;
    const int gn = n0 + brow;
    const __nv_bfloat16* srcB = (tid < 128) ? Bh : Bl;
    __nv_bfloat16* dstB = (tid < 128) ? Bsh : Bsl;

    uint4 vh, vl, vb;
    const uint4 zv = make_uint4(0, 0, 0, 0);
    // prologue load k0 = 0
    {
        vh = zv; vl = zv; vb = zv;
        if (gm < M) {
            vh = *(const uint4*)(Ah + (size_t)gm * lda + ah8);
            vl = *(const uint4*)(Al + (size_t)gm * lda + ah8);
        }
        if (gn < N) vb = *(const uint4*)(srcB + (size_t)gn * ldb + bh8);
    }

    for (int k0 = 0; k0 < Kp; k0 += 16) {
        *(uint4*)&Ash[ar * SAP + ah8] = vh;
        *(uint4*)&Asl[ar * SAP + ah8] = vl;
        *(uint4*)&dstB[brow * SAP + bh8] = vb;
        __syncthreads();

        // prefetch next k-tile into registers (overlaps with MMAs below)
        if (k0 + 16 < Kp) {
            int kn = k0 + 16;
            vh = zv; vl = zv; vb = zv;
            if (gm < M) {
                vh = *(const uint4*)(Ah + (size_t)gm * lda + kn + ah8);
                vl = *(const uint4*)(Al + (size_t)gm * lda + kn + ah8);
            }
            if (gn < N) vb = *(const uint4*)(srcB + (size_t)gn * ldb + kn + bh8);
        }

        unsigned bh[4][2], bl[4][2];
        #pragma unroll
        for (int ni = 0; ni < 4; ++ni) {
            int base = (wx * 32 + ni * 8 + g) * SAP;
            bh[ni][0] = *(const unsigned*)&Bsh[base + 2 * t];
            bh[ni][1] = *(const unsigned*)&Bsh[base + 2 * t + 8];
            bl[ni][0] = *(const unsigned*)&Bsl[base + 2 * t];
            bl[ni][1] = *(const unsigned*)&Bsl[base + 2 * t + 8];
        }
        #pragma unroll
        for (int mi = 0; mi < 2; ++mi) {
            int r0 = (wy * 32 + mi * 16 + g) * SAP;
            int r1 = (wy * 32 + mi * 16 + 8 + g) * SAP;
            unsigned ahf[4], alf[4];
            ahf[0] = *(const unsigned*)&Ash[r0 + 2 * t];
            ahf[1] = *(const unsigned*)&Ash[r1 + 2 * t];
            ahf[2] = *(const unsigned*)&Ash[r0 + 2 * t + 8];
            ahf[3] = *(const unsigned*)&Ash[r1 + 2 * t + 8];
            alf[0] = *(const unsigned*)&Asl[r0 + 2 * t];
            alf[1] = *(const unsigned*)&Asl[r1 + 2 * t];
            alf[2] = *(const unsigned*)&Asl[r0 + 2 * t + 8];
            alf[3] = *(const unsigned*)&Asl[r1 + 2 * t + 8];
            #pragma unroll
            for (int ni = 0; ni < 4; ++ni) {
                mma16816(d[mi][ni], ahf, bh[ni]);
                mma16816(d[mi][ni], ahf, bl[ni]);
                mma16816(d[mi][ni], alf, bh[ni]);
            }
        }
        __syncthreads();
    }

    if (!lossOut) {
        #pragma unroll
        for (int mi = 0; mi < 2; ++mi) {
            #pragma unroll
            for (int rr = 0; rr < 2; ++rr) {
                int m = m0 + wy * 32 + mi * 16 + rr * 8 + g;
                if (m >= M) continue;
                #pragma unroll
                for (int ni = 0; ni < 4; ++ni) {
                    int n = n0 + wx * 32 + ni * 8 + 2 * t;
                    if (n + 1 < N) {
                        float v0 = d[mi][ni][rr * 2 + 0];
                        float v1 = d[mi][ni][rr * 2 + 1];
                        if (bias1) { v0 += bias1[n]; v1 += bias1[n + 1]; }
                        if (bias2) { v0 += bias2[n]; v1 += bias2[n + 1]; }
                        *(float2*)(C + (size_t)m * N + n) = make_float2(v0, v1);
                    } else if (n < N) {
                        float v0 = d[mi][ni][rr * 2 + 0];
                        if (bias1) v0 += bias1[n];
                        if (bias2) v0 += bias2[n];
                        C[(size_t)m * N + n] = v0;
                    }
                }
            }
        }
    } else {
        float ls = 0.f;
        #pragma unroll
        for (int mi = 0; mi < 2; ++mi) {
            #pragma unroll
            for (int rr = 0; rr < 2; ++rr) {
                int m = m0 + wy * 32 + mi * 16 + rr * 8 + g;
                if (m >= M) continue;
                const float* rrow;
                if (revT > 0) {
                    int b = m / revT, tt = m - b * revT;
                    rrow = ref + ((size_t)b * revT + (revT - 1 - tt)) * N;
                } else {
                    rrow = ref + (size_t)m * N;
                }
                #pragma unroll
                for (int ni = 0; ni < 4; ++ni) {
                    int n = n0 + wx * 32 + ni * 8 + 2 * t;
                    #pragma unroll
                    for (int e = 0; e < 2; ++e) {
                        if (n + e < N) {
                            float v = d[mi][ni][rr * 2 + e];
                            if (bias1) v += bias1[n + e];
                            float diff = v - rrow[n + e];
                            ls = fmaf(diff, diff, ls);
                        }
                    }
                }
            }
        }
        red[tid] = ls;
        __syncthreads();
        for (int s = 128; s > 0; s >>= 1) {
            if (tid < s) red[tid] += red[tid + s];
            __syncthreads();
        }
        if (tid == 0) atomicAdd(lossOut, red[0]);
    }
}

// ---------------- LSTM recurrence kernels ----------------------------------
#define NB 7
#define NT_RNN 416
#define RNN_SMEM_F (40000 + 800 + 800 + 3600)

__global__ __launch_bounds__(NT_RNN, 1) void rnn_enc(
    const float* __restrict__ X, const float* __restrict__ Whh,
    float* __restrict__ hf, float* __restrict__ cf)
{
    extern __shared__ float s[];
    float* sW  = s;
    float* sHa = s + 40000;
    float* sHb = sHa + 800;
    float* sG  = sHb + 800;
    const int tid = threadIdx.x;
    const int b0 = blockIdx.x * NB;

    for (int i = tid; i < 10000; i += NT_RNN)
        ((float4*)sW)[i] = ((const float4*)Whh)[i];
    for (int i = tid; i < 800; i += NT_RNN) sHa[i] = 0.f;
    __syncthreads();

    const int i0 = tid, i1 = tid + NT_RNN;
    const int k0c = i0 % 100, b0c = i0 / 100;
    const int k1c = i1 % 100, b1c = i1 / 100;
    const bool v0 = (i0 < NB * 100), v1 = (i1 < NB * 100);
    float c0r = 0.f, c1r = 0.f, h0r = 0.f, h1r = 0.f;

    int bidx[NB];
    #pragma unroll
    for (int b = 0; b < NB; ++b) {
        int bb = b0 + b; if (bb > BSZ - 1) bb = BSZ - 1;
        bidx[b] = bb;
    }

    for (int t = 0; t < TSZ; ++t) {
        const float* hin = (t & 1) ? sHb : sHa;
        float* hout = (t & 1) ? sHa : sHb;
        if (tid < 400) {
            const int j = tid;
            float xr[NB];
            #pragma unroll
            for (int b = 0; b < NB; ++b)
                xr[b] = X[((size_t)bidx[b] * TSZ + t) * G4 + j];
            float acc[NB];
            #pragma unroll
            for (int b = 0; b < NB; ++b) acc[b] = 0.f;
            const float4* wj = (const float4*)(sW + j * 100);
            const float* hp = hin;
            #pragma unroll 5
            for (int k4 = 0; k4 < 25; ++k4) {
                float4 w = wj[k4];
                #pragma unroll
                for (int dd = 0; dd < 4; ++dd) {
                    float wv = (dd == 0) ? w.x : (dd == 1) ? w.y : (dd == 2) ? w.z : w.w;
                    float4 ha = *(const float4*)(hp + (k4 * 4 + dd) * 8);
                    float4 hb = *(const float4*)(hp + (k4 * 4 + dd) * 8 + 4);
                    acc[0] = fmaf(wv, ha.x, acc[0]);
                    acc[1] = fmaf(wv, ha.y, acc[1]);
                    acc[2] = fmaf(wv, ha.z, acc[2]);
                    acc[3] = fmaf(wv, ha.w, acc[3]);
                    acc[4] = fmaf(wv, hb.x, acc[4]);
                    acc[5] = fmaf(wv, hb.y, acc[5]);
                    acc[6] = fmaf(wv, hb.z, acc[6]);
                }
            }
            float* gp = sG + j * 9;
            #pragma unroll
            for (int b = 0; b < NB; ++b) gp[b] = acc[b] + xr[b];
        }
        __syncthreads();
        if (v0) {
            float gi = sigf(sG[(k0c) * 9 + b0c]);
            float gf = sigf(sG[(100 + k0c) * 9 + b0c]);
            float gg = tanhf(sG[(200 + k0c) * 9 + b0c]);
            float go = sigf(sG[(300 + k0c) * 9 + b0c]);
            c0r = fmaf(gf, c0r, gi * gg);
            h0r = go * tanhf(c0r);
            hout[k0c * 8 + b0c] = h0r;
        }
        if (v1) {
            float gi = sigf(sG[(k1c) * 9 + b1c]);
            float gf = sigf(sG[(100 + k1c) * 9 + b1c]);
            float gg = tanhf(sG[(200 + k1c) * 9 + b1c]);
            float go = sigf(sG[(300 + k1c) * 9 + b1c]);
            c1r = fmaf(gf, c1r, gi * gg);
            h1r = go * tanhf(c1r);
            hout[k1c * 8 + b1c] = h1r;
        }
        __syncthreads();
    }

    if (v0 && b0 + b0c < BSZ) {
        hf[(b0 + b0c) * HSZ + k0c] = h0r;
        cf[(b0 + b0c) * HSZ + k0c] = c0r;
    }
    if (v1 && b0 + b1c < BSZ) {
        hf[(b0 + b1c) * HSZ + k1c] = h1r;
        cf[(b0 + b1c) * HSZ + k1c] = c1r;
    }
}

// merged decoders: grid (143, 2); blockIdx.y selects decoder; 2 CTAs/SM.
__global__ __launch_bounds__(NT_RNN, 2) void rnn_dec2(
    const float* __restrict__ G0base, const float* __restrict__ Weffbase,
    const float* __restrict__ beffbase,
    const float* __restrict__ h0, const float* __restrict__ c0,
    __nv_bfloat16* __restrict__ hdhb, __nv_bfloat16* __restrict__ hdlb)
{
    extern __shared__ float s[];
    float* sW  = s;
    float* sHa = s + 40000;
    float* sHb = sHa + 800;
    float* sG  = sHb + 800;
    const int tid = threadIdx.x;
    const int b0 = blockIdx.x * NB;
    const int did = blockIdx.y;

    const float* G0   = G0base + (size_t)did * BSZ * G4;
    const float* Weff = Weffbase + (size_t)did * G4 * HSZ;
    const float* beff = beffbase + (size_t)did * G4;
    const size_t hdoff = (size_t)did * BSZ * TSZ * KPL;
    __nv_bfloat16* hdh = hdhb + hdoff;
    __nv_bfloat16* hdl = hdlb + hdoff;

    for (int i = tid; i < 10000; i += NT_RNN)
        ((float4*)sW)[i] = ((const float4*)Weff)[i];

    const float bq = (tid < 400) ? beff[tid] : 0.f;

    const int i0 = tid, i1 = tid + NT_RNN;
    const int k0c = i0 % 100, b0c = i0 / 100;
    const int k1c = i1 % 100, b1c = i1 / 100;
    const bool v0 = (i0 < NB * 100), v1 = (i1 < NB * 100);
    const bool w0 = v0 && (b0 + b0c < BSZ);
    const bool w1 = v1 && (b0 + b1c < BSZ);
    float c0r = 0.f, c1r = 0.f;
    // precomputed output bases (per step advance by KPL)
    __nv_bfloat16* out0h = hdh + ((size_t)(b0 + b0c) * TSZ) * KPL + k0c;
    __nv_bfloat16* out0l = hdl + ((size_t)(b0 + b0c) * TSZ) * KPL + k0c;
    __nv_bfloat16* out1h = hdh + ((size_t)(b0 + b1c) * TSZ) * KPL + k1c;
    __nv_bfloat16* out1l = hdl + ((size_t)(b0 + b1c) * TSZ) * KPL + k1c;

    int bidx[NB];
    #pragma unroll
    for (int b = 0; b < NB; ++b) {
        int bb = b0 + b; if (bb > BSZ - 1) bb = BSZ - 1;
        bidx[b] = bb;
    }

    if (v0) {
        sHa[k0c * 8 + b0c] = h0[bidx[b0c] * HSZ + k0c];
        c0r = c0[bidx[b0c] * HSZ + k0c];
    }
    if (v1) {
        sHa[k1c * 8 + b1c] = h0[bidx[b1c] * HSZ + k1c];
        c1r = c0[bidx[b1c] * HSZ + k1c];
    }
    __syncthreads();

    for (int t = 0; t < TSZ; ++t) {
        const float* hin = (t & 1) ? sHb : sHa;
        float* hout = (t & 1) ? sHa : sHb;
        if (tid < 400) {
            const int j = tid;
            float* gp = sG + j * 9;
            if (t == 0) {
                #pragma unroll
                for (int b = 0; b < NB; ++b)
                    gp[b] = G0[(size_t)bidx[b] * G4 + j];
            } else {
                float acc[NB];
                #pragma unroll
                for (int b = 0; b < NB; ++b) acc[b] = 0.f;
                const float4* wj = (const float4*)(sW + j * 100);
                const float* hp = hin;
                #pragma unroll 5
                for (int k4 = 0; k4 < 25; ++k4) {
                    float4 w = wj[k4];
                    #pragma unroll
                    for (int dd = 0; dd < 4; ++dd) {
                        float wv = (dd == 0) ? w.x : (dd == 1) ? w.y : (dd == 2) ? w.z : w.w;
                        float4 ha = *(const float4*)(hp + (k4 * 4 + dd) * 8);
                        float4 hb = *(const float4*)(hp + (k4 * 4 + dd) * 8 + 4);
                        acc[0] = fmaf(wv, ha.x, acc[0]);
                        acc[1] = fmaf(wv, ha.y, acc[1]);
                        acc[2] = fmaf(wv, ha.z, acc[2]);
                        acc[3] = fmaf(wv, ha.w, acc[3]);
                        acc[4] = fmaf(wv, hb.x, acc[4]);
                        acc[5] = fmaf(wv, hb.y, acc[5]);
                        acc[6] = fmaf(wv, hb.z, acc[6]);
                    }
                }
                #pragma unroll
                for (int b = 0; b < NB; ++b) gp[b] = acc[b] + bq;
            }
        }
        __syncthreads();
        if (v0) {
            float gi = sigf(sG[(k0c) * 9 + b0c]);
            float gf = sigf(sG[(100 + k0c) * 9 + b0c]);
            float gg = tanhf(sG[(200 + k0c) * 9 + b0c]);
            float go = sigf(sG[(300 + k0c) * 9 + b0c]);
            c0r = fmaf(gf, c0r, gi * gg);
            float h = go * tanhf(c0r);
            hout[k0c * 8 + b0c] = h;
            if (w0) {
                __nv_bfloat16 hi = __float2bfloat16(h);
                out0h[(size_t)t * KPL] = hi;
                out0l[(size_t)t * KPL] = __float2bfloat16(h - __bfloat162float(hi));
            }
        }
        if (v1) {
            float gi = sigf(sG[(k1c) * 9 + b1c]);
            float gf = sigf(sG[(100 + k1c) * 9 + b1c]);
            float gg = tanhf(sG[(200 + k1c) * 9 + b1c]);
            float go = sigf(sG[(300 + k1c) * 9 + b1c]);
            c1r = fmaf(gf, c1r, gi * gg);
            float h = go * tanhf(c1r);
            hout[k1c * 8 + b1c] = h;
            if (w1) {
                __nv_bfloat16 hi = __float2bfloat16(h);
                out1h[(size_t)t * KPL] = hi;
                out1l[(size_t)t * KPL] = __float2bfloat16(h - __bfloat162float(hi));
            }
        }
        __syncthreads();
    }
}

// ---------------- launch ----------------------------------------------------
extern "C" void kernel_launch(void* const* d_in, const int* in_sizes, int n_in,
                              void* d_out, int out_size)
{
    const float* src     = (const float*)d_in[0];
    const float* trg     = (const float*)d_in[1];
    const float* enc_Wih = (const float*)d_in[2];
    const float* enc_Whh = (const float*)d_in[3];
    const float* enc_bih = (const float*)d_in[4];
    const float* enc_bhh = (const float*)d_in[5];
    const float* pd_Wih  = (const float*)d_in[6];
    const float* pd_Whh  = (const float*)d_in[7];
    const float* pd_bih  = (const float*)d_in[8];
    const float* pd_bhh  = (const float*)d_in[9];
    const float* pd_fcW  = (const float*)d_in[10];
    const float* pd_fcb  = (const float*)d_in[11];
    const float* rd_Wih  = (const float*)d_in[12];
    const float* rd_Whh  = (const float*)d_in[13];
    const float* rd_bih  = (const float*)d_in[14];
    const float* rd_bhh  = (const float*)d_in[15];
    const float* rd_fcW  = (const float*)d_in[16];
    const float* rd_fcb  = (const float*)d_in[17];
    float* out = (float*)d_out;

    float *pX, *pHenc, *pCenc, *pG0, *pWeff, *pBeff, *pLoss;
    __nv_bfloat16 *pSrch, *pSrcl, *pWihh, *pWihl, *pFcwh, *pFcwl, *pHdh, *pHdl;
    cudaGetSymbolAddress((void**)&pX,    g_X);
    cudaGetSymbolAddress((void**)&pHenc, g_henc);
    cudaGetSymbolAddress((void**)&pCenc, g_cenc);
    cudaGetSymbolAddress((void**)&pG0,   g_G0);
    cudaGetSymbolAddress((void**)&pWeff, g_Weff);
    cudaGetSymbolAddress((void**)&pBeff, g_beff);
    cudaGetSymbolAddress((void**)&pLoss, g_loss);
    cudaGetSymbolAddress((void**)&pSrch, g_srch);
    cudaGetSymbolAddress((void**)&pSrcl, g_srcl);
    cudaGetSymbolAddress((void**)&pWihh, g_wihh);
    cudaGetSymbolAddress((void**)&pWihl, g_wihl);
    cudaGetSymbolAddress((void**)&pFcwh, g_fcwh);
    cudaGetSymbolAddress((void**)&pFcwl, g_fcwl);
    cudaGetSymbolAddress((void**)&pHdh,  g_hdh);
    cudaGetSymbolAddress((void**)&pHdl,  g_hdl);

    const int SMEM_RNN = RNN_SMEM_F * 4;
    cudaFuncSetAttribute(rnn_enc,  cudaFuncAttributeMaxDynamicSharedMemorySize, SMEM_RNN);
    cudaFuncSetAttribute(rnn_dec2, cudaFuncAttributeMaxDynamicSharedMemorySize, SMEM_RNN);

    const int RNN_BLOCKS = (BSZ + NB - 1) / NB;  // 143
    const int MROWS = BSZ * TSZ;                 // 100000

    // launches 1-5: prep (order chosen so launch #6 = phase-A tensor GEMM,
    // which is what ncu -s 5 -c 1 captures)
    cvt_split_t<ISZ, KPA><<<(MROWS * (KPA / 4) + 255) / 256, 256>>>(src, pSrch, pSrcl, MROWS);
    cvt_split_t<ISZ, KPA><<<(G4 * (KPA / 4) + 255) / 256, 256>>>(enc_Wih, pWihh, pWihl, G4);
    cvt_split_t<HSZ, KPL><<<(ISZ * (KPL / 4) + 255) / 256, 256>>>(pd_fcW, pFcwh, pFcwl, ISZ);
    cvt_split_t<HSZ, KPL><<<(ISZ * (KPL / 4) + 255) / 256, 256>>>(rd_fcW, pFcwh + ISZ * KPL,
                                                                  pFcwl + ISZ * KPL, ISZ);
    {
        dim3 grid(G4, 2);
        fold2_kernel<<<grid, 128>>>(pd_Wih, pd_Whh, pd_fcW, pd_fcb, pd_bih, pd_bhh,
                                    rd_Wih, rd_Whh, rd_fcW, rd_fcb, rd_bih, rd_bhh,
                                    pWeff, pBeff, pLoss);
    }

    // launch 6: phase A: X = src @ enc_Wih^T + biases (tensor cores)
    {
        dim3 grid((G4 + 63) / 64, (MROWS + 127) / 128);
        gemm_bf16_nt<<<grid, 256>>>(pSrch, pSrcl, KPA, pWihh, pWihl, KPA,
                                    enc_bih, enc_bhh, pX, MROWS, G4, KPA,
                                    nullptr, nullptr, 0);
    }

    // encoder recurrence
    rnn_enc<<<RNN_BLOCKS, NT_RNN, SMEM_RNN>>>(pX, enc_Whh, pHenc, pCenc);

    // decoder step-0 gates (both decoders, one launch)
    {
        dim3 grid((G4 + 63) / 64, (BSZ + 255) / 256, 2);
        gemm_g0<<<grid, 256>>>(pHenc, pd_Whh, rd_Whh, pd_bih, rd_bih,
                               pd_bhh, rd_bhh, pG0, BSZ, G4, HSZ);
    }

    // merged decoders (2 CTAs/SM)
    {
        dim3 grid(RNN_BLOCKS, 2);
        rnn_dec2<<<grid, NT_RNN, SMEM_RNN>>>(pG0, pWeff, pBeff, pHenc, pCenc,
                                             pHdh, pHdl);
    }

    // losses (tensor cores, fused MSE epilogue)
    {
        size_t hdsz = (size_t)MROWS * KPL;
        dim3 grid((ISZ + 63) / 64, (MROWS + 127) / 128);
        gemm_bf16_nt<<<grid, 256>>>(pHdh, pHdl, KPL, pFcwh, pFcwl, KPL,
                                    pd_fcb, nullptr, nullptr, MROWS, ISZ, KPL,
                                    trg, pLoss + 1, 0);
        gemm_bf16_nt<<<grid, 256>>>(pHdh + hdsz, pHdl + hdsz, KPL,
                                    pFcwh + ISZ * KPL, pFcwl + ISZ * KPL, KPL,
                                    rd_fcb, nullptr, nullptr, MROWS, ISZ, KPL,
                                    src, pLoss + 0, TSZ);
    }

    finalize_kernel<<<1, 1>>>(pLoss, out, 1.0f / (float)(BSZ * TSZ * ISZ));
}

// round 8
// speedup vs baseline: 2.1536x; 1.0459x over previous
#include <cuda_runtime.h>
#include <cuda_bf16.h>
#include <math.h>

#define BSZ 1000
#define TSZ 100
#define ISZ 264
#define HSZ 100
#define G4  400   // 4*H
#define KPA 272   // padded K for phase A (264 -> 17*16)
#define KPL 112   // padded K for loss GEMMs (100 -> 7*16)

// ---------------- device scratch (static: no allocation allowed) ----------
__device__ float g_X[(size_t)BSZ * TSZ * G4];       // encoder gate inputs fp32
__device__ float g_henc[BSZ * HSZ];
__device__ float g_cenc[BSZ * HSZ];
__device__ float g_G0[2][BSZ * G4];                 // decoder step-0 gates
__device__ float g_Weff[2][G4 * HSZ];
__device__ float g_beff[2][G4];
__device__ float g_loss[2];

// bf16 split operands
__device__ __nv_bfloat16 g_srch[(size_t)BSZ * TSZ * KPA];
__device__ __nv_bfloat16 g_srcl[(size_t)BSZ * TSZ * KPA];
__device__ __nv_bfloat16 g_wihh[G4 * KPA];
__device__ __nv_bfloat16 g_wihl[G4 * KPA];
__device__ __nv_bfloat16 g_fcwh[2][ISZ * KPL];
__device__ __nv_bfloat16 g_fcwl[2][ISZ * KPL];
__device__ __nv_bfloat16 g_hdh[2][(size_t)BSZ * TSZ * KPL];  // decoder h, split
__device__ __nv_bfloat16 g_hdl[2][(size_t)BSZ * TSZ * KPL];

// ---------------- fast activations (ex2/rcp approx: ~2^-22 rel err) --------
__device__ __forceinline__ float ex2f(float x) {
    float r; asm("ex2.approx.f32 %0, %1;" : "=f"(r) : "f"(x)); return r;
}
__device__ __forceinline__ float rcpf(float x) {
    float r; asm("rcp.approx.f32 %0, %1;" : "=f"(r) : "f"(x)); return r;
}
__device__ __forceinline__ float sigf(float x) {
    return rcpf(1.f + ex2f(-1.4426950408889634f * x));
}
__device__ __forceinline__ float tanhf_fast(float x) {
    return fmaf(2.f, rcpf(1.f + ex2f(-2.8853900817779268f * x)), -1.f);
}

// ---------------- small kernels -------------------------------------------
__global__ void finalize_kernel(const float* loss, float* out, float inv) {
    out[0] = loss[0] * inv;
    out[1] = loss[1] * inv;
}

// fp32 -> (bf16 hi, bf16 lo), K padded to Kp, templated, float4 vectorized.
template <int K, int Kp>
__global__ __launch_bounds__(256) void cvt_split_t(
    const float* __restrict__ x, __nv_bfloat16* __restrict__ h,
    __nv_bfloat16* __restrict__ l, int rows)
{
    const int Kp4 = Kp / 4;
    int idx = blockIdx.x * 256 + threadIdx.x;
    if (idx >= rows * Kp4) return;
    int r = idx / Kp4;
    int k4 = (idx - r * Kp4) * 4;
    float4 v;
    if (k4 + 3 < K) {
        v = *(const float4*)(x + (size_t)r * K + k4);
    } else {
        float tmp[4] = {0.f, 0.f, 0.f, 0.f};
        #pragma unroll
        for (int e = 0; e < 4; ++e)
            if (k4 + e < K) tmp[e] = x[(size_t)r * K + k4 + e];
        v = make_float4(tmp[0], tmp[1], tmp[2], tmp[3]);
    }
    float vv[4] = {v.x, v.y, v.z, v.w};
    __nv_bfloat16 hh[4], ll[4];
    #pragma unroll
    for (int e = 0; e < 4; ++e) {
        hh[e] = __float2bfloat16(vv[e]);
        ll[e] = __float2bfloat16(vv[e] - __bfloat162float(hh[e]));
    }
    *(uint2*)(h + (size_t)idx * 4) = *(const uint2*)hh;
    *(uint2*)(l + (size_t)idx * 4) = *(const uint2*)ll;
}

// Both decoder folds in one launch: blockIdx.y selects decoder.
__global__ __launch_bounds__(128) void fold2_kernel(
    const float* __restrict__ pd_Wih, const float* __restrict__ pd_Whh,
    const float* __restrict__ pd_fcW, const float* __restrict__ pd_fcb,
    const float* __restrict__ pd_bih, const float* __restrict__ pd_bhh,
    const float* __restrict__ rd_Wih, const float* __restrict__ rd_Whh,
    const float* __restrict__ rd_fcW, const float* __restrict__ rd_fcb,
    const float* __restrict__ rd_bih, const float* __restrict__ rd_bhh,
    float* __restrict__ Weff, float* __restrict__ beff, float* __restrict__ loss)
{
    const int did = blockIdx.y;
    const float* Wih = did ? rd_Wih : pd_Wih;
    const float* Whh = did ? rd_Whh : pd_Whh;
    const float* fcW = did ? rd_fcW : pd_fcW;
    const float* fcb = did ? rd_fcb : pd_fcb;
    const float* bih = did ? rd_bih : pd_bih;
    const float* bhh = did ? rd_bhh : pd_bhh;
    float* We = Weff + (size_t)did * G4 * HSZ;
    float* be = beff + (size_t)did * G4;

    int j = blockIdx.x;
    int tid = threadIdx.x;
    if (blockIdx.x == 0 && did == 0 && tid < 2) loss[tid] = 0.f;

    __shared__ float swih[ISZ];
    __shared__ float red[128];
    for (int i = tid; i < ISZ; i += 128) swih[i] = Wih[j * ISZ + i];
    __syncthreads();
    if (tid < HSZ) {
        float acc = Whh[j * HSZ + tid];
        #pragma unroll 4
        for (int i = 0; i < ISZ; ++i)
            acc = fmaf(swih[i], fcW[i * HSZ + tid], acc);
        We[j * HSZ + tid] = acc;
    }
    float p = 0.f;
    for (int i = tid; i < ISZ; i += 128) p = fmaf(swih[i], fcb[i], p);
    red[tid] = p;
    __syncthreads();
    for (int s = 64; s > 0; s >>= 1) {
        if (tid < s) red[tid] += red[tid + s];
        __syncthreads();
    }
    if (tid == 0) be[j] = bih[j] + bhh[j] + red[0];
}

// ---------------- SIMT NT GEMM for the two small G0 GEMMs ------------------
#define AP 264
#define BP 68
__global__ __launch_bounds__(256) void gemm_g0(
    const float* __restrict__ A,
    const float* __restrict__ B0, const float* __restrict__ B1,
    const float* __restrict__ b10, const float* __restrict__ b11,
    const float* __restrict__ b20, const float* __restrict__ b21,
    float* __restrict__ Cbase, int M, int N, int K)
{
    const int did = blockIdx.z;
    const float* B = did ? B1 : B0;
    const float* bias1 = did ? b11 : b10;
    const float* bias2 = did ? b21 : b20;
    float* C = Cbase + (size_t)did * M * N;

    __shared__ float As[8 * AP];
    __shared__ float Bs[8 * BP];
    const int tid = threadIdx.x;
    const int tx = tid & 7;
    const int ty = tid >> 3;
    const int m0 = blockIdx.y * 256, n0 = blockIdx.x * 64;

    float acc[8][8];
    #pragma unroll
    for (int i = 0; i < 8; ++i)
        #pragma unroll
        for (int j = 0; j < 8; ++j) acc[i][j] = 0.f;

    const int am = m0 + tid;
    const int br = tid >> 2;
    const int bc = (tid & 3) * 2;

    for (int k0 = 0; k0 < K; k0 += 8) {
        #pragma unroll
        for (int j = 0; j < 8; ++j) {
            int k = k0 + j;
            As[j * AP + tid] = (am < M && k < K) ? A[(size_t)am * K + k] : 0.f;
        }
        {
            int n = n0 + br;
            #pragma unroll
            for (int j = 0; j < 2; ++j) {
                int k = k0 + bc + j;
                Bs[(bc + j) * BP + br] = (n < N && k < K) ? B[(size_t)n * K + k] : 0.f;
            }
        }
        __syncthreads();
        #pragma unroll
        for (int kk = 0; kk < 8; ++kk) {
            float4 a0 = *(const float4*)(As + kk * AP + ty * 8);
            float4 a1 = *(const float4*)(As + kk * AP + ty * 8 + 4);
            float4 b0 = *(const float4*)(Bs + kk * BP + tx * 8);
            float4 b1 = *(const float4*)(Bs + kk * BP + tx * 8 + 4);
            float av[8] = {a0.x, a0.y, a0.z, a0.w, a1.x, a1.y, a1.z, a1.w};
            float bv[8] = {b0.x, b0.y, b0.z, b0.w, b1.x, b1.y, b1.z, b1.w};
            #pragma unroll
            for (int i = 0; i < 8; ++i)
                #pragma unroll
                for (int j = 0; j < 8; ++j)
                    acc[i][j] = fmaf(av[i], bv[j], acc[i][j]);
        }
        __syncthreads();
    }

    #pragma unroll
    for (int i = 0; i < 8; ++i) {
        int m = m0 + ty * 8 + i;
        if (m < M) {
            #pragma unroll
            for (int j = 0; j < 8; ++j) {
                int n = n0 + tx * 8 + j;
                if (n < N) C[(size_t)m * N + n] = acc[i][j] + bias1[n] + bias2[n];
            }
        }
    }
}

// ---------------- tensor-core split-bf16 NT GEMM core ----------------------
// Double-buffered smem, one __syncthreads per k-iter.
#define SAP 24

__device__ __forceinline__ void mma16816(float* d, const unsigned* a, const unsigned* b) {
    asm volatile(
        "mma.sync.aligned.m16n8k16.row.col.f32.bf16.bf16.f32 "
        "{%0,%1,%2,%3},{%4,%5,%6,%7},{%8,%9},{%0,%1,%2,%3};"
        : "+f"(d[0]), "+f"(d[1]), "+f"(d[2]), "+f"(d[3])
        : "r"(a[0]), "r"(a[1]), "r"(a[2]), "r"(a[3]), "r"(b[0]), "r"(b[1]));
}

// Shared mainloop: computes d[2][4][4] for a 128x64 tile.
struct Bf16GemmSmem {
    __nv_bfloat16 Ash[2][128 * SAP];
    __nv_bfloat16 Asl[2][128 * SAP];
    __nv_bfloat16 Bsh[2][64 * SAP];
    __nv_bfloat16 Bsl[2][64 * SAP];
    float red[256];
};

__device__ __forceinline__ void bf16_mainloop(
    Bf16GemmSmem* sm, float d[2][4][4],
    const __nv_bfloat16* Ah, const __nv_bfloat16* Al, int lda,
    const __nv_bfloat16* Bh, const __nv_bfloat16* Bl, int ldb,
    int m0, int n0, int M, int N, int Kp)
{
    const int tid = threadIdx.x;
    const int lane = tid & 31;
    const int wid = tid >> 5;
    const int wy = wid & 3;
    const int wx = wid >> 2;
    const int g = lane >> 2, t = lane & 3;

    const int ar = tid >> 1;
    const int ah8 = (tid & 1) * 8;
    const int bs = tid & 127;
    const int brow = bs >> 1;
    const int bh8 = (bs & 1) * 8;
    const int gm = m0 + ar;
    const int gn = n0 + brow;
    const __nv_bfloat16* srcB = (tid < 128) ? Bh : Bl;

    const uint4 zv = make_uint4(0, 0, 0, 0);
    uint4 vh = zv, vl = zv, vb = zv;
    if (gm < M) {
        vh = *(const uint4*)(Ah + (size_t)gm * lda + ah8);
        vl = *(const uint4*)(Al + (size_t)gm * lda + ah8);
    }
    if (gn < N) vb = *(const uint4*)(srcB + (size_t)gn * ldb + bh8);

    const int niter = Kp / 16;
    for (int i = 0; i < niter; ++i) {
        const int cur = i & 1;
        *(uint4*)&sm->Ash[cur][ar * SAP + ah8] = vh;
        *(uint4*)&sm->Asl[cur][ar * SAP + ah8] = vl;
        __nv_bfloat16* dstB = (tid < 128) ? sm->Bsh[cur] : sm->Bsl[cur];
        *(uint4*)&dstB[brow * SAP + bh8] = vb;
        __syncthreads();

        if (i + 1 < niter) {
            int kn = (i + 1) * 16;
            vh = zv; vl = zv; vb = zv;
            if (gm < M) {
                vh = *(const uint4*)(Ah + (size_t)gm * lda + kn + ah8);
                vl = *(const uint4*)(Al + (size_t)gm * lda + kn + ah8);
            }
            if (gn < N) vb = *(const uint4*)(srcB + (size_t)gn * ldb + kn + bh8);
        }

        unsigned bhf[4][2], blf[4][2];
        #pragma unroll
        for (int ni = 0; ni < 4; ++ni) {
            int base = (wx * 32 + ni * 8 + g) * SAP;
            bhf[ni][0] = *(const unsigned*)&sm->Bsh[cur][base + 2 * t];
            bhf[ni][1] = *(const unsigned*)&sm->Bsh[cur][base + 2 * t + 8];
            blf[ni][0] = *(const unsigned*)&sm->Bsl[cur][base + 2 * t];
            blf[ni][1] = *(const unsigned*)&sm->Bsl[cur][base + 2 * t + 8];
        }
        #pragma unroll
        for (int mi = 0; mi < 2; ++mi) {
            int r0 = (wy * 32 + mi * 16 + g) * SAP;
            int r1 = (wy * 32 + mi * 16 + 8 + g) * SAP;
            unsigned ahf[4], alf[4];
            ahf[0] = *(const unsigned*)&sm->Ash[cur][r0 + 2 * t];
            ahf[1] = *(const unsigned*)&sm->Ash[cur][r1 + 2 * t];
            ahf[2] = *(const unsigned*)&sm->Ash[cur][r0 + 2 * t + 8];
            ahf[3] = *(const unsigned*)&sm->Ash[cur][r1 + 2 * t + 8];
            alf[0] = *(const unsigned*)&sm->Asl[cur][r0 + 2 * t];
            alf[1] = *(const unsigned*)&sm->Asl[cur][r1 + 2 * t];
            alf[2] = *(const unsigned*)&sm->Asl[cur][r0 + 2 * t + 8];
            alf[3] = *(const unsigned*)&sm->Asl[cur][r1 + 2 * t + 8];
            #pragma unroll
            for (int ni = 0; ni < 4; ++ni) {
                mma16816(d[mi][ni], ahf, bhf[ni]);
                mma16816(d[mi][ni], ahf, blf[ni]);
                mma16816(d[mi][ni], alf, bhf[ni]);
            }
        }
    }
    __syncthreads();
}

// Phase-A variant: stores C with two biases.
__global__ __launch_bounds__(256) void gemm_bf16_store(
    const __nv_bfloat16* __restrict__ Ah, const __nv_bfloat16* __restrict__ Al, int lda,
    const __nv_bfloat16* __restrict__ Bh, const __nv_bfloat16* __restrict__ Bl, int ldb,
    const float* __restrict__ bias1, const float* __restrict__ bias2,
    float* __restrict__ C, int M, int N, int Kp)
{
    extern __shared__ char smraw[];
    Bf16GemmSmem* sm = (Bf16GemmSmem*)smraw;
    const int tid = threadIdx.x;
    const int lane = tid & 31;
    const int wid = tid >> 5;
    const int wy = wid & 3, wx = wid >> 2;
    const int g = lane >> 2, t = lane & 3;
    const int m0 = blockIdx.y * 128, n0 = blockIdx.x * 64;

    float d[2][4][4];
    #pragma unroll
    for (int mi = 0; mi < 2; ++mi)
        #pragma unroll
        for (int ni = 0; ni < 4; ++ni)
            #pragma unroll
            for (int e = 0; e < 4; ++e) d[mi][ni][e] = 0.f;

    bf16_mainloop(sm, d, Ah, Al, lda, Bh, Bl, ldb, m0, n0, M, N, Kp);

    #pragma unroll
    for (int mi = 0; mi < 2; ++mi) {
        #pragma unroll
        for (int rr = 0; rr < 2; ++rr) {
            int m = m0 + wy * 32 + mi * 16 + rr * 8 + g;
            if (m >= M) continue;
            #pragma unroll
            for (int ni = 0; ni < 4; ++ni) {
                int n = n0 + wx * 32 + ni * 8 + 2 * t;
                if (n + 1 < N) {
                    float v0 = d[mi][ni][rr * 2 + 0] + bias1[n] + bias2[n];
                    float v1 = d[mi][ni][rr * 2 + 1] + bias1[n + 1] + bias2[n + 1];
                    *(float2*)(C + (size_t)m * N + n) = make_float2(v0, v1);
                } else if (n < N) {
                    C[(size_t)m * N + n] = d[mi][ni][rr * 2 + 0] + bias1[n] + bias2[n];
                }
            }
        }
    }
}

// Merged loss variant: blockIdx.z selects decoder stream; fused MSE epilogue.
__global__ __launch_bounds__(256) void gemm_bf16_loss2(
    const __nv_bfloat16* __restrict__ Ahb, const __nv_bfloat16* __restrict__ Alb,
    const __nv_bfloat16* __restrict__ Bhb, const __nv_bfloat16* __restrict__ Blb,
    const float* __restrict__ fcb0, const float* __restrict__ fcb1,
    const float* __restrict__ trg, const float* __restrict__ src,
    float* __restrict__ loss, int M, int N)
{
    extern __shared__ char smraw[];
    Bf16GemmSmem* sm = (Bf16GemmSmem*)smraw;
    const int did = blockIdx.z;
    const __nv_bfloat16* Ah = Ahb + (size_t)did * M * KPL;
    const __nv_bfloat16* Al = Alb + (size_t)did * M * KPL;
    const __nv_bfloat16* Bh = Bhb + (size_t)did * N * KPL;
    const __nv_bfloat16* Bl = Blb + (size_t)did * N * KPL;
    const float* bias = did ? fcb1 : fcb0;
    const float* ref = did ? src : trg;
    float* lossOut = did ? (loss + 0) : (loss + 1);
    const int revT = did ? TSZ : 0;

    const int tid = threadIdx.x;
    const int lane = tid & 31;
    const int wid = tid >> 5;
    const int wy = wid & 3, wx = wid >> 2;
    const int g = lane >> 2, t = lane & 3;
    const int m0 = blockIdx.y * 128, n0 = blockIdx.x * 64;

    float d[2][4][4];
    #pragma unroll
    for (int mi = 0; mi < 2; ++mi)
        #pragma unroll
        for (int ni = 0; ni < 4; ++ni)
            #pragma unroll
            for (int e = 0; e < 4; ++e) d[mi][ni][e] = 0.f;

    bf16_mainloop(sm, d, Ah, Al, KPL, Bh, Bl, KPL, m0, n0, M, N, KPL);

    float ls = 0.f;
    #pragma unroll
    for (int mi = 0; mi < 2; ++mi) {
        #pragma unroll
        for (int rr = 0; rr < 2; ++rr) {
            int m = m0 + wy * 32 + mi * 16 + rr * 8 + g;
            if (m >= M) continue;
            const float* rrow;
            if (revT > 0) {
                int b = m / revT, tt = m - b * revT;
                rrow = ref + ((size_t)b * revT + (revT - 1 - tt)) * N;
            } else {
                rrow = ref + (size_t)m * N;
            }
            #pragma unroll
            for (int ni = 0; ni < 4; ++ni) {
                int n = n0 + wx * 32 + ni * 8 + 2 * t;
                #pragma unroll
                for (int e = 0; e < 2; ++e) {
                    if (n + e < N) {
                        float v = d[mi][ni][rr * 2 + e] + bias[n + e];
                        float diff = v - rrow[n + e];
                        ls = fmaf(diff, diff, ls);
                    }
                }
            }
        }
    }
    sm->red[tid] = ls;
    __syncthreads();
    for (int s = 128; s > 0; s >>= 1) {
        if (tid < s) sm->red[tid] += sm->red[tid + s];
        __syncthreads();
    }
    if (tid == 0) atomicAdd(lossOut, sm->red[0]);
}

// ---------------- LSTM recurrence kernels ----------------------------------
#define NB 7
#define NT_RNN 416
#define RNN_SMEM_F (40000 + 800 + 800 + 3600)

__global__ __launch_bounds__(NT_RNN, 1) void rnn_enc(
    const float* __restrict__ X, const float* __restrict__ Whh,
    float* __restrict__ hf, float* __restrict__ cf)
{
    extern __shared__ float s[];
    float* sW  = s;
    float* sHa = s + 40000;
    float* sHb = sHa + 800;
    float* sG  = sHb + 800;
    const int tid = threadIdx.x;
    const int b0 = blockIdx.x * NB;

    for (int i = tid; i < 10000; i += NT_RNN)
        ((float4*)sW)[i] = ((const float4*)Whh)[i];
    for (int i = tid; i < 800; i += NT_RNN) sHa[i] = 0.f;
    __syncthreads();

    const int i0 = tid, i1 = tid + NT_RNN;
    const int k0c = i0 % 100, b0c = i0 / 100;
    const int k1c = i1 % 100, b1c = i1 / 100;
    const bool v0 = (i0 < NB * 100), v1 = (i1 < NB * 100);
    float c0r = 0.f, c1r = 0.f, h0r = 0.f, h1r = 0.f;

    int bidx[NB];
    #pragma unroll
    for (int b = 0; b < NB; ++b) {
        int bb = b0 + b; if (bb > BSZ - 1) bb = BSZ - 1;
        bidx[b] = bb;
    }

    for (int t = 0; t < TSZ; ++t) {
        const float* hin = (t & 1) ? sHb : sHa;
        float* hout = (t & 1) ? sHa : sHb;
        if (tid < 400) {
            const int j = tid;
            float xr[NB];
            #pragma unroll
            for (int b = 0; b < NB; ++b)
                xr[b] = X[((size_t)bidx[b] * TSZ + t) * G4 + j];
            float acc[NB];
            #pragma unroll
            for (int b = 0; b < NB; ++b) acc[b] = 0.f;
            const float4* wj = (const float4*)(sW + j * 100);
            const float* hp = hin;
            #pragma unroll 5
            for (int k4 = 0; k4 < 25; ++k4) {
                float4 w = wj[k4];
                #pragma unroll
                for (int dd = 0; dd < 4; ++dd) {
                    float wv = (dd == 0) ? w.x : (dd == 1) ? w.y : (dd == 2) ? w.z : w.w;
                    float4 ha = *(const float4*)(hp + (k4 * 4 + dd) * 8);
                    float4 hb = *(const float4*)(hp + (k4 * 4 + dd) * 8 + 4);
                    acc[0] = fmaf(wv, ha.x, acc[0]);
                    acc[1] = fmaf(wv, ha.y, acc[1]);
                    acc[2] = fmaf(wv, ha.z, acc[2]);
                    acc[3] = fmaf(wv, ha.w, acc[3]);
                    acc[4] = fmaf(wv, hb.x, acc[4]);
                    acc[5] = fmaf(wv, hb.y, acc[5]);
                    acc[6] = fmaf(wv, hb.z, acc[6]);
                }
            }
            float* gp = sG + j * 9;
            #pragma unroll
            for (int b = 0; b < NB; ++b) gp[b] = acc[b] + xr[b];
        }
        __syncthreads();
        if (v0) {
            float gi = sigf(sG[(k0c) * 9 + b0c]);
            float gf = sigf(sG[(100 + k0c) * 9 + b0c]);
            float gg = tanhf_fast(sG[(200 + k0c) * 9 + b0c]);
            float go = sigf(sG[(300 + k0c) * 9 + b0c]);
            c0r = fmaf(gf, c0r, gi * gg);
            h0r = go * tanhf_fast(c0r);
            hout[k0c * 8 + b0c] = h0r;
        }
        if (v1) {
            float gi = sigf(sG[(k1c) * 9 + b1c]);
            float gf = sigf(sG[(100 + k1c) * 9 + b1c]);
            float gg = tanhf_fast(sG[(200 + k1c) * 9 + b1c]);
            float go = sigf(sG[(300 + k1c) * 9 + b1c]);
            c1r = fmaf(gf, c1r, gi * gg);
            h1r = go * tanhf_fast(c1r);
            hout[k1c * 8 + b1c] = h1r;
        }
        __syncthreads();
    }

    if (v0 && b0 + b0c < BSZ) {
        hf[(b0 + b0c) * HSZ + k0c] = h0r;
        cf[(b0 + b0c) * HSZ + k0c] = c0r;
    }
    if (v1 && b0 + b1c < BSZ) {
        hf[(b0 + b1c) * HSZ + k1c] = h1r;
        cf[(b0 + b1c) * HSZ + k1c] = c1r;
    }
}

// merged decoders: grid (143, 2); blockIdx.y selects decoder.
// (180KB smem/CTA -> 1 CTA/SM; occupancy 1 so no reg cap.)
__global__ __launch_bounds__(NT_RNN, 1) void rnn_dec2(
    const float* __restrict__ G0base, const float* __restrict__ Weffbase,
    const float* __restrict__ beffbase,
    const float* __restrict__ h0, const float* __restrict__ c0,
    __nv_bfloat16* __restrict__ hdhb, __nv_bfloat16* __restrict__ hdlb)
{
    extern __shared__ float s[];
    float* sW  = s;
    float* sHa = s + 40000;
    float* sHb = sHa + 800;
    float* sG  = sHb + 800;
    const int tid = threadIdx.x;
    const int b0 = blockIdx.x * NB;
    const int did = blockIdx.y;

    const float* G0   = G0base + (size_t)did * BSZ * G4;
    const float* Weff = Weffbase + (size_t)did * G4 * HSZ;
    const float* beff = beffbase + (size_t)did * G4;
    const size_t hdoff = (size_t)did * BSZ * TSZ * KPL;
    __nv_bfloat16* hdh = hdhb + hdoff;
    __nv_bfloat16* hdl = hdlb + hdoff;

    for (int i = tid; i < 10000; i += NT_RNN)
        ((float4*)sW)[i] = ((const float4*)Weff)[i];

    const float bq = (tid < 400) ? beff[tid] : 0.f;

    const int i0 = tid, i1 = tid + NT_RNN;
    const int k0c = i0 % 100, b0c = i0 / 100;
    const int k1c = i1 % 100, b1c = i1 / 100;
    const bool v0 = (i0 < NB * 100), v1 = (i1 < NB * 100);
    const bool w0 = v0 && (b0 + b0c < BSZ);
    const bool w1 = v1 && (b0 + b1c < BSZ);
    float c0r = 0.f, c1r = 0.f;
    __nv_bfloat16* out0h = hdh + ((size_t)(b0 + b0c) * TSZ) * KPL + k0c;
    __nv_bfloat16* out0l = hdl + ((size_t)(b0 + b0c) * TSZ) * KPL + k0c;
    __nv_bfloat16* out1h = hdh + ((size_t)(b0 + b1c) * TSZ) * KPL + k1c;
    __nv_bfloat16* out1l = hdl + ((size_t)(b0 + b1c) * TSZ) * KPL + k1c;

    int bidx[NB];
    #pragma unroll
    for (int b = 0; b < NB; ++b) {
        int bb = b0 + b; if (bb > BSZ - 1) bb = BSZ - 1;
        bidx[b] = bb;
    }

    if (v0) {
        sHa[k0c * 8 + b0c] = h0[bidx[b0c] * HSZ + k0c];
        c0r = c0[bidx[b0c] * HSZ + k0c];
    }
    if (v1) {
        sHa[k1c * 8 + b1c] = h0[bidx[b1c] * HSZ + k1c];
        c1r = c0[bidx[b1c] * HSZ + k1c];
    }
    __syncthreads();

    for (int t = 0; t < TSZ; ++t) {
        const float* hin = (t & 1) ? sHb : sHa;
        float* hout = (t & 1) ? sHa : sHb;
        if (tid < 400) {
            const int j = tid;
            float* gp = sG + j * 9;
            if (t == 0) {
                #pragma unroll
                for (int b = 0; b < NB; ++b)
                    gp[b] = G0[(size_t)bidx[b] * G4 + j];
            } else {
                float acc[NB];
                #pragma unroll
                for (int b = 0; b < NB; ++b) acc[b] = 0.f;
                const float4* wj = (const float4*)(sW + j * 100);
                const float* hp = hin;
                #pragma unroll 5
                for (int k4 = 0; k4 < 25; ++k4) {
                    float4 w = wj[k4];
                    #pragma unroll
                    for (int dd = 0; dd < 4; ++dd) {
                        float wv = (dd == 0) ? w.x : (dd == 1) ? w.y : (dd == 2) ? w.z : w.w;
                        float4 ha = *(const float4*)(hp + (k4 * 4 + dd) * 8);
                        float4 hb = *(const float4*)(hp + (k4 * 4 + dd) * 8 + 4);
                        acc[0] = fmaf(wv, ha.x, acc[0]);
                        acc[1] = fmaf(wv, ha.y, acc[1]);
                        acc[2] = fmaf(wv, ha.z, acc[2]);
                        acc[3] = fmaf(wv, ha.w, acc[3]);
                        acc[4] = fmaf(wv, hb.x, acc[4]);
                        acc[5] = fmaf(wv, hb.y, acc[5]);
                        acc[6] = fmaf(wv, hb.z, acc[6]);
                    }
                }
                #pragma unroll
                for (int b = 0; b < NB; ++b) gp[b] = acc[b] + bq;
            }
        }
        __syncthreads();
        if (v0) {
            float gi = sigf(sG[(k0c) * 9 + b0c]);
            float gf = sigf(sG[(100 + k0c) * 9 + b0c]);
            float gg = tanhf_fast(sG[(200 + k0c) * 9 + b0c]);
            float go = sigf(sG[(300 + k0c) * 9 + b0c]);
            c0r = fmaf(gf, c0r, gi * gg);
            float h = go * tanhf_fast(c0r);
            hout[k0c * 8 + b0c] = h;
            if (w0) {
                __nv_bfloat16 hi = __float2bfloat16(h);
                out0h[(size_t)t * KPL] = hi;
                out0l[(size_t)t * KPL] = __float2bfloat16(h - __bfloat162float(hi));
            }
        }
        if (v1) {
            float gi = sigf(sG[(k1c) * 9 + b1c]);
            float gf = sigf(sG[(100 + k1c) * 9 + b1c]);
            float gg = tanhf_fast(sG[(200 + k1c) * 9 + b1c]);
            float go = sigf(sG[(300 + k1c) * 9 + b1c]);
            c1r = fmaf(gf, c1r, gi * gg);
            float h = go * tanhf_fast(c1r);
            hout[k1c * 8 + b1c] = h;
            if (w1) {
                __nv_bfloat16 hi = __float2bfloat16(h);
                out1h[(size_t)t * KPL] = hi;
                out1l[(size_t)t * KPL] = __float2bfloat16(h - __bfloat162float(hi));
            }
        }
        __syncthreads();
    }
}

// ---------------- launch ----------------------------------------------------
extern "C" void kernel_launch(void* const* d_in, const int* in_sizes, int n_in,
                              void* d_out, int out_size)
{
    const float* src     = (const float*)d_in[0];
    const float* trg     = (const float*)d_in[1];
    const float* enc_Wih = (const float*)d_in[2];
    const float* enc_Whh = (const float*)d_in[3];
    const float* enc_bih = (const float*)d_in[4];
    const float* enc_bhh = (const float*)d_in[5];
    const float* pd_Wih  = (const float*)d_in[6];
    const float* pd_Whh  = (const float*)d_in[7];
    const float* pd_bih  = (const float*)d_in[8];
    const float* pd_bhh  = (const float*)d_in[9];
    const float* pd_fcW  = (const float*)d_in[10];
    const float* pd_fcb  = (const float*)d_in[11];
    const float* rd_Wih  = (const float*)d_in[12];
    const float* rd_Whh  = (const float*)d_in[13];
    const float* rd_bih  = (const float*)d_in[14];
    const float* rd_bhh  = (const float*)d_in[15];
    const float* rd_fcW  = (const float*)d_in[16];
    const float* rd_fcb  = (const float*)d_in[17];
    float* out = (float*)d_out;

    float *pX, *pHenc, *pCenc, *pG0, *pWeff, *pBeff, *pLoss;
    __nv_bfloat16 *pSrch, *pSrcl, *pWihh, *pWihl, *pFcwh, *pFcwl, *pHdh, *pHdl;
    cudaGetSymbolAddress((void**)&pX,    g_X);
    cudaGetSymbolAddress((void**)&pHenc, g_henc);
    cudaGetSymbolAddress((void**)&pCenc, g_cenc);
    cudaGetSymbolAddress((void**)&pG0,   g_G0);
    cudaGetSymbolAddress((void**)&pWeff, g_Weff);
    cudaGetSymbolAddress((void**)&pBeff, g_beff);
    cudaGetSymbolAddress((void**)&pLoss, g_loss);
    cudaGetSymbolAddress((void**)&pSrch, g_srch);
    cudaGetSymbolAddress((void**)&pSrcl, g_srcl);
    cudaGetSymbolAddress((void**)&pWihh, g_wihh);
    cudaGetSymbolAddress((void**)&pWihl, g_wihl);
    cudaGetSymbolAddress((void**)&pFcwh, g_fcwh);
    cudaGetSymbolAddress((void**)&pFcwl, g_fcwl);
    cudaGetSymbolAddress((void**)&pHdh,  g_hdh);
    cudaGetSymbolAddress((void**)&pHdl,  g_hdl);

    const int SMEM_RNN = RNN_SMEM_F * 4;
    const int SMEM_GEMM = (int)sizeof(Bf16GemmSmem);
    cudaFuncSetAttribute(rnn_enc,  cudaFuncAttributeMaxDynamicSharedMemorySize, SMEM_RNN);
    cudaFuncSetAttribute(rnn_dec2, cudaFuncAttributeMaxDynamicSharedMemorySize, SMEM_RNN);
    cudaFuncSetAttribute(gemm_bf16_store, cudaFuncAttributeMaxDynamicSharedMemorySize, SMEM_GEMM);
    cudaFuncSetAttribute(gemm_bf16_loss2, cudaFuncAttributeMaxDynamicSharedMemorySize, SMEM_GEMM);

    const int RNN_BLOCKS = (BSZ + NB - 1) / NB;  // 143
    const int MROWS = BSZ * TSZ;                 // 100000

    // prep
    cvt_split_t<ISZ, KPA><<<(MROWS * (KPA / 4) + 255) / 256, 256>>>(src, pSrch, pSrcl, MROWS);
    cvt_split_t<ISZ, KPA><<<(G4 * (KPA / 4) + 255) / 256, 256>>>(enc_Wih, pWihh, pWihl, G4);
    cvt_split_t<HSZ, KPL><<<(ISZ * (KPL / 4) + 255) / 256, 256>>>(pd_fcW, pFcwh, pFcwl, ISZ);
    cvt_split_t<HSZ, KPL><<<(ISZ * (KPL / 4) + 255) / 256, 256>>>(rd_fcW, pFcwh + ISZ * KPL,
                                                                  pFcwl + ISZ * KPL, ISZ);
    {
        dim3 grid(G4, 2);
        fold2_kernel<<<grid, 128>>>(pd_Wih, pd_Whh, pd_fcW, pd_fcb, pd_bih, pd_bhh,
                                    rd_Wih, rd_Whh, rd_fcW, rd_fcb, rd_bih, rd_bhh,
                                    pWeff, pBeff, pLoss);
    }

    // phase A: X = src @ enc_Wih^T + biases (tensor cores)
    {
        dim3 grid((G4 + 63) / 64, (MROWS + 127) / 128);
        gemm_bf16_store<<<grid, 256, SMEM_GEMM>>>(pSrch, pSrcl, KPA, pWihh, pWihl, KPA,
                                                  enc_bih, enc_bhh, pX, MROWS, G4, KPA);
    }

    // encoder recurrence
    rnn_enc<<<RNN_BLOCKS, NT_RNN, SMEM_RNN>>>(pX, enc_Whh, pHenc, pCenc);

    // decoder step-0 gates (both decoders, one launch)
    {
        dim3 grid((G4 + 63) / 64, (BSZ + 255) / 256, 2);
        gemm_g0<<<grid, 256>>>(pHenc, pd_Whh, rd_Whh, pd_bih, rd_bih,
                               pd_bhh, rd_bhh, pG0, BSZ, G4, HSZ);
    }

    // merged decoders
    {
        dim3 grid(RNN_BLOCKS, 2);
        rnn_dec2<<<grid, NT_RNN, SMEM_RNN>>>(pG0, pWeff, pBeff, pHenc, pCenc,
                                             pHdh, pHdl);
    }

    // merged losses (tensor cores, fused MSE epilogue)
    {
        dim3 grid((ISZ + 63) / 64, (MROWS + 127) / 128, 2);
        gemm_bf16_loss2<<<grid, 256, SMEM_GEMM>>>(pHdh, pHdl, pFcwh, pFcwl,
                                                  pd_fcb, rd_fcb, trg, src,
                                                  pLoss, MROWS, ISZ);
    }

    finalize_kernel<<<1, 1>>>(pLoss, out, 1.0f / (float)(BSZ * TSZ * ISZ));
}

// round 9
// speedup vs baseline: 2.2795x; 1.0584x over previous
#include <cuda_runtime.h>
#include <cuda_bf16.h>
#include <math.h>

#define BSZ 1000
#define TSZ 100
#define ISZ 264
#define HSZ 100
#define G4  400   // 4*H
#define KPA 272   // padded K for phase A (264 -> 17*16)
#define KPL 112   // padded K for loss GEMMs (100 -> 7*16)

// ---------------- device scratch (static: no allocation allowed) ----------
__device__ float g_X[(size_t)BSZ * TSZ * G4];       // encoder gate inputs fp32
__device__ float g_henc[BSZ * HSZ];
__device__ float g_cenc[BSZ * HSZ];
__device__ float g_G0[2][BSZ * G4];                 // decoder step-0 gates
__device__ float g_Weff[2][G4 * HSZ];
__device__ float g_beff[2][G4];
__device__ float g_loss[2];

// bf16 split operands
__device__ __nv_bfloat16 g_srch[(size_t)BSZ * TSZ * KPA];
__device__ __nv_bfloat16 g_srcl[(size_t)BSZ * TSZ * KPA];
__device__ __nv_bfloat16 g_wihh[G4 * KPA];
__device__ __nv_bfloat16 g_wihl[G4 * KPA];
__device__ __nv_bfloat16 g_fcwh[2][ISZ * KPL];
__device__ __nv_bfloat16 g_fcwl[2][ISZ * KPL];
__device__ __nv_bfloat16 g_hdh[2][(size_t)BSZ * TSZ * KPL];  // decoder h, split
__device__ __nv_bfloat16 g_hdl[2][(size_t)BSZ * TSZ * KPL];

// ---------------- fast activations (ex2/rcp approx: ~2^-22 rel err) --------
__device__ __forceinline__ float ex2f(float x) {
    float r; asm("ex2.approx.f32 %0, %1;" : "=f"(r) : "f"(x)); return r;
}
__device__ __forceinline__ float rcpf(float x) {
    float r; asm("rcp.approx.f32 %0, %1;" : "=f"(r) : "f"(x)); return r;
}
__device__ __forceinline__ float sigf(float x) {
    return rcpf(1.f + ex2f(-1.4426950408889634f * x));
}
__device__ __forceinline__ float tanhf_fast(float x) {
    return fmaf(2.f, rcpf(1.f + ex2f(-2.8853900817779268f * x)), -1.f);
}

// ---------------- small kernels -------------------------------------------
__global__ void finalize_kernel(const float* loss, float* out, float inv) {
    out[0] = loss[0] * inv;
    out[1] = loss[1] * inv;
}

// fp32 -> (bf16 hi, bf16 lo), K padded to Kp, templated, float4 vectorized.
template <int K, int Kp>
__global__ __launch_bounds__(256) void cvt_split_t(
    const float* __restrict__ x, __nv_bfloat16* __restrict__ h,
    __nv_bfloat16* __restrict__ l, int rows)
{
    const int Kp4 = Kp / 4;
    int idx = blockIdx.x * 256 + threadIdx.x;
    if (idx >= rows * Kp4) return;
    int r = idx / Kp4;
    int k4 = (idx - r * Kp4) * 4;
    float4 v;
    if (k4 + 3 < K) {
        v = *(const float4*)(x + (size_t)r * K + k4);
    } else {
        float tmp[4] = {0.f, 0.f, 0.f, 0.f};
        #pragma unroll
        for (int e = 0; e < 4; ++e)
            if (k4 + e < K) tmp[e] = x[(size_t)r * K + k4 + e];
        v = make_float4(tmp[0], tmp[1], tmp[2], tmp[3]);
    }
    float vv[4] = {v.x, v.y, v.z, v.w};
    __nv_bfloat16 hh[4], ll[4];
    #pragma unroll
    for (int e = 0; e < 4; ++e) {
        hh[e] = __float2bfloat16(vv[e]);
        ll[e] = __float2bfloat16(vv[e] - __bfloat162float(hh[e]));
    }
    *(uint2*)(h + (size_t)idx * 4) = *(const uint2*)hh;
    *(uint2*)(l + (size_t)idx * 4) = *(const uint2*)ll;
}

// Both decoder folds in one launch: blockIdx.y selects decoder.
__global__ __launch_bounds__(128) void fold2_kernel(
    const float* __restrict__ pd_Wih, const float* __restrict__ pd_Whh,
    const float* __restrict__ pd_fcW, const float* __restrict__ pd_fcb,
    const float* __restrict__ pd_bih, const float* __restrict__ pd_bhh,
    const float* __restrict__ rd_Wih, const float* __restrict__ rd_Whh,
    const float* __restrict__ rd_fcW, const float* __restrict__ rd_fcb,
    const float* __restrict__ rd_bih, const float* __restrict__ rd_bhh,
    float* __restrict__ Weff, float* __restrict__ beff, float* __restrict__ loss)
{
    const int did = blockIdx.y;
    const float* Wih = did ? rd_Wih : pd_Wih;
    const float* Whh = did ? rd_Whh : pd_Whh;
    const float* fcW = did ? rd_fcW : pd_fcW;
    const float* fcb = did ? rd_fcb : pd_fcb;
    const float* bih = did ? rd_bih : pd_bih;
    const float* bhh = did ? rd_bhh : pd_bhh;
    float* We = Weff + (size_t)did * G4 * HSZ;
    float* be = beff + (size_t)did * G4;

    int j = blockIdx.x;
    int tid = threadIdx.x;
    if (blockIdx.x == 0 && did == 0 && tid < 2) loss[tid] = 0.f;

    __shared__ float swih[ISZ];
    __shared__ float red[128];
    for (int i = tid; i < ISZ; i += 128) swih[i] = Wih[j * ISZ + i];
    __syncthreads();
    if (tid < HSZ) {
        float acc = Whh[j * HSZ + tid];
        #pragma unroll 4
        for (int i = 0; i < ISZ; ++i)
            acc = fmaf(swih[i], fcW[i * HSZ + tid], acc);
        We[j * HSZ + tid] = acc;
    }
    float p = 0.f;
    for (int i = tid; i < ISZ; i += 128) p = fmaf(swih[i], fcb[i], p);
    red[tid] = p;
    __syncthreads();
    for (int s = 64; s > 0; s >>= 1) {
        if (tid < s) red[tid] += red[tid + s];
        __syncthreads();
    }
    if (tid == 0) be[j] = bih[j] + bhh[j] + red[0];
}

// ---------------- SIMT NT GEMM for the two small G0 GEMMs ------------------
#define AP 264
#define BP 68
__global__ __launch_bounds__(256) void gemm_g0(
    const float* __restrict__ A,
    const float* __restrict__ B0, const float* __restrict__ B1,
    const float* __restrict__ b10, const float* __restrict__ b11,
    const float* __restrict__ b20, const float* __restrict__ b21,
    float* __restrict__ Cbase, int M, int N, int K)
{
    const int did = blockIdx.z;
    const float* B = did ? B1 : B0;
    const float* bias1 = did ? b11 : b10;
    const float* bias2 = did ? b21 : b20;
    float* C = Cbase + (size_t)did * M * N;

    __shared__ float As[8 * AP];
    __shared__ float Bs[8 * BP];
    const int tid = threadIdx.x;
    const int tx = tid & 7;
    const int ty = tid >> 3;
    const int m0 = blockIdx.y * 256, n0 = blockIdx.x * 64;

    float acc[8][8];
    #pragma unroll
    for (int i = 0; i < 8; ++i)
        #pragma unroll
        for (int j = 0; j < 8; ++j) acc[i][j] = 0.f;

    const int am = m0 + tid;
    const int br = tid >> 2;
    const int bc = (tid & 3) * 2;

    for (int k0 = 0; k0 < K; k0 += 8) {
        #pragma unroll
        for (int j = 0; j < 8; ++j) {
            int k = k0 + j;
            As[j * AP + tid] = (am < M && k < K) ? A[(size_t)am * K + k] : 0.f;
        }
        {
            int n = n0 + br;
            #pragma unroll
            for (int j = 0; j < 2; ++j) {
                int k = k0 + bc + j;
                Bs[(bc + j) * BP + br] = (n < N && k < K) ? B[(size_t)n * K + k] : 0.f;
            }
        }
        __syncthreads();
        #pragma unroll
        for (int kk = 0; kk < 8; ++kk) {
            float4 a0 = *(const float4*)(As + kk * AP + ty * 8);
            float4 a1 = *(const float4*)(As + kk * AP + ty * 8 + 4);
            float4 b0 = *(const float4*)(Bs + kk * BP + tx * 8);
            float4 b1 = *(const float4*)(Bs + kk * BP + tx * 8 + 4);
            float av[8] = {a0.x, a0.y, a0.z, a0.w, a1.x, a1.y, a1.z, a1.w};
            float bv[8] = {b0.x, b0.y, b0.z, b0.w, b1.x, b1.y, b1.z, b1.w};
            #pragma unroll
            for (int i = 0; i < 8; ++i)
                #pragma unroll
                for (int j = 0; j < 8; ++j)
                    acc[i][j] = fmaf(av[i], bv[j], acc[i][j]);
        }
        __syncthreads();
    }

    #pragma unroll
    for (int i = 0; i < 8; ++i) {
        int m = m0 + ty * 8 + i;
        if (m < M) {
            #pragma unroll
            for (int j = 0; j < 8; ++j) {
                int n = n0 + tx * 8 + j;
                if (n < N) C[(size_t)m * N + n] = acc[i][j] + bias1[n] + bias2[n];
            }
        }
    }
}

// ---------------- tensor-core split-bf16 NT GEMM core ----------------------
#define SAP 24

__device__ __forceinline__ void mma16816(float* d, const unsigned* a, const unsigned* b) {
    asm volatile(
        "mma.sync.aligned.m16n8k16.row.col.f32.bf16.bf16.f32 "
        "{%0,%1,%2,%3},{%4,%5,%6,%7},{%8,%9},{%0,%1,%2,%3};"
        : "+f"(d[0]), "+f"(d[1]), "+f"(d[2]), "+f"(d[3])
        : "r"(a[0]), "r"(a[1]), "r"(a[2]), "r"(a[3]), "r"(b[0]), "r"(b[1]));
}

struct Bf16GemmSmem {
    __nv_bfloat16 Ash[2][128 * SAP];
    __nv_bfloat16 Asl[2][128 * SAP];
    __nv_bfloat16 Bsh[2][64 * SAP];
    __nv_bfloat16 Bsl[2][64 * SAP];
    float red[256];
};

__device__ __forceinline__ void bf16_mainloop(
    Bf16GemmSmem* sm, float d[2][4][4],
    const __nv_bfloat16* Ah, const __nv_bfloat16* Al, int lda,
    const __nv_bfloat16* Bh, const __nv_bfloat16* Bl, int ldb,
    int m0, int n0, int M, int N, int Kp)
{
    const int tid = threadIdx.x;
    const int lane = tid & 31;
    const int wid = tid >> 5;
    const int wy = wid & 3;
    const int wx = wid >> 2;
    const int g = lane >> 2, t = lane & 3;

    const int ar = tid >> 1;
    const int ah8 = (tid & 1) * 8;
    const int bs = tid & 127;
    const int brow = bs >> 1;
    const int bh8 = (bs & 1) * 8;
    const int gm = m0 + ar;
    const int gn = n0 + brow;
    const __nv_bfloat16* srcB = (tid < 128) ? Bh : Bl;

    const uint4 zv = make_uint4(0, 0, 0, 0);
    uint4 vh = zv, vl = zv, vb = zv;
    if (gm < M) {
        vh = *(const uint4*)(Ah + (size_t)gm * lda + ah8);
        vl = *(const uint4*)(Al + (size_t)gm * lda + ah8);
    }
    if (gn < N) vb = *(const uint4*)(srcB + (size_t)gn * ldb + bh8);

    const int niter = Kp / 16;
    for (int i = 0; i < niter; ++i) {
        const int cur = i & 1;
        *(uint4*)&sm->Ash[cur][ar * SAP + ah8] = vh;
        *(uint4*)&sm->Asl[cur][ar * SAP + ah8] = vl;
        __nv_bfloat16* dstB = (tid < 128) ? sm->Bsh[cur] : sm->Bsl[cur];
        *(uint4*)&dstB[brow * SAP + bh8] = vb;
        __syncthreads();

        if (i + 1 < niter) {
            int kn = (i + 1) * 16;
            vh = zv; vl = zv; vb = zv;
            if (gm < M) {
                vh = *(const uint4*)(Ah + (size_t)gm * lda + kn + ah8);
                vl = *(const uint4*)(Al + (size_t)gm * lda + kn + ah8);
            }
            if (gn < N) vb = *(const uint4*)(srcB + (size_t)gn * ldb + kn + bh8);
        }

        unsigned bhf[4][2], blf[4][2];
        #pragma unroll
        for (int ni = 0; ni < 4; ++ni) {
            int base = (wx * 32 + ni * 8 + g) * SAP;
            bhf[ni][0] = *(const unsigned*)&sm->Bsh[cur][base + 2 * t];
            bhf[ni][1] = *(const unsigned*)&sm->Bsh[cur][base + 2 * t + 8];
            blf[ni][0] = *(const unsigned*)&sm->Bsl[cur][base + 2 * t];
            blf[ni][1] = *(const unsigned*)&sm->Bsl[cur][base + 2 * t + 8];
        }
        #pragma unroll
        for (int mi = 0; mi < 2; ++mi) {
            int r0 = (wy * 32 + mi * 16 + g) * SAP;
            int r1 = (wy * 32 + mi * 16 + 8 + g) * SAP;
            unsigned ahf[4], alf[4];
            ahf[0] = *(const unsigned*)&sm->Ash[cur][r0 + 2 * t];
            ahf[1] = *(const unsigned*)&sm->Ash[cur][r1 + 2 * t];
            ahf[2] = *(const unsigned*)&sm->Ash[cur][r0 + 2 * t + 8];
            ahf[3] = *(const unsigned*)&sm->Ash[cur][r1 + 2 * t + 8];
            alf[0] = *(const unsigned*)&sm->Asl[cur][r0 + 2 * t];
            alf[1] = *(const unsigned*)&sm->Asl[cur][r1 + 2 * t];
            alf[2] = *(const unsigned*)&sm->Asl[cur][r0 + 2 * t + 8];
            alf[3] = *(const unsigned*)&sm->Asl[cur][r1 + 2 * t + 8];
            #pragma unroll
            for (int ni = 0; ni < 4; ++ni) {
                mma16816(d[mi][ni], ahf, bhf[ni]);
                mma16816(d[mi][ni], ahf, blf[ni]);
                mma16816(d[mi][ni], alf, bhf[ni]);
            }
        }
    }
    __syncthreads();
}

// Phase-A variant: stores C with two biases.
__global__ __launch_bounds__(256) void gemm_bf16_store(
    const __nv_bfloat16* __restrict__ Ah, const __nv_bfloat16* __restrict__ Al, int lda,
    const __nv_bfloat16* __restrict__ Bh, const __nv_bfloat16* __restrict__ Bl, int ldb,
    const float* __restrict__ bias1, const float* __restrict__ bias2,
    float* __restrict__ C, int M, int N, int Kp)
{
    extern __shared__ char smraw[];
    Bf16GemmSmem* sm = (Bf16GemmSmem*)smraw;
    const int tid = threadIdx.x;
    const int lane = tid & 31;
    const int wid = tid >> 5;
    const int wy = wid & 3, wx = wid >> 2;
    const int g = lane >> 2, t = lane & 3;
    const int m0 = blockIdx.y * 128, n0 = blockIdx.x * 64;

    float d[2][4][4];
    #pragma unroll
    for (int mi = 0; mi < 2; ++mi)
        #pragma unroll
        for (int ni = 0; ni < 4; ++ni)
            #pragma unroll
            for (int e = 0; e < 4; ++e) d[mi][ni][e] = 0.f;

    bf16_mainloop(sm, d, Ah, Al, lda, Bh, Bl, ldb, m0, n0, M, N, Kp);

    #pragma unroll
    for (int mi = 0; mi < 2; ++mi) {
        #pragma unroll
        for (int rr = 0; rr < 2; ++rr) {
            int m = m0 + wy * 32 + mi * 16 + rr * 8 + g;
            if (m >= M) continue;
            #pragma unroll
            for (int ni = 0; ni < 4; ++ni) {
                int n = n0 + wx * 32 + ni * 8 + 2 * t;
                if (n + 1 < N) {
                    float v0 = d[mi][ni][rr * 2 + 0] + bias1[n] + bias2[n];
                    float v1 = d[mi][ni][rr * 2 + 1] + bias1[n + 1] + bias2[n + 1];
                    *(float2*)(C + (size_t)m * N + n) = make_float2(v0, v1);
                } else if (n < N) {
                    C[(size_t)m * N + n] = d[mi][ni][rr * 2 + 0] + bias1[n] + bias2[n];
                }
            }
        }
    }
}

// Merged loss variant: blockIdx.z selects decoder stream; fused MSE epilogue.
__global__ __launch_bounds__(256) void gemm_bf16_loss2(
    const __nv_bfloat16* __restrict__ Ahb, const __nv_bfloat16* __restrict__ Alb,
    const __nv_bfloat16* __restrict__ Bhb, const __nv_bfloat16* __restrict__ Blb,
    const float* __restrict__ fcb0, const float* __restrict__ fcb1,
    const float* __restrict__ trg, const float* __restrict__ src,
    float* __restrict__ loss, int M, int N)
{
    extern __shared__ char smraw[];
    Bf16GemmSmem* sm = (Bf16GemmSmem*)smraw;
    const int did = blockIdx.z;
    const __nv_bfloat16* Ah = Ahb + (size_t)did * M * KPL;
    const __nv_bfloat16* Al = Alb + (size_t)did * M * KPL;
    const __nv_bfloat16* Bh = Bhb + (size_t)did * N * KPL;
    const __nv_bfloat16* Bl = Blb + (size_t)did * N * KPL;
    const float* bias = did ? fcb1 : fcb0;
    const float* ref = did ? src : trg;
    float* lossOut = did ? (loss + 0) : (loss + 1);
    const int revT = did ? TSZ : 0;

    const int tid = threadIdx.x;
    const int lane = tid & 31;
    const int wid = tid >> 5;
    const int wy = wid & 3, wx = wid >> 2;
    const int g = lane >> 2, t = lane & 3;
    const int m0 = blockIdx.y * 128, n0 = blockIdx.x * 64;

    float d[2][4][4];
    #pragma unroll
    for (int mi = 0; mi < 2; ++mi)
        #pragma unroll
        for (int ni = 0; ni < 4; ++ni)
            #pragma unroll
            for (int e = 0; e < 4; ++e) d[mi][ni][e] = 0.f;

    bf16_mainloop(sm, d, Ah, Al, KPL, Bh, Bl, KPL, m0, n0, M, N, KPL);

    float ls = 0.f;
    #pragma unroll
    for (int mi = 0; mi < 2; ++mi) {
        #pragma unroll
        for (int rr = 0; rr < 2; ++rr) {
            int m = m0 + wy * 32 + mi * 16 + rr * 8 + g;
            if (m >= M) continue;
            const float* rrow;
            if (revT > 0) {
                int b = m / revT, tt = m - b * revT;
                rrow = ref + ((size_t)b * revT + (revT - 1 - tt)) * N;
            } else {
                rrow = ref + (size_t)m * N;
            }
            #pragma unroll
            for (int ni = 0; ni < 4; ++ni) {
                int n = n0 + wx * 32 + ni * 8 + 2 * t;
                #pragma unroll
                for (int e = 0; e < 2; ++e) {
                    if (n + e < N) {
                        float v = d[mi][ni][rr * 2 + e] + bias[n + e];
                        float diff = v - rrow[n + e];
                        ls = fmaf(diff, diff, ls);
                    }
                }
            }
        }
    }
    sm->red[tid] = ls;
    __syncthreads();
    for (int s = 128; s > 0; s >>= 1) {
        if (tid < s) sm->red[tid] += sm->red[tid + s];
        __syncthreads();
    }
    if (tid == 0) atomicAdd(lossOut, sm->red[0]);
}

// ---------------- LSTM recurrence kernels ----------------------------------
#define NB 7
#define NT_RNN 416
#define RNN_SMEM_F (40000 + 800 + 800 + 3600)

__global__ __launch_bounds__(NT_RNN, 1) void rnn_enc(
    const float* __restrict__ X, const float* __restrict__ Whh,
    float* __restrict__ hf, float* __restrict__ cf)
{
    extern __shared__ float s[];
    float* sW  = s;
    float* sHa = s + 40000;
    float* sHb = sHa + 800;
    float* sG  = sHb + 800;
    const int tid = threadIdx.x;
    const int b0 = blockIdx.x * NB;

    for (int i = tid; i < 10000; i += NT_RNN)
        ((float4*)sW)[i] = ((const float4*)Whh)[i];
    for (int i = tid; i < 800; i += NT_RNN) sHa[i] = 0.f;
    __syncthreads();

    const int i0 = tid, i1 = tid + NT_RNN;
    const int k0c = i0 % 100, b0c = i0 / 100;
    const int k1c = i1 % 100, b1c = i1 / 100;
    const bool v0 = (i0 < NB * 100), v1 = (i1 < NB * 100);
    float c0r = 0.f, c1r = 0.f, h0r = 0.f, h1r = 0.f;

    int bidx[NB];
    #pragma unroll
    for (int b = 0; b < NB; ++b) {
        int bb = b0 + b; if (bb > BSZ - 1) bb = BSZ - 1;
        bidx[b] = bb;
    }

    for (int t = 0; t < TSZ; ++t) {
        const float* hin = (t & 1) ? sHb : sHa;
        float* hout = (t & 1) ? sHa : sHb;
        if (tid < 400) {
            const int j = tid;
            float xr[NB];
            #pragma unroll
            for (int b = 0; b < NB; ++b)
                xr[b] = X[((size_t)bidx[b] * TSZ + t) * G4 + j];
            float acc[NB];
            #pragma unroll
            for (int b = 0; b < NB; ++b) acc[b] = 0.f;
            const float4* wj = (const float4*)(sW + j * 100);
            const float* hp = hin;
            #pragma unroll 5
            for (int k4 = 0; k4 < 25; ++k4) {
                float4 w = wj[k4];
                #pragma unroll
                for (int dd = 0; dd < 4; ++dd) {
                    float wv = (dd == 0) ? w.x : (dd == 1) ? w.y : (dd == 2) ? w.z : w.w;
                    float4 ha = *(const float4*)(hp + (k4 * 4 + dd) * 8);
                    float4 hb = *(const float4*)(hp + (k4 * 4 + dd) * 8 + 4);
                    acc[0] = fmaf(wv, ha.x, acc[0]);
                    acc[1] = fmaf(wv, ha.y, acc[1]);
                    acc[2] = fmaf(wv, ha.z, acc[2]);
                    acc[3] = fmaf(wv, ha.w, acc[3]);
                    acc[4] = fmaf(wv, hb.x, acc[4]);
                    acc[5] = fmaf(wv, hb.y, acc[5]);
                    acc[6] = fmaf(wv, hb.z, acc[6]);
                }
            }
            float* gp = sG + j * 9;
            #pragma unroll
            for (int b = 0; b < NB; ++b) gp[b] = acc[b] + xr[b];
        }
        __syncthreads();
        if (v0) {
            float gi = sigf(sG[(k0c) * 9 + b0c]);
            float gf = sigf(sG[(100 + k0c) * 9 + b0c]);
            float gg = tanhf_fast(sG[(200 + k0c) * 9 + b0c]);
            float go = sigf(sG[(300 + k0c) * 9 + b0c]);
            c0r = fmaf(gf, c0r, gi * gg);
            h0r = go * tanhf_fast(c0r);
            hout[k0c * 8 + b0c] = h0r;
        }
        if (v1) {
            float gi = sigf(sG[(k1c) * 9 + b1c]);
            float gf = sigf(sG[(100 + k1c) * 9 + b1c]);
            float gg = tanhf_fast(sG[(200 + k1c) * 9 + b1c]);
            float go = sigf(sG[(300 + k1c) * 9 + b1c]);
            c1r = fmaf(gf, c1r, gi * gg);
            h1r = go * tanhf_fast(c1r);
            hout[k1c * 8 + b1c] = h1r;
        }
        __syncthreads();
    }

    if (v0 && b0 + b0c < BSZ) {
        hf[(b0 + b0c) * HSZ + k0c] = h0r;
        cf[(b0 + b0c) * HSZ + k0c] = c0r;
    }
    if (v1 && b0 + b1c < BSZ) {
        hf[(b0 + b1c) * HSZ + k1c] = h1r;
        cf[(b0 + b1c) * HSZ + k1c] = c1r;
    }
}

// ---- merged decoders, NB=14 per CTA: grid (72, 2) = 144 CTAs = ONE wave ----
#define NBD 14
#define HP 16    // h buffer pitch (floats)
#define GP 15    // gate buffer pitch
// sW 40000 | sHa 1600 | sHb 1600 | sG 6000 = 49200 floats (196.8 KB)
#define DEC_SMEM_F (40000 + 1600 + 1600 + 6000)

__global__ __launch_bounds__(NT_RNN, 1) void rnn_dec2(
    const float* __restrict__ G0base, const float* __restrict__ Weffbase,
    const float* __restrict__ beffbase,
    const float* __restrict__ h0, const float* __restrict__ c0,
    __nv_bfloat16* __restrict__ hdhb, __nv_bfloat16* __restrict__ hdlb)
{
    extern __shared__ float s[];
    float* sW  = s;
    float* sHa = s + 40000;
    float* sHb = sHa + 1600;
    float* sG  = sHb + 1600;
    const int tid = threadIdx.x;
    const int b0 = blockIdx.x * NBD;
    const int did = blockIdx.y;

    const float* G0   = G0base + (size_t)did * BSZ * G4;
    const float* Weff = Weffbase + (size_t)did * G4 * HSZ;
    const float* beff = beffbase + (size_t)did * G4;
    const size_t hdoff = (size_t)did * BSZ * TSZ * KPL;
    __nv_bfloat16* hdh = hdhb + hdoff;
    __nv_bfloat16* hdl = hdlb + hdoff;

    for (int i = tid; i < 10000; i += NT_RNN)
        ((float4*)sW)[i] = ((const float4*)Weff)[i];
    // zero h pads (b = 14,15) and init below
    for (int i = tid; i < 3200; i += NT_RNN) sHa[i] = 0.f;  // covers sHa+sHb

    const float bq = (tid < 400) ? beff[tid] : 0.f;

    int bidx[NBD];
    #pragma unroll
    for (int b = 0; b < NBD; ++b) {
        int bb = b0 + b; if (bb > BSZ - 1) bb = BSZ - 1;
        bidx[b] = bb;
    }

    // cell-phase ownership: 4 items per thread, item = q*NT_RNN + tid,
    // decode item -> (b = item/100, k = item%100)
    int ck[4], cb[4];
    bool cv[4], cw[4];
    float cc[4];
    const __nv_bfloat16* dummy;
    __nv_bfloat16* outh[4];
    __nv_bfloat16* outl[4];
    #pragma unroll
    for (int q = 0; q < 4; ++q) {
        int item = q * NT_RNN + tid;
        bool v = item < NBD * 100;
        int k = v ? (item % 100) : 0;
        int b = v ? (item / 100) : 0;
        ck[q] = k; cb[q] = b; cv[q] = v;
        cw[q] = v && (b0 + b < BSZ);
        cc[q] = 0.f;
        outh[q] = hdh + ((size_t)(b0 + b) * TSZ) * KPL + k;
        outl[q] = hdl + ((size_t)(b0 + b) * TSZ) * KPL + k;
    }
    (void)dummy;
    __syncthreads();

    // init h (smem) and c (registers)
    #pragma unroll
    for (int q = 0; q < 4; ++q) {
        if (cv[q]) {
            sHa[ck[q] * HP + cb[q]] = h0[bidx[cb[q]] * HSZ + ck[q]];
            cc[q] = c0[bidx[cb[q]] * HSZ + ck[q]];
        }
    }
    __syncthreads();

    for (int t = 0; t < TSZ; ++t) {
        const float* hin = (t & 1) ? sHb : sHa;
        float* hout = (t & 1) ? sHa : sHb;
        if (tid < 400) {
            const int j = tid;
            float* gp = sG + j * GP;
            if (t == 0) {
                #pragma unroll
                for (int b = 0; b < NBD; ++b)
                    gp[b] = G0[(size_t)bidx[b] * G4 + j];
            } else {
                float acc[NBD];
                #pragma unroll
                for (int b = 0; b < NBD; ++b) acc[b] = 0.f;
                const float4* wj = (const float4*)(sW + j * 100);
                const float* hp = hin;
                #pragma unroll 5
                for (int k4 = 0; k4 < 25; ++k4) {
                    float4 w = wj[k4];
                    #pragma unroll
                    for (int dd = 0; dd < 4; ++dd) {
                        float wv = (dd == 0) ? w.x : (dd == 1) ? w.y : (dd == 2) ? w.z : w.w;
                        const float* hr = hp + (k4 * 4 + dd) * HP;
                        float4 h0v = *(const float4*)(hr);
                        float4 h1v = *(const float4*)(hr + 4);
                        float4 h2v = *(const float4*)(hr + 8);
                        float2 h3v = *(const float2*)(hr + 12);
                        acc[0]  = fmaf(wv, h0v.x, acc[0]);
                        acc[1]  = fmaf(wv, h0v.y, acc[1]);
                        acc[2]  = fmaf(wv, h0v.z, acc[2]);
                        acc[3]  = fmaf(wv, h0v.w, acc[3]);
                        acc[4]  = fmaf(wv, h1v.x, acc[4]);
                        acc[5]  = fmaf(wv, h1v.y, acc[5]);
                        acc[6]  = fmaf(wv, h1v.z, acc[6]);
                        acc[7]  = fmaf(wv, h1v.w, acc[7]);
                        acc[8]  = fmaf(wv, h2v.x, acc[8]);
                        acc[9]  = fmaf(wv, h2v.y, acc[9]);
                        acc[10] = fmaf(wv, h2v.z, acc[10]);
                        acc[11] = fmaf(wv, h2v.w, acc[11]);
                        acc[12] = fmaf(wv, h3v.x, acc[12]);
                        acc[13] = fmaf(wv, h3v.y, acc[13]);
                    }
                }
                #pragma unroll
                for (int b = 0; b < NBD; ++b) gp[b] = acc[b] + bq;
            }
        }
        __syncthreads();
        #pragma unroll
        for (int q = 0; q < 4; ++q) {
            if (cv[q]) {
                int k = ck[q], b = cb[q];
                float gi = sigf(sG[(k) * GP + b]);
                float gf = sigf(sG[(100 + k) * GP + b]);
                float gg = tanhf_fast(sG[(200 + k) * GP + b]);
                float go = sigf(sG[(300 + k) * GP + b]);
                float c = fmaf(gf, cc[q], gi * gg);
                cc[q] = c;
                float h = go * tanhf_fast(c);
                hout[k * HP + b] = h;
                if (cw[q]) {
                    __nv_bfloat16 hi = __float2bfloat16(h);
                    outh[q][(size_t)t * KPL] = hi;
                    outl[q][(size_t)t * KPL] = __float2bfloat16(h - __bfloat162float(hi));
                }
            }
        }
        __syncthreads();
    }
}

// ---------------- launch ----------------------------------------------------
extern "C" void kernel_launch(void* const* d_in, const int* in_sizes, int n_in,
                              void* d_out, int out_size)
{
    const float* src     = (const float*)d_in[0];
    const float* trg     = (const float*)d_in[1];
    const float* enc_Wih = (const float*)d_in[2];
    const float* enc_Whh = (const float*)d_in[3];
    const float* enc_bih = (const float*)d_in[4];
    const float* enc_bhh = (const float*)d_in[5];
    const float* pd_Wih  = (const float*)d_in[6];
    const float* pd_Whh  = (const float*)d_in[7];
    const float* pd_bih  = (const float*)d_in[8];
    const float* pd_bhh  = (const float*)d_in[9];
    const float* pd_fcW  = (const float*)d_in[10];
    const float* pd_fcb  = (const float*)d_in[11];
    const float* rd_Wih  = (const float*)d_in[12];
    const float* rd_Whh  = (const float*)d_in[13];
    const float* rd_bih  = (const float*)d_in[14];
    const float* rd_bhh  = (const float*)d_in[15];
    const float* rd_fcW  = (const float*)d_in[16];
    const float* rd_fcb  = (const float*)d_in[17];
    float* out = (float*)d_out;

    float *pX, *pHenc, *pCenc, *pG0, *pWeff, *pBeff, *pLoss;
    __nv_bfloat16 *pSrch, *pSrcl, *pWihh, *pWihl, *pFcwh, *pFcwl, *pHdh, *pHdl;
    cudaGetSymbolAddress((void**)&pX,    g_X);
    cudaGetSymbolAddress((void**)&pHenc, g_henc);
    cudaGetSymbolAddress((void**)&pCenc, g_cenc);
    cudaGetSymbolAddress((void**)&pG0,   g_G0);
    cudaGetSymbolAddress((void**)&pWeff, g_Weff);
    cudaGetSymbolAddress((void**)&pBeff, g_beff);
    cudaGetSymbolAddress((void**)&pLoss, g_loss);
    cudaGetSymbolAddress((void**)&pSrch, g_srch);
    cudaGetSymbolAddress((void**)&pSrcl, g_srcl);
    cudaGetSymbolAddress((void**)&pWihh, g_wihh);
    cudaGetSymbolAddress((void**)&pWihl, g_wihl);
    cudaGetSymbolAddress((void**)&pFcwh, g_fcwh);
    cudaGetSymbolAddress((void**)&pFcwl, g_fcwl);
    cudaGetSymbolAddress((void**)&pHdh,  g_hdh);
    cudaGetSymbolAddress((void**)&pHdl,  g_hdl);

    const int SMEM_RNN = RNN_SMEM_F * 4;
    const int SMEM_DEC = DEC_SMEM_F * 4;
    const int SMEM_GEMM = (int)sizeof(Bf16GemmSmem);
    cudaFuncSetAttribute(rnn_enc,  cudaFuncAttributeMaxDynamicSharedMemorySize, SMEM_RNN);
    cudaFuncSetAttribute(rnn_dec2, cudaFuncAttributeMaxDynamicSharedMemorySize, SMEM_DEC);
    cudaFuncSetAttribute(gemm_bf16_store, cudaFuncAttributeMaxDynamicSharedMemorySize, SMEM_GEMM);
    cudaFuncSetAttribute(gemm_bf16_loss2, cudaFuncAttributeMaxDynamicSharedMemorySize, SMEM_GEMM);

    const int RNN_BLOCKS = (BSZ + NB - 1) / NB;     // 143
    const int DEC_BLOCKS = (BSZ + NBD - 1) / NBD;   // 72
    const int MROWS = BSZ * TSZ;                    // 100000

    // launches 1-3: minimal prep for phase A (so launch #4 = tensor GEMM,
    // the slot ncu has been capturing)
    cvt_split_t<ISZ, KPA><<<(MROWS * (KPA / 4) + 255) / 256, 256>>>(src, pSrch, pSrcl, MROWS);
    cvt_split_t<ISZ, KPA><<<(G4 * (KPA / 4) + 255) / 256, 256>>>(enc_Wih, pWihh, pWihl, G4);
    {
        dim3 grid(G4, 2);
        fold2_kernel<<<grid, 128>>>(pd_Wih, pd_Whh, pd_fcW, pd_fcb, pd_bih, pd_bhh,
                                    rd_Wih, rd_Whh, rd_fcW, rd_fcb, rd_bih, rd_bhh,
                                    pWeff, pBeff, pLoss);
    }

    // launch 4: phase A (tensor cores) — profiled slot
    {
        dim3 grid((G4 + 63) / 64, (MROWS + 127) / 128);
        gemm_bf16_store<<<grid, 256, SMEM_GEMM>>>(pSrch, pSrcl, KPA, pWihh, pWihl, KPA,
                                                  enc_bih, enc_bhh, pX, MROWS, G4, KPA);
    }

    // encoder recurrence
    rnn_enc<<<RNN_BLOCKS, NT_RNN, SMEM_RNN>>>(pX, enc_Whh, pHenc, pCenc);

    // fcW splits (only needed by loss GEMMs)
    cvt_split_t<HSZ, KPL><<<(ISZ * (KPL / 4) + 255) / 256, 256>>>(pd_fcW, pFcwh, pFcwl, ISZ);
    cvt_split_t<HSZ, KPL><<<(ISZ * (KPL / 4) + 255) / 256, 256>>>(rd_fcW, pFcwh + ISZ * KPL,
                                                                  pFcwl + ISZ * KPL, ISZ);

    // decoder step-0 gates (both decoders, one launch)
    {
        dim3 grid((G4 + 63) / 64, (BSZ + 255) / 256, 2);
        gemm_g0<<<grid, 256>>>(pHenc, pd_Whh, rd_Whh, pd_bih, rd_bih,
                               pd_bhh, rd_bhh, pG0, BSZ, G4, HSZ);
    }

    // merged decoders: 144 CTAs = one full wave
    {
        dim3 grid(DEC_BLOCKS, 2);
        rnn_dec2<<<grid, NT_RNN, SMEM_DEC>>>(pG0, pWeff, pBeff, pHenc, pCenc,
                                             pHdh, pHdl);
    }

    // merged losses (tensor cores, fused MSE epilogue)
    {
        dim3 grid((ISZ + 63) / 64, (MROWS + 127) / 128, 2);
        gemm_bf16_loss2<<<grid, 256, SMEM_GEMM>>>(pHdh, pHdl, pFcwh, pFcwl,
                                                  pd_fcb, rd_fcb, trg, src,
                                                  pLoss, MROWS, ISZ);
    }

    finalize_kernel<<<1, 1>>>(pLoss, out, 1.0f / (float)(BSZ * TSZ * ISZ));
}

// round 10
// speedup vs baseline: 2.4416x; 1.0711x over previous
#include <cuda_runtime.h>
#include <cuda_bf16.h>
#include <math.h>

#define BSZ 1000
#define TSZ 100
#define ISZ 264
#define HSZ 100
#define G4  400   // 4*H
#define KPA 272   // padded K for phase A (264 -> 17*16)
#define KPL 112   // padded K for loss GEMMs (100 -> 7*16)

// ---------------- device scratch (static: no allocation allowed) ----------
__device__ float g_X[(size_t)BSZ * TSZ * G4];       // encoder gate inputs fp32
__device__ float g_henc[BSZ * HSZ];
__device__ float g_cenc[BSZ * HSZ];
__device__ float g_G0[2][BSZ * G4];                 // decoder step-0 gates
__device__ float g_Weff[2][G4 * HSZ];
__device__ float g_beff[2][G4];
__device__ float g_loss[2];

// bf16 split operands
__device__ __nv_bfloat16 g_srch[(size_t)BSZ * TSZ * KPA];
__device__ __nv_bfloat16 g_srcl[(size_t)BSZ * TSZ * KPA];
__device__ __nv_bfloat16 g_wihh[G4 * KPA];
__device__ __nv_bfloat16 g_wihl[G4 * KPA];
__device__ __nv_bfloat16 g_fcwh[2][ISZ * KPL];
__device__ __nv_bfloat16 g_fcwl[2][ISZ * KPL];
__device__ __nv_bfloat16 g_hdh[2][(size_t)BSZ * TSZ * KPL];  // decoder h, split
__device__ __nv_bfloat16 g_hdl[2][(size_t)BSZ * TSZ * KPL];

// ---------------- fast activations (ex2/rcp approx: ~2^-22 rel err) --------
__device__ __forceinline__ float ex2f(float x) {
    float r; asm("ex2.approx.f32 %0, %1;" : "=f"(r) : "f"(x)); return r;
}
__device__ __forceinline__ float rcpf(float x) {
    float r; asm("rcp.approx.f32 %0, %1;" : "=f"(r) : "f"(x)); return r;
}
__device__ __forceinline__ float sigf(float x) {
    return rcpf(1.f + ex2f(-1.4426950408889634f * x));
}
__device__ __forceinline__ float tanhf_fast(float x) {
    return fmaf(2.f, rcpf(1.f + ex2f(-2.8853900817779268f * x)), -1.f);
}

// ---------------- small kernels -------------------------------------------
__global__ void finalize_kernel(const float* loss, float* out, float inv) {
    out[0] = loss[0] * inv;
    out[1] = loss[1] * inv;
}

// fp32 -> (bf16 hi, bf16 lo), K padded to Kp, templated, float4 vectorized.
template <int K, int Kp>
__global__ __launch_bounds__(256) void cvt_split_t(
    const float* __restrict__ x, __nv_bfloat16* __restrict__ h,
    __nv_bfloat16* __restrict__ l, int rows)
{
    const int Kp4 = Kp / 4;
    int idx = blockIdx.x * 256 + threadIdx.x;
    if (idx >= rows * Kp4) return;
    int r = idx / Kp4;
    int k4 = (idx - r * Kp4) * 4;
    float4 v;
    if (k4 + 3 < K) {
        v = *(const float4*)(x + (size_t)r * K + k4);
    } else {
        float tmp[4] = {0.f, 0.f, 0.f, 0.f};
        #pragma unroll
        for (int e = 0; e < 4; ++e)
            if (k4 + e < K) tmp[e] = x[(size_t)r * K + k4 + e];
        v = make_float4(tmp[0], tmp[1], tmp[2], tmp[3]);
    }
    float vv[4] = {v.x, v.y, v.z, v.w};
    __nv_bfloat16 hh[4], ll[4];
    #pragma unroll
    for (int e = 0; e < 4; ++e) {
        hh[e] = __float2bfloat16(vv[e]);
        ll[e] = __float2bfloat16(vv[e] - __bfloat162float(hh[e]));
    }
    *(uint2*)(h + (size_t)idx * 4) = *(const uint2*)hh;
    *(uint2*)(l + (size_t)idx * 4) = *(const uint2*)ll;
}

// Both decoder folds in one launch: blockIdx.y selects decoder.
__global__ __launch_bounds__(128) void fold2_kernel(
    const float* __restrict__ pd_Wih, const float* __restrict__ pd_Whh,
    const float* __restrict__ pd_fcW, const float* __restrict__ pd_fcb,
    const float* __restrict__ pd_bih, const float* __restrict__ pd_bhh,
    const float* __restrict__ rd_Wih, const float* __restrict__ rd_Whh,
    const float* __restrict__ rd_fcW, const float* __restrict__ rd_fcb,
    const float* __restrict__ rd_bih, const float* __restrict__ rd_bhh,
    float* __restrict__ Weff, float* __restrict__ beff, float* __restrict__ loss)
{
    const int did = blockIdx.y;
    const float* Wih = did ? rd_Wih : pd_Wih;
    const float* Whh = did ? rd_Whh : pd_Whh;
    const float* fcW = did ? rd_fcW : pd_fcW;
    const float* fcb = did ? rd_fcb : pd_fcb;
    const float* bih = did ? rd_bih : pd_bih;
    const float* bhh = did ? rd_bhh : pd_bhh;
    float* We = Weff + (size_t)did * G4 * HSZ;
    float* be = beff + (size_t)did * G4;

    int j = blockIdx.x;
    int tid = threadIdx.x;
    if (blockIdx.x == 0 && did == 0 && tid < 2) loss[tid] = 0.f;

    __shared__ float swih[ISZ];
    __shared__ float red[128];
    for (int i = tid; i < ISZ; i += 128) swih[i] = Wih[j * ISZ + i];
    __syncthreads();
    if (tid < HSZ) {
        float acc = Whh[j * HSZ + tid];
        #pragma unroll 4
        for (int i = 0; i < ISZ; ++i)
            acc = fmaf(swih[i], fcW[i * HSZ + tid], acc);
        We[j * HSZ + tid] = acc;
    }
    float p = 0.f;
    for (int i = tid; i < ISZ; i += 128) p = fmaf(swih[i], fcb[i], p);
    red[tid] = p;
    __syncthreads();
    for (int s = 64; s > 0; s >>= 1) {
        if (tid < s) red[tid] += red[tid + s];
        __syncthreads();
    }
    if (tid == 0) be[j] = bih[j] + bhh[j] + red[0];
}

// ---------------- SIMT NT GEMM for the two small G0 GEMMs ------------------
#define AP 264
#define BP 68
__global__ __launch_bounds__(256) void gemm_g0(
    const float* __restrict__ A,
    const float* __restrict__ B0, const float* __restrict__ B1,
    const float* __restrict__ b10, const float* __restrict__ b11,
    const float* __restrict__ b20, const float* __restrict__ b21,
    float* __restrict__ Cbase, int M, int N, int K)
{
    const int did = blockIdx.z;
    const float* B = did ? B1 : B0;
    const float* bias1 = did ? b11 : b10;
    const float* bias2 = did ? b21 : b20;
    float* C = Cbase + (size_t)did * M * N;

    __shared__ float As[8 * AP];
    __shared__ float Bs[8 * BP];
    const int tid = threadIdx.x;
    const int tx = tid & 7;
    const int ty = tid >> 3;
    const int m0 = blockIdx.y * 256, n0 = blockIdx.x * 64;

    float acc[8][8];
    #pragma unroll
    for (int i = 0; i < 8; ++i)
        #pragma unroll
        for (int j = 0; j < 8; ++j) acc[i][j] = 0.f;

    const int am = m0 + tid;
    const int br = tid >> 2;
    const int bc = (tid & 3) * 2;

    for (int k0 = 0; k0 < K; k0 += 8) {
        #pragma unroll
        for (int j = 0; j < 8; ++j) {
            int k = k0 + j;
            As[j * AP + tid] = (am < M && k < K) ? A[(size_t)am * K + k] : 0.f;
        }
        {
            int n = n0 + br;
            #pragma unroll
            for (int j = 0; j < 2; ++j) {
                int k = k0 + bc + j;
                Bs[(bc + j) * BP + br] = (n < N && k < K) ? B[(size_t)n * K + k] : 0.f;
            }
        }
        __syncthreads();
        #pragma unroll
        for (int kk = 0; kk < 8; ++kk) {
            float4 a0 = *(const float4*)(As + kk * AP + ty * 8);
            float4 a1 = *(const float4*)(As + kk * AP + ty * 8 + 4);
            float4 b0 = *(const float4*)(Bs + kk * BP + tx * 8);
            float4 b1 = *(const float4*)(Bs + kk * BP + tx * 8 + 4);
            float av[8] = {a0.x, a0.y, a0.z, a0.w, a1.x, a1.y, a1.z, a1.w};
            float bv[8] = {b0.x, b0.y, b0.z, b0.w, b1.x, b1.y, b1.z, b1.w};
            #pragma unroll
            for (int i = 0; i < 8; ++i)
                #pragma unroll
                for (int j = 0; j < 8; ++j)
                    acc[i][j] = fmaf(av[i], bv[j], acc[i][j]);
        }
        __syncthreads();
    }

    #pragma unroll
    for (int i = 0; i < 8; ++i) {
        int m = m0 + ty * 8 + i;
        if (m < M) {
            #pragma unroll
            for (int j = 0; j < 8; ++j) {
                int n = n0 + tx * 8 + j;
                if (n < N) C[(size_t)m * N + n] = acc[i][j] + bias1[n] + bias2[n];
            }
        }
    }
}

// ---------------- tensor-core split-bf16 NT GEMM core ----------------------
#define SAP 24

__device__ __forceinline__ void mma16816(float* d, const unsigned* a, const unsigned* b) {
    asm volatile(
        "mma.sync.aligned.m16n8k16.row.col.f32.bf16.bf16.f32 "
        "{%0,%1,%2,%3},{%4,%5,%6,%7},{%8,%9},{%0,%1,%2,%3};"
        : "+f"(d[0]), "+f"(d[1]), "+f"(d[2]), "+f"(d[3])
        : "r"(a[0]), "r"(a[1]), "r"(a[2]), "r"(a[3]), "r"(b[0]), "r"(b[1]));
}

__device__ __forceinline__ void ldsm_x4(unsigned* r, unsigned addr) {
    asm volatile(
        "ldmatrix.sync.aligned.m8n8.x4.shared.b16 {%0,%1,%2,%3}, [%4];"
        : "=r"(r[0]), "=r"(r[1]), "=r"(r[2]), "=r"(r[3]) : "r"(addr));
}

struct Bf16GemmSmem {
    __nv_bfloat16 Ash[2][128 * SAP];
    __nv_bfloat16 Asl[2][128 * SAP];
    __nv_bfloat16 Bsh[2][64 * SAP];
    __nv_bfloat16 Bsl[2][64 * SAP];
    float red[256];
};

__device__ __forceinline__ void bf16_mainloop(
    Bf16GemmSmem* sm, float d[2][4][4],
    const __nv_bfloat16* Ah, const __nv_bfloat16* Al, int lda,
    const __nv_bfloat16* Bh, const __nv_bfloat16* Bl, int ldb,
    int m0, int n0, int M, int N, int Kp)
{
    const int tid = threadIdx.x;
    const int lane = tid & 31;
    const int wid = tid >> 5;
    const int wy = wid & 3;
    const int wx = wid >> 2;

    const int ar = tid >> 1;
    const int ah8 = (tid & 1) * 8;
    const int bs = tid & 127;
    const int brow = bs >> 1;
    const int bh8 = (bs & 1) * 8;
    const int gm = m0 + ar;
    const int gn = n0 + brow;
    const __nv_bfloat16* srcB = (tid < 128) ? Bh : Bl;

    // ldmatrix lane-address offsets (bytes, within a buffer)
    // A x4: matrices (m0-7,k0),(m8-15,k0),(m0-7,k8),(m8-15,k8) -> a0..a3
    const unsigned aoff =
        ((unsigned)((wy * 32 + ((lane >> 3) & 1) * 8 + (lane & 7)) * SAP
                    + (lane >> 4) * 8)) * 2u;
    // B x4: matrices (n0-7,k0),(n0-7,k8),(n8-15,k0),(n8-15,k8) -> b[ni][0],b[ni][1],b[ni+1][0],b[ni+1][1]
    const unsigned boff =
        ((unsigned)((wx * 32 + ((lane >> 4) & 1) * 8 + (lane & 7)) * SAP
                    + ((lane >> 3) & 1) * 8)) * 2u;

    const unsigned ashb = (unsigned)__cvta_generic_to_shared(sm->Ash[0]);
    const unsigned aslb = (unsigned)__cvta_generic_to_shared(sm->Asl[0]);
    const unsigned bshb = (unsigned)__cvta_generic_to_shared(sm->Bsh[0]);
    const unsigned bslb = (unsigned)__cvta_generic_to_shared(sm->Bsl[0]);
    const unsigned abuf = 128 * SAP * 2;
    const unsigned bbuf = 64 * SAP * 2;
    const unsigned ni2step = 16 * SAP * 2;   // two ni strips (16 n rows)
    const unsigned mistep = 16 * SAP * 2;    // one mi strip (16 m rows)

    const uint4 zv = make_uint4(0, 0, 0, 0);
    uint4 vh = zv, vl = zv, vb = zv;
    if (gm < M) {
        vh = *(const uint4*)(Ah + (size_t)gm * lda + ah8);
        vl = *(const uint4*)(Al + (size_t)gm * lda + ah8);
    }
    if (gn < N) vb = *(const uint4*)(srcB + (size_t)gn * ldb + bh8);

    const int niter = Kp / 16;
    for (int i = 0; i < niter; ++i) {
        const unsigned cur = (unsigned)(i & 1);
        *(uint4*)&sm->Ash[cur][ar * SAP + ah8] = vh;
        *(uint4*)&sm->Asl[cur][ar * SAP + ah8] = vl;
        __nv_bfloat16* dstB = (tid < 128) ? sm->Bsh[cur] : sm->Bsl[cur];
        *(uint4*)&dstB[brow * SAP + bh8] = vb;
        __syncthreads();

        if (i + 1 < niter) {
            int kn = (i + 1) * 16;
            vh = zv; vl = zv; vb = zv;
            if (gm < M) {
                vh = *(const uint4*)(Ah + (size_t)gm * lda + kn + ah8);
                vl = *(const uint4*)(Al + (size_t)gm * lda + kn + ah8);
            }
            if (gn < N) vb = *(const uint4*)(srcB + (size_t)gn * ldb + kn + bh8);
        }

        // B fragments: 2 LDSM.x4 per hi/lo cover all 4 ni strips
        unsigned bhf[4][2], blf[4][2];
        {
            unsigned r[4];
            unsigned b0 = bshb + cur * bbuf + boff;
            ldsm_x4(r, b0);
            bhf[0][0] = r[0]; bhf[0][1] = r[1]; bhf[1][0] = r[2]; bhf[1][1] = r[3];
            ldsm_x4(r, b0 + ni2step);
            bhf[2][0] = r[0]; bhf[2][1] = r[1]; bhf[3][0] = r[2]; bhf[3][1] = r[3];
            unsigned b1 = bslb + cur * bbuf + boff;
            ldsm_x4(r, b1);
            blf[0][0] = r[0]; blf[0][1] = r[1]; blf[1][0] = r[2]; blf[1][1] = r[3];
            ldsm_x4(r, b1 + ni2step);
            blf[2][0] = r[0]; blf[2][1] = r[1]; blf[3][0] = r[2]; blf[3][1] = r[3];
        }
        #pragma unroll
        for (int mi = 0; mi < 2; ++mi) {
            unsigned ahf[4], alf[4];
            ldsm_x4(ahf, ashb + cur * abuf + aoff + mi * mistep);
            ldsm_x4(alf, aslb + cur * abuf + aoff + mi * mistep);
            #pragma unroll
            for (int ni = 0; ni < 4; ++ni) {
                mma16816(d[mi][ni], ahf, bhf[ni]);
                mma16816(d[mi][ni], ahf, blf[ni]);
                mma16816(d[mi][ni], alf, bhf[ni]);
            }
        }
    }
    __syncthreads();
}

// Phase-A variant: stores C with two biases.
__global__ __launch_bounds__(256, 3) void gemm_bf16_store(
    const __nv_bfloat16* __restrict__ Ah, const __nv_bfloat16* __restrict__ Al, int lda,
    const __nv_bfloat16* __restrict__ Bh, const __nv_bfloat16* __restrict__ Bl, int ldb,
    const float* __restrict__ bias1, const float* __restrict__ bias2,
    float* __restrict__ C, int M, int N, int Kp)
{
    extern __shared__ char smraw[];
    Bf16GemmSmem* sm = (Bf16GemmSmem*)smraw;
    const int tid = threadIdx.x;
    const int lane = tid & 31;
    const int wid = tid >> 5;
    const int wy = wid & 3, wx = wid >> 2;
    const int g = lane >> 2, t = lane & 3;
    const int m0 = blockIdx.y * 128, n0 = blockIdx.x * 64;

    float d[2][4][4];
    #pragma unroll
    for (int mi = 0; mi < 2; ++mi)
        #pragma unroll
        for (int ni = 0; ni < 4; ++ni)
            #pragma unroll
            for (int e = 0; e < 4; ++e) d[mi][ni][e] = 0.f;

    bf16_mainloop(sm, d, Ah, Al, lda, Bh, Bl, ldb, m0, n0, M, N, Kp);

    #pragma unroll
    for (int mi = 0; mi < 2; ++mi) {
        #pragma unroll
        for (int rr = 0; rr < 2; ++rr) {
            int m = m0 + wy * 32 + mi * 16 + rr * 8 + g;
            if (m >= M) continue;
            #pragma unroll
            for (int ni = 0; ni < 4; ++ni) {
                int n = n0 + wx * 32 + ni * 8 + 2 * t;
                if (n + 1 < N) {
                    float v0 = d[mi][ni][rr * 2 + 0] + bias1[n] + bias2[n];
                    float v1 = d[mi][ni][rr * 2 + 1] + bias1[n + 1] + bias2[n + 1];
                    *(float2*)(C + (size_t)m * N + n) = make_float2(v0, v1);
                } else if (n < N) {
                    C[(size_t)m * N + n] = d[mi][ni][rr * 2 + 0] + bias1[n] + bias2[n];
                }
            }
        }
    }
}

// Merged loss variant: blockIdx.z selects decoder stream; fused MSE epilogue.
__global__ __launch_bounds__(256, 3) void gemm_bf16_loss2(
    const __nv_bfloat16* __restrict__ Ahb, const __nv_bfloat16* __restrict__ Alb,
    const __nv_bfloat16* __restrict__ Bhb, const __nv_bfloat16* __restrict__ Blb,
    const float* __restrict__ fcb0, const float* __restrict__ fcb1,
    const float* __restrict__ trg, const float* __restrict__ src,
    float* __restrict__ loss, int M, int N)
{
    extern __shared__ char smraw[];
    Bf16GemmSmem* sm = (Bf16GemmSmem*)smraw;
    const int did = blockIdx.z;
    const __nv_bfloat16* Ah = Ahb + (size_t)did * M * KPL;
    const __nv_bfloat16* Al = Alb + (size_t)did * M * KPL;
    const __nv_bfloat16* Bh = Bhb + (size_t)did * N * KPL;
    const __nv_bfloat16* Bl = Blb + (size_t)did * N * KPL;
    const float* bias = did ? fcb1 : fcb0;
    const float* ref = did ? src : trg;
    float* lossOut = did ? (loss + 0) : (loss + 1);
    const int revT = did ? TSZ : 0;

    const int tid = threadIdx.x;
    const int lane = tid & 31;
    const int wid = tid >> 5;
    const int wy = wid & 3, wx = wid >> 2;
    const int g = lane >> 2, t = lane & 3;
    const int m0 = blockIdx.y * 128, n0 = blockIdx.x * 64;

    float d[2][4][4];
    #pragma unroll
    for (int mi = 0; mi < 2; ++mi)
        #pragma unroll
        for (int ni = 0; ni < 4; ++ni)
            #pragma unroll
            for (int e = 0; e < 4; ++e) d[mi][ni][e] = 0.f;

    bf16_mainloop(sm, d, Ah, Al, KPL, Bh, Bl, KPL, m0, n0, M, N, KPL);

    float ls = 0.f;
    #pragma unroll
    for (int mi = 0; mi < 2; ++mi) {
        #pragma unroll
        for (int rr = 0; rr < 2; ++rr) {
            int m = m0 + wy * 32 + mi * 16 + rr * 8 + g;
            if (m >= M) continue;
            const float* rrow;
            if (revT > 0) {
                int b = m / revT, tt = m - b * revT;
                rrow = ref + ((size_t)b * revT + (revT - 1 - tt)) * N;
            } else {
                rrow = ref + (size_t)m * N;
            }
            #pragma unroll
            for (int ni = 0; ni < 4; ++ni) {
                int n = n0 + wx * 32 + ni * 8 + 2 * t;
                #pragma unroll
                for (int e = 0; e < 2; ++e) {
                    if (n + e < N) {
                        float v = d[mi][ni][rr * 2 + e] + bias[n + e];
                        float diff = v - rrow[n + e];
                        ls = fmaf(diff, diff, ls);
                    }
                }
            }
        }
    }
    sm->red[tid] = ls;
    __syncthreads();
    for (int s = 128; s > 0; s >>= 1) {
        if (tid < s) sm->red[tid] += sm->red[tid + s];
        __syncthreads();
    }
    if (tid == 0) atomicAdd(lossOut, sm->red[0]);
}

// ---------------- LSTM recurrence kernels ----------------------------------
#define NB 7
#define NT_RNN 416
#define RNN_SMEM_F (40000 + 800 + 800 + 3600)

__global__ __launch_bounds__(NT_RNN, 1) void rnn_enc(
    const float* __restrict__ X, const float* __restrict__ Whh,
    float* __restrict__ hf, float* __restrict__ cf)
{
    extern __shared__ float s[];
    float* sW  = s;
    float* sHa = s + 40000;
    float* sHb = sHa + 800;
    float* sG  = sHb + 800;
    const int tid = threadIdx.x;
    const int b0 = blockIdx.x * NB;

    for (int i = tid; i < 10000; i += NT_RNN)
        ((float4*)sW)[i] = ((const float4*)Whh)[i];
    for (int i = tid; i < 800; i += NT_RNN) sHa[i] = 0.f;
    __syncthreads();

    const int i0 = tid, i1 = tid + NT_RNN;
    const int k0c = i0 % 100, b0c = i0 / 100;
    const int k1c = i1 % 100, b1c = i1 / 100;
    const bool v0 = (i0 < NB * 100), v1 = (i1 < NB * 100);
    float c0r = 0.f, c1r = 0.f, h0r = 0.f, h1r = 0.f;

    int bidx[NB];
    #pragma unroll
    for (int b = 0; b < NB; ++b) {
        int bb = b0 + b; if (bb > BSZ - 1) bb = BSZ - 1;
        bidx[b] = bb;
    }

    for (int t = 0; t < TSZ; ++t) {
        const float* hin = (t & 1) ? sHb : sHa;
        float* hout = (t & 1) ? sHa : sHb;
        if (tid < 400) {
            const int j = tid;
            float xr[NB];
            #pragma unroll
            for (int b = 0; b < NB; ++b)
                xr[b] = X[((size_t)bidx[b] * TSZ + t) * G4 + j];
            float acc[NB];
            #pragma unroll
            for (int b = 0; b < NB; ++b) acc[b] = 0.f;
            const float4* wj = (const float4*)(sW + j * 100);
            const float* hp = hin;
            #pragma unroll 5
            for (int k4 = 0; k4 < 25; ++k4) {
                float4 w = wj[k4];
                #pragma unroll
                for (int dd = 0; dd < 4; ++dd) {
                    float wv = (dd == 0) ? w.x : (dd == 1) ? w.y : (dd == 2) ? w.z : w.w;
                    float4 ha = *(const float4*)(hp + (k4 * 4 + dd) * 8);
                    float4 hb = *(const float4*)(hp + (k4 * 4 + dd) * 8 + 4);
                    acc[0] = fmaf(wv, ha.x, acc[0]);
                    acc[1] = fmaf(wv, ha.y, acc[1]);
                    acc[2] = fmaf(wv, ha.z, acc[2]);
                    acc[3] = fmaf(wv, ha.w, acc[3]);
                    acc[4] = fmaf(wv, hb.x, acc[4]);
                    acc[5] = fmaf(wv, hb.y, acc[5]);
                    acc[6] = fmaf(wv, hb.z, acc[6]);
                }
            }
            float* gp = sG + j * 9;
            #pragma unroll
            for (int b = 0; b < NB; ++b) gp[b] = acc[b] + xr[b];
        }
        __syncthreads();
        if (v0) {
            float gi = sigf(sG[(k0c) * 9 + b0c]);
            float gf = sigf(sG[(100 + k0c) * 9 + b0c]);
            float gg = tanhf_fast(sG[(200 + k0c) * 9 + b0c]);
            float go = sigf(sG[(300 + k0c) * 9 + b0c]);
            c0r = fmaf(gf, c0r, gi * gg);
            h0r = go * tanhf_fast(c0r);
            hout[k0c * 8 + b0c] = h0r;
        }
        if (v1) {
            float gi = sigf(sG[(k1c) * 9 + b1c]);
            float gf = sigf(sG[(100 + k1c) * 9 + b1c]);
            float gg = tanhf_fast(sG[(200 + k1c) * 9 + b1c]);
            float go = sigf(sG[(300 + k1c) * 9 + b1c]);
            c1r = fmaf(gf, c1r, gi * gg);
            h1r = go * tanhf_fast(c1r);
            hout[k1c * 8 + b1c] = h1r;
        }
        __syncthreads();
    }

    if (v0 && b0 + b0c < BSZ) {
        hf[(b0 + b0c) * HSZ + k0c] = h0r;
        cf[(b0 + b0c) * HSZ + k0c] = c0r;
    }
    if (v1 && b0 + b1c < BSZ) {
        hf[(b0 + b1c) * HSZ + k1c] = h1r;
        cf[(b0 + b1c) * HSZ + k1c] = c1r;
    }
}

// ---- merged decoders, NB=14 per CTA: grid (72, 2) = 144 CTAs = ONE wave ----
#define NBD 14
#define HP 16
#define GP 15
#define DEC_SMEM_F (40000 + 1600 + 1600 + 6000)

__global__ __launch_bounds__(NT_RNN, 1) void rnn_dec2(
    const float* __restrict__ G0base, const float* __restrict__ Weffbase,
    const float* __restrict__ beffbase,
    const float* __restrict__ h0, const float* __restrict__ c0,
    __nv_bfloat16* __restrict__ hdhb, __nv_bfloat16* __restrict__ hdlb)
{
    extern __shared__ float s[];
    float* sW  = s;
    float* sHa = s + 40000;
    float* sHb = sHa + 1600;
    float* sG  = sHb + 1600;
    const int tid = threadIdx.x;
    const int b0 = blockIdx.x * NBD;
    const int did = blockIdx.y;

    const float* G0   = G0base + (size_t)did * BSZ * G4;
    const float* Weff = Weffbase + (size_t)did * G4 * HSZ;
    const float* beff = beffbase + (size_t)did * G4;
    const size_t hdoff = (size_t)did * BSZ * TSZ * KPL;
    __nv_bfloat16* hdh = hdhb + hdoff;
    __nv_bfloat16* hdl = hdlb + hdoff;

    for (int i = tid; i < 10000; i += NT_RNN)
        ((float4*)sW)[i] = ((const float4*)Weff)[i];
    for (int i = tid; i < 3200; i += NT_RNN) sHa[i] = 0.f;

    const float bq = (tid < 400) ? beff[tid] : 0.f;

    int bidx[NBD];
    #pragma unroll
    for (int b = 0; b < NBD; ++b) {
        int bb = b0 + b; if (bb > BSZ - 1) bb = BSZ - 1;
        bidx[b] = bb;
    }

    int ck[4], cb[4];
    bool cv[4], cw[4];
    float cc[4];
    __nv_bfloat16* outh[4];
    __nv_bfloat16* outl[4];
    #pragma unroll
    for (int q = 0; q < 4; ++q) {
        int item = q * NT_RNN + tid;
        bool v = item < NBD * 100;
        int k = v ? (item % 100) : 0;
        int b = v ? (item / 100) : 0;
        ck[q] = k; cb[q] = b; cv[q] = v;
        cw[q] = v && (b0 + b < BSZ);
        cc[q] = 0.f;
        outh[q] = hdh + ((size_t)(b0 + b) * TSZ) * KPL + k;
        outl[q] = hdl + ((size_t)(b0 + b) * TSZ) * KPL + k;
    }
    __syncthreads();

    #pragma unroll
    for (int q = 0; q < 4; ++q) {
        if (cv[q]) {
            sHa[ck[q] * HP + cb[q]] = h0[bidx[cb[q]] * HSZ + ck[q]];
            cc[q] = c0[bidx[cb[q]] * HSZ + ck[q]];
        }
    }
    __syncthreads();

    for (int t = 0; t < TSZ; ++t) {
        const float* hin = (t & 1) ? sHb : sHa;
        float* hout = (t & 1) ? sHa : sHb;
        if (tid < 400) {
            const int j = tid;
            float* gp = sG + j * GP;
            if (t == 0) {
                #pragma unroll
                for (int b = 0; b < NBD; ++b)
                    gp[b] = G0[(size_t)bidx[b] * G4 + j];
            } else {
                float acc[NBD];
                #pragma unroll
                for (int b = 0; b < NBD; ++b) acc[b] = 0.f;
                const float4* wj = (const float4*)(sW + j * 100);
                const float* hp = hin;
                #pragma unroll 5
                for (int k4 = 0; k4 < 25; ++k4) {
                    float4 w = wj[k4];
                    #pragma unroll
                    for (int dd = 0; dd < 4; ++dd) {
                        float wv = (dd == 0) ? w.x : (dd == 1) ? w.y : (dd == 2) ? w.z : w.w;
                        const float* hr = hp + (k4 * 4 + dd) * HP;
                        float4 h0v = *(const float4*)(hr);
                        float4 h1v = *(const float4*)(hr + 4);
                        float4 h2v = *(const float4*)(hr + 8);
                        float2 h3v = *(const float2*)(hr + 12);
                        acc[0]  = fmaf(wv, h0v.x, acc[0]);
                        acc[1]  = fmaf(wv, h0v.y, acc[1]);
                        acc[2]  = fmaf(wv, h0v.z, acc[2]);
                        acc[3]  = fmaf(wv, h0v.w, acc[3]);
                        acc[4]  = fmaf(wv, h1v.x, acc[4]);
                        acc[5]  = fmaf(wv, h1v.y, acc[5]);
                        acc[6]  = fmaf(wv, h1v.z, acc[6]);
                        acc[7]  = fmaf(wv, h1v.w, acc[7]);
                        acc[8]  = fmaf(wv, h2v.x, acc[8]);
                        acc[9]  = fmaf(wv, h2v.y, acc[9]);
                        acc[10] = fmaf(wv, h2v.z, acc[10]);
                        acc[11] = fmaf(wv, h2v.w, acc[11]);
                        acc[12] = fmaf(wv, h3v.x, acc[12]);
                        acc[13] = fmaf(wv, h3v.y, acc[13]);
                    }
                }
                #pragma unroll
                for (int b = 0; b < NBD; ++b) gp[b] = acc[b] + bq;
            }
        }
        __syncthreads();
        #pragma unroll
        for (int q = 0; q < 4; ++q) {
            if (cv[q]) {
                int k = ck[q], b = cb[q];
                float gi = sigf(sG[(k) * GP + b]);
                float gf = sigf(sG[(100 + k) * GP + b]);
                float gg = tanhf_fast(sG[(200 + k) * GP + b]);
                float go = sigf(sG[(300 + k) * GP + b]);
                float c = fmaf(gf, cc[q], gi * gg);
                cc[q] = c;
                float h = go * tanhf_fast(c);
                hout[k * HP + b] = h;
                if (cw[q]) {
                    __nv_bfloat16 hi = __float2bfloat16(h);
                    outh[q][(size_t)t * KPL] = hi;
                    outl[q][(size_t)t * KPL] = __float2bfloat16(h - __bfloat162float(hi));
                }
            }
        }
        __syncthreads();
    }
}

// ---------------- launch ----------------------------------------------------
extern "C" void kernel_launch(void* const* d_in, const int* in_sizes, int n_in,
                              void* d_out, int out_size)
{
    const float* src     = (const float*)d_in[0];
    const float* trg     = (const float*)d_in[1];
    const float* enc_Wih = (const float*)d_in[2];
    const float* enc_Whh = (const float*)d_in[3];
    const float* enc_bih = (const float*)d_in[4];
    const float* enc_bhh = (const float*)d_in[5];
    const float* pd_Wih  = (const float*)d_in[6];
    const float* pd_Whh  = (const float*)d_in[7];
    const float* pd_bih  = (const float*)d_in[8];
    const float* pd_bhh  = (const float*)d_in[9];
    const float* pd_fcW  = (const float*)d_in[10];
    const float* pd_fcb  = (const float*)d_in[11];
    const float* rd_Wih  = (const float*)d_in[12];
    const float* rd_Whh  = (const float*)d_in[13];
    const float* rd_bih  = (const float*)d_in[14];
    const float* rd_bhh  = (const float*)d_in[15];
    const float* rd_fcW  = (const float*)d_in[16];
    const float* rd_fcb  = (const float*)d_in[17];
    float* out = (float*)d_out;

    float *pX, *pHenc, *pCenc, *pG0, *pWeff, *pBeff, *pLoss;
    __nv_bfloat16 *pSrch, *pSrcl, *pWihh, *pWihl, *pFcwh, *pFcwl, *pHdh, *pHdl;
    cudaGetSymbolAddress((void**)&pX,    g_X);
    cudaGetSymbolAddress((void**)&pHenc, g_henc);
    cudaGetSymbolAddress((void**)&pCenc, g_cenc);
    cudaGetSymbolAddress((void**)&pG0,   g_G0);
    cudaGetSymbolAddress((void**)&pWeff, g_Weff);
    cudaGetSymbolAddress((void**)&pBeff, g_beff);
    cudaGetSymbolAddress((void**)&pLoss, g_loss);
    cudaGetSymbolAddress((void**)&pSrch, g_srch);
    cudaGetSymbolAddress((void**)&pSrcl, g_srcl);
    cudaGetSymbolAddress((void**)&pWihh, g_wihh);
    cudaGetSymbolAddress((void**)&pWihl, g_wihl);
    cudaGetSymbolAddress((void**)&pFcwh, g_fcwh);
    cudaGetSymbolAddress((void**)&pFcwl, g_fcwl);
    cudaGetSymbolAddress((void**)&pHdh,  g_hdh);
    cudaGetSymbolAddress((void**)&pHdl,  g_hdl);

    const int SMEM_RNN = RNN_SMEM_F * 4;
    const int SMEM_DEC = DEC_SMEM_F * 4;
    const int SMEM_GEMM = (int)sizeof(Bf16GemmSmem);
    cudaFuncSetAttribute(rnn_enc,  cudaFuncAttributeMaxDynamicSharedMemorySize, SMEM_RNN);
    cudaFuncSetAttribute(rnn_dec2, cudaFuncAttributeMaxDynamicSharedMemorySize, SMEM_DEC);
    cudaFuncSetAttribute(gemm_bf16_store, cudaFuncAttributeMaxDynamicSharedMemorySize, SMEM_GEMM);
    cudaFuncSetAttribute(gemm_bf16_loss2, cudaFuncAttributeMaxDynamicSharedMemorySize, SMEM_GEMM);

    const int RNN_BLOCKS = (BSZ + NB - 1) / NB;     // 143
    const int DEC_BLOCKS = (BSZ + NBD - 1) / NBD;   // 72
    const int MROWS = BSZ * TSZ;                    // 100000

    // launches 1-3: prep (launch #4 = phase-A tensor GEMM, the profiled slot)
    cvt_split_t<ISZ, KPA><<<(MROWS * (KPA / 4) + 255) / 256, 256>>>(src, pSrch, pSrcl, MROWS);
    cvt_split_t<ISZ, KPA><<<(G4 * (KPA / 4) + 255) / 256, 256>>>(enc_Wih, pWihh, pWihl, G4);
    {
        dim3 grid(G4, 2);
        fold2_kernel<<<grid, 128>>>(pd_Wih, pd_Whh, pd_fcW, pd_fcb, pd_bih, pd_bhh,
                                    rd_Wih, rd_Whh, rd_fcW, rd_fcb, rd_bih, rd_bhh,
                                    pWeff, pBeff, pLoss);
    }

    // launch 4: phase A (tensor cores)
    {
        dim3 grid((G4 + 63) / 64, (MROWS + 127) / 128);
        gemm_bf16_store<<<grid, 256, SMEM_GEMM>>>(pSrch, pSrcl, KPA, pWihh, pWihl, KPA,
                                                  enc_bih, enc_bhh, pX, MROWS, G4, KPA);
    }

    // encoder recurrence
    rnn_enc<<<RNN_BLOCKS, NT_RNN, SMEM_RNN>>>(pX, enc_Whh, pHenc, pCenc);

    // fcW splits (only needed by loss GEMMs)
    cvt_split_t<HSZ, KPL><<<(ISZ * (KPL / 4) + 255) / 256, 256>>>(pd_fcW, pFcwh, pFcwl, ISZ);
    cvt_split_t<HSZ, KPL><<<(ISZ * (KPL / 4) + 255) / 256, 256>>>(rd_fcW, pFcwh + ISZ * KPL,
                                                                  pFcwl + ISZ * KPL, ISZ);

    // decoder step-0 gates (both decoders, one launch)
    {
        dim3 grid((G4 + 63) / 64, (BSZ + 255) / 256, 2);
        gemm_g0<<<grid, 256>>>(pHenc, pd_Whh, rd_Whh, pd_bih, rd_bih,
                               pd_bhh, rd_bhh, pG0, BSZ, G4, HSZ);
    }

    // merged decoders: 144 CTAs = one full wave
    {
        dim3 grid(DEC_BLOCKS, 2);
        rnn_dec2<<<grid, NT_RNN, SMEM_DEC>>>(pG0, pWeff, pBeff, pHenc, pCenc,
                                             pHdh, pHdl);
    }

    // merged losses (tensor cores, fused MSE epilogue)
    {
        dim3 grid((ISZ + 63) / 64, (MROWS + 127) / 128, 2);
        gemm_bf16_loss2<<<grid, 256, SMEM_GEMM>>>(pHdh, pHdl, pFcwh, pFcwl,
                                                  pd_fcb, rd_fcb, trg, src,
                                                  pLoss, MROWS, ISZ);
    }

    finalize_kernel<<<1, 1>>>(pLoss, out, 1.0f / (float)(BSZ * TSZ * ISZ));
}